// round 3
// baseline (speedup 1.0000x reference)
#include <cuda_runtime.h>
#include <cuda_bf16.h>
#include <cstdint>

// ---------------- problem constants (fixed by setup_inputs) ----------------
#define BATCH   32
#define NNODE   512
#define NROWS   (BATCH*NNODE)      // 16384
#define FDIM    1024
#define H1      512
#define H2      256
#define H3      128
#define NC      8
#define EDGES   32768              // per batch
#define NEDGE   (BATCH*EDGES)      // 1048576
#define EH      64
#define EC      10
#define CATTR   9
#define NODE_OUT_ELEMS (NROWS*NC)  // 131072

// ---------------- scratch (device globals; no allocation allowed) ----------
__device__ __nv_bfloat16 g_h1hi[NROWS * H1];   // 16 MB
__device__ __nv_bfloat16 g_h1lo[NROWS * H1];   // 16 MB
__device__ __nv_bfloat16 g_h2hi[NROWS * H2];   //  8 MB
__device__ __nv_bfloat16 g_h2lo[NROWS * H2];   //  8 MB
__device__ float         g_h3[NROWS * H3];     //  8 MB
__device__ __nv_bfloat16 g_w1hi[H1 * FDIM], g_w1lo[H1 * FDIM];
__device__ __nv_bfloat16 g_w2hi[H2 * H1],   g_w2lo[H2 * H1];
__device__ __nv_bfloat16 g_w3hi[H3 * H2],   g_w3lo[H3 * H2];

// ---------------- small helpers ---------------------------------------------
__device__ __forceinline__ uint32_t smem_u32(const void* p) {
    uint32_t a;
    asm("{ .reg .u64 t; cvta.to.shared.u64 t, %1; cvt.u32.u64 %0, t; }"
        : "=r"(a) : "l"(p));
    return a;
}
__device__ __forceinline__ void ldsm4(uint32_t addr, uint32_t* r) {
    asm volatile("ldmatrix.sync.aligned.m8n8.x4.shared.b16 {%0,%1,%2,%3}, [%4];"
                 : "=r"(r[0]), "=r"(r[1]), "=r"(r[2]), "=r"(r[3]) : "r"(addr));
}
__device__ __forceinline__ void mma16816(float* c, const uint32_t* a, const uint32_t* b) {
    asm volatile(
        "mma.sync.aligned.m16n8k16.row.col.f32.bf16.bf16.f32 "
        "{%0,%1,%2,%3}, {%4,%5,%6,%7}, {%8,%9}, {%0,%1,%2,%3};"
        : "+f"(c[0]), "+f"(c[1]), "+f"(c[2]), "+f"(c[3])
        : "r"(a[0]), "r"(a[1]), "r"(a[2]), "r"(a[3]), "r"(b[0]), "r"(b[1]));
}
__device__ __forceinline__ void sts64(uint32_t addr, uint32_t a, uint32_t b) {
    asm volatile("st.shared.v2.b32 [%0], {%1,%2};" :: "r"(addr), "r"(a), "r"(b) : "memory");
}
__device__ __forceinline__ void sts128(uint32_t addr, uint4 v) {
    asm volatile("st.shared.v4.b32 [%0], {%1,%2,%3,%4};"
                 :: "r"(addr), "r"(v.x), "r"(v.y), "r"(v.z), "r"(v.w) : "memory");
}

// ---------------- split-bf16 mma.sync GEMM ----------------------------------
// C = relu( (A @ B^T_pre + bias)[bn-fold] ), where weights are pre-transposed
// (N x K) and pre-split into bf16 hi/lo. A is fp32 (AF32=1, split inline) or
// pre-split bf16 pairs. Output: fp32 (OSPLIT=0) or bf16 hi/lo pair (OSPLIT=1).
// CTA tile 128x128, 8 warps of 32x64, K-chunk 32, double-buffered SMEM.
static constexpr int GEMM_SMEM = 2 * 32768;   // 2 stages x (Ahi|Alo|Bhi|Blo) x 8KB

template<int K, int N, int EPI, int AF32, int OSPLIT>
__global__ __launch_bounds__(256)
void gemm_mma(const float* __restrict__ Af,
              const __nv_bfloat16* __restrict__ Ahi, const __nv_bfloat16* __restrict__ Alo,
              const __nv_bfloat16* __restrict__ Bhi, const __nv_bfloat16* __restrict__ Blo,
              const float* __restrict__ bias,
              const float* __restrict__ bng, const float* __restrict__ bnb,
              const float* __restrict__ bnrm, const float* __restrict__ bnrv,
              float* __restrict__ Cf,
              __nv_bfloat16* __restrict__ Chi, __nv_bfloat16* __restrict__ Clo)
{
    extern __shared__ char sm_raw[];
    const uint32_t sb = smem_u32(sm_raw);
    const int tid = threadIdx.x;
    const int lane = tid & 31, w = tid >> 5;
    const int bn = blockIdx.x, bm = blockIdx.y;
    const int wr = (w & 3) * 32;       // warp row offset in tile
    const int wc = (w >> 2) * 64;      // warp col offset in tile

    float acc[2][8][4];
    #pragma unroll
    for (int a = 0; a < 2; a++)
        #pragma unroll
        for (int b = 0; b < 8; b++)
            #pragma unroll
            for (int c = 0; c < 4; c++) acc[a][b][c] = 0.f;

    const int lr = tid >> 1;                 // loader row 0..127
    const int swz_r = (lr >> 1) & 3;

    const float* gAf = Af + (size_t)(bm * 128 + lr) * K;
    const __nv_bfloat16* gAhi = Ahi + (size_t)(bm * 128 + lr) * K;
    const __nv_bfloat16* gAlo = Alo + (size_t)(bm * 128 + lr) * K;
    const __nv_bfloat16* gBhi = Bhi + (size_t)(bn * 128 + lr) * K;
    const __nv_bfloat16* gBlo = Blo + (size_t)(bn * 128 + lr) * K;

    // prefetch registers
    float4 pa[4];
    uint4 pah[2], pal[2], pbh[2], pbl[2];

    auto LDG = [&](int c) {
        if (AF32) {
            const float4* s = (const float4*)(gAf + c * 32);
            const int fb = (tid & 1) * 4;
            #pragma unroll
            for (int i = 0; i < 4; i++) pa[i] = s[fb + i];
        } else {
            const uint4* sh = (const uint4*)(gAhi + c * 32);
            const uint4* sl = (const uint4*)(gAlo + c * 32);
            const int ub = (tid & 1) * 2;
            pah[0] = sh[ub]; pah[1] = sh[ub + 1];
            pal[0] = sl[ub]; pal[1] = sl[ub + 1];
        }
        const uint4* th = (const uint4*)(gBhi + c * 32);
        const uint4* tl = (const uint4*)(gBlo + c * 32);
        const int ub = (tid & 1) * 2;
        pbh[0] = th[ub]; pbh[1] = th[ub + 1];
        pbl[0] = tl[ub]; pbl[1] = tl[ub + 1];
    };

    auto STS = [&](int stage) {
        const uint32_t base = sb + stage * 32768;
        if (AF32) {
            const int fb = (tid & 1) * 4;
            #pragma unroll
            for (int i = 0; i < 4; i++) {
                const int f4 = fb + i;
                const int ch = f4 >> 1;
                const uint32_t off = lr * 64 + (((ch ^ swz_r)) << 4) + ((f4 & 1) << 3);
                float4 v = pa[i];
                __nv_bfloat162 h0 = __floats2bfloat162_rn(v.x, v.y);
                __nv_bfloat162 h1 = __floats2bfloat162_rn(v.z, v.w);
                float lx = v.x - __bfloat162float(h0.x);
                float ly = v.y - __bfloat162float(h0.y);
                float lz = v.z - __bfloat162float(h1.x);
                float lw = v.w - __bfloat162float(h1.y);
                __nv_bfloat162 l0 = __floats2bfloat162_rn(lx, ly);
                __nv_bfloat162 l1 = __floats2bfloat162_rn(lz, lw);
                uint32_t u0, u1, u2, u3;
                memcpy(&u0, &h0, 4); memcpy(&u1, &h1, 4);
                memcpy(&u2, &l0, 4); memcpy(&u3, &l1, 4);
                sts64(base + off, u0, u1);
                sts64(base + 8192 + off, u2, u3);
            }
        } else {
            const int ub = (tid & 1) * 2;
            #pragma unroll
            for (int i = 0; i < 2; i++) {
                const int u = ub + i;
                const uint32_t off = lr * 64 + ((u ^ swz_r) << 4);
                sts128(base + off, pah[i]);
                sts128(base + 8192 + off, pal[i]);
            }
        }
        const int ub = (tid & 1) * 2;
        #pragma unroll
        for (int i = 0; i < 2; i++) {
            const int u = ub + i;
            const uint32_t off = lr * 64 + ((u ^ swz_r) << 4);
            sts128(base + 16384 + off, pbh[i]);
            sts128(base + 24576 + off, pbl[i]);
        }
    };

    const int m = lane >> 3, rr = lane & 7;

    auto COMPUTE = [&](int stage) {
        const uint32_t aB = sb + stage * 32768;
        const uint32_t bB = aB + 16384;
        #pragma unroll
        for (int ks = 0; ks < 2; ks++) {
            const int ckb = ks * 2;
            uint32_t ah[2][4], al[2][4], bh[4][4], bl[4][4];
            #pragma unroll
            for (int t2 = 0; t2 < 2; t2++) {
                const int r_l = wr + t2 * 16 + ((m & 1) << 3) + rr;
                const int c_l = ckb + (m >> 1);
                const uint32_t off = r_l * 64 + ((c_l ^ ((r_l >> 1) & 3)) << 4);
                ldsm4(aB + off, ah[t2]);
                ldsm4(aB + 8192 + off, al[t2]);
            }
            #pragma unroll
            for (int p = 0; p < 4; p++) {
                const int n_l = wc + p * 16 + ((m >> 1) << 3) + rr;
                const int c_l = ckb + (m & 1);
                const uint32_t off = n_l * 64 + ((c_l ^ ((n_l >> 1) & 3)) << 4);
                ldsm4(bB + off, bh[p]);
                ldsm4(bB + 8192 + off, bl[p]);
            }
            #pragma unroll
            for (int t2 = 0; t2 < 2; t2++)
                #pragma unroll
                for (int nt = 0; nt < 8; nt++) {
                    const uint32_t* Bh = &bh[nt >> 1][(nt & 1) * 2];
                    const uint32_t* Bl = &bl[nt >> 1][(nt & 1) * 2];
                    mma16816(acc[t2][nt], ah[t2], Bh);
                    mma16816(acc[t2][nt], al[t2], Bh);
                    mma16816(acc[t2][nt], ah[t2], Bl);
                }
        }
    };

    constexpr int NCH = K / 32;
    LDG(0); STS(0); __syncthreads();
    for (int c = 0; c < NCH; c++) {
        if (c + 1 < NCH) LDG(c + 1);
        COMPUTE(c & 1);
        if (c + 1 < NCH) { STS((c + 1) & 1); __syncthreads(); }
    }

    // ---------------- epilogue ----------------
    #pragma unroll
    for (int t2 = 0; t2 < 2; t2++) {
        const int row0 = bm * 128 + wr + t2 * 16 + (lane >> 2);
        #pragma unroll
        for (int nt = 0; nt < 8; nt++) {
            const int col = bn * 128 + wc + nt * 8 + 2 * (lane & 3);
            float b0 = __ldg(&bias[col]), b1 = __ldg(&bias[col + 1]);
            float s0 = 1.f, s1 = 1.f, f0 = 0.f, f1 = 0.f;
            if (EPI) {
                s0 = __ldg(&bng[col]) * rsqrtf(__ldg(&bnrv[col]) + 1e-5f);
                f0 = __ldg(&bnb[col]) - __ldg(&bnrm[col]) * s0;
                s1 = __ldg(&bng[col + 1]) * rsqrtf(__ldg(&bnrv[col + 1]) + 1e-5f);
                f1 = __ldg(&bnb[col + 1]) - __ldg(&bnrm[col + 1]) * s1;
            }
            float v00 = acc[t2][nt][0] + b0, v01 = acc[t2][nt][1] + b1;
            float v10 = acc[t2][nt][2] + b0, v11 = acc[t2][nt][3] + b1;
            if (EPI) {
                v00 = v00 * s0 + f0; v01 = v01 * s1 + f1;
                v10 = v10 * s0 + f0; v11 = v11 * s1 + f1;
            }
            v00 = fmaxf(v00, 0.f); v01 = fmaxf(v01, 0.f);
            v10 = fmaxf(v10, 0.f); v11 = fmaxf(v11, 0.f);
            if (OSPLIT) {
                __nv_bfloat162 h0 = __floats2bfloat162_rn(v00, v01);
                __nv_bfloat162 l0 = __floats2bfloat162_rn(v00 - __bfloat162float(h0.x),
                                                          v01 - __bfloat162float(h0.y));
                __nv_bfloat162 h1 = __floats2bfloat162_rn(v10, v11);
                __nv_bfloat162 l1 = __floats2bfloat162_rn(v10 - __bfloat162float(h1.x),
                                                          v11 - __bfloat162float(h1.y));
                *(__nv_bfloat162*)(Chi + (size_t)row0 * N + col) = h0;
                *(__nv_bfloat162*)(Clo + (size_t)row0 * N + col) = l0;
                *(__nv_bfloat162*)(Chi + (size_t)(row0 + 8) * N + col) = h1;
                *(__nv_bfloat162*)(Clo + (size_t)(row0 + 8) * N + col) = l1;
            } else {
                *(float2*)(Cf + (size_t)row0 * N + col) = make_float2(v00, v01);
                *(float2*)(Cf + (size_t)(row0 + 8) * N + col) = make_float2(v10, v11);
            }
        }
    }
}

// ------- weight transpose + bf16 hi/lo split: in (R x C) -> out (C x R) -----
__global__ void transpose_split(const float* __restrict__ in,
                                __nv_bfloat16* __restrict__ ohi,
                                __nv_bfloat16* __restrict__ olo,
                                int R, int C)
{
    __shared__ float t[32][33];
    int x = blockIdx.x * 32 + threadIdx.x;
    int y = blockIdx.y * 32 + threadIdx.y;
    #pragma unroll
    for (int i = 0; i < 32; i += 8)
        t[threadIdx.y + i][threadIdx.x] = in[(size_t)(y + i) * C + x];
    __syncthreads();
    x = blockIdx.y * 32 + threadIdx.x;
    y = blockIdx.x * 32 + threadIdx.y;
    #pragma unroll
    for (int i = 0; i < 32; i += 8) {
        float v = t[threadIdx.x][threadIdx.y + i];
        __nv_bfloat16 h = __float2bfloat16(v);
        ohi[(size_t)(y + i) * R + x] = h;
        olo[(size_t)(y + i) * R + x] = __float2bfloat16(v - __bfloat162float(h));
    }
}

// ---------------- node head: h3(16384x128) @ ni_w(128x8) -> sigmoid ---------
__global__ __launch_bounds__(256)
void node_out_kernel(const float* __restrict__ h3,
                     const float* __restrict__ w,
                     const float* __restrict__ b,
                     float* __restrict__ out)
{
    int t = blockIdx.x * 256 + threadIdx.x;
    int row = t >> 3;
    int j = t & 7;
    const float* x = h3 + (size_t)row * H3;
    float acc = b[j];
    #pragma unroll 8
    for (int k = 0; k < H3; k++)
        acc += x[k] * __ldg(&w[k * NC + j]);
    out[t] = 1.f / (1.f + __expf(-acc));
}

// ---------------- fused edge MLP: gather + 18->64->64->10 + sigmoid ---------
__global__ __launch_bounds__(256)
void edge_kernel(const float* __restrict__ bboxes,
                 const float* __restrict__ dirs,
                 const float* __restrict__ prio,
                 const int*   __restrict__ eidx,
                 const float* __restrict__ w1, const float* __restrict__ b1,
                 const float* __restrict__ w2, const float* __restrict__ b2,
                 const float* __restrict__ wi, const float* __restrict__ bi,
                 float* __restrict__ out)
{
    __shared__ float sw1[2 * CATTR * EH];
    __shared__ float sw2[EH * EH];
    __shared__ float swi[EH * 12];
    __shared__ float sb1[EH], sb2[EH], sbi[12];

    for (int i = threadIdx.x; i < 2 * CATTR * EH; i += 256) sw1[i] = w1[i];
    for (int i = threadIdx.x; i < EH * EH;        i += 256) sw2[i] = w2[i];
    for (int i = threadIdx.x; i < EH * 12;        i += 256) {
        int k = i / 12, j = i % 12;
        swi[i] = (j < EC) ? wi[k * EC + j] : 0.f;
    }
    for (int i = threadIdx.x; i < EH; i += 256) { sb1[i] = b1[i]; sb2[i] = b2[i]; }
    if (threadIdx.x < 12) sbi[threadIdx.x] = (threadIdx.x < EC) ? bi[threadIdx.x] : 0.f;
    __syncthreads();

    const int e  = blockIdx.x * 256 + threadIdx.x;
    const int bt = e >> 15;
    const int ei = e & (EDGES - 1);
    const int src = eidx[bt * 2 * EDGES + ei];
    const int dst = eidx[bt * 2 * EDGES + EDGES + ei];

    float x[2 * CATTR];
    {
        int n0 = bt * NNODE + src;
        float4 bb = *(const float4*)&bboxes[(size_t)n0 * 4];
        float4 dd = *(const float4*)&dirs[(size_t)n0 * 4];
        const float inv = 1.f / 1024.f;
        x[0] = bb.x * inv; x[1] = bb.y * inv; x[2] = bb.z * inv; x[3] = bb.w * inv;
        x[4] = dd.x; x[5] = dd.y; x[6] = dd.z; x[7] = dd.w;
        x[8] = prio[n0];
        int n1 = bt * NNODE + dst;
        float4 bb2 = *(const float4*)&bboxes[(size_t)n1 * 4];
        float4 dd2 = *(const float4*)&dirs[(size_t)n1 * 4];
        x[9]  = bb2.x * inv; x[10] = bb2.y * inv; x[11] = bb2.z * inv; x[12] = bb2.w * inv;
        x[13] = dd2.x; x[14] = dd2.y; x[15] = dd2.z; x[16] = dd2.w;
        x[17] = prio[n1];
    }

    float h[EH];
    #pragma unroll
    for (int j = 0; j < EH; j += 4) *(float4*)&h[j] = *(const float4*)&sb1[j];
    #pragma unroll
    for (int k = 0; k < 2 * CATTR; k++) {
        float xk = x[k];
        const float4* wr = (const float4*)&sw1[k * EH];
        #pragma unroll
        for (int j4 = 0; j4 < EH / 4; j4++) {
            float4 wv = wr[j4];
            h[j4 * 4 + 0] += xk * wv.x;
            h[j4 * 4 + 1] += xk * wv.y;
            h[j4 * 4 + 2] += xk * wv.z;
            h[j4 * 4 + 3] += xk * wv.w;
        }
    }

    float g[EH];
    #pragma unroll
    for (int j = 0; j < EH; j += 4) *(float4*)&g[j] = *(const float4*)&sb2[j];
    #pragma unroll
    for (int k = 0; k < EH; k++) {
        float hk = fmaxf(h[k], 0.f);
        const float4* wr = (const float4*)&sw2[k * EH];
        #pragma unroll
        for (int j4 = 0; j4 < EH / 4; j4++) {
            float4 wv = wr[j4];
            g[j4 * 4 + 0] += hk * wv.x;
            g[j4 * 4 + 1] += hk * wv.y;
            g[j4 * 4 + 2] += hk * wv.z;
            g[j4 * 4 + 3] += hk * wv.w;
        }
    }

    float acc[12];
    #pragma unroll
    for (int j = 0; j < 12; j += 4) *(float4*)&acc[j] = *(const float4*)&sbi[j];
    #pragma unroll
    for (int k = 0; k < EH; k++) {
        float gk = fmaxf(g[k], 0.f);
        const float4* wr = (const float4*)&swi[k * 12];
        #pragma unroll
        for (int j4 = 0; j4 < 3; j4++) {
            float4 wv = wr[j4];
            acc[j4 * 4 + 0] += gk * wv.x;
            acc[j4 * 4 + 1] += gk * wv.y;
            acc[j4 * 4 + 2] += gk * wv.z;
            acc[j4 * 4 + 3] += gk * wv.w;
        }
    }
    float* op = out + (size_t)e * EC;
    #pragma unroll
    for (int j = 0; j < EC; j++)
        op[j] = 1.f / (1.f + __expf(-acc[j]));
}

// ---------------- launch ----------------------------------------------------
extern "C" void kernel_launch(void* const* d_in, const int* in_sizes, int n_in,
                              void* d_out, int out_size)
{
    const float* roi    = (const float*)d_in[0];
    const float* bboxes = (const float*)d_in[1];
    const float* dirs   = (const float*)d_in[2];
    const float* prio   = (const float*)d_in[3];
    const int*   eidx   = (const int*)  d_in[4];
    const float* np_w1  = (const float*)d_in[5];
    const float* np_b1  = (const float*)d_in[6];
    const float* bn1_g  = (const float*)d_in[7];
    const float* bn1_b  = (const float*)d_in[8];
    const float* bn1_rm = (const float*)d_in[9];
    const float* bn1_rv = (const float*)d_in[10];
    const float* np_w2  = (const float*)d_in[11];
    const float* np_b2  = (const float*)d_in[12];
    const float* bn2_g  = (const float*)d_in[13];
    const float* bn2_b  = (const float*)d_in[14];
    const float* bn2_rm = (const float*)d_in[15];
    const float* bn2_rv = (const float*)d_in[16];
    const float* np_w3  = (const float*)d_in[17];
    const float* np_b3  = (const float*)d_in[18];
    const float* ni_w   = (const float*)d_in[19];
    const float* ni_b   = (const float*)d_in[20];
    const float* ep_w1  = (const float*)d_in[21];
    const float* ep_b1  = (const float*)d_in[22];
    const float* ep_w2  = (const float*)d_in[23];
    const float* ep_b2  = (const float*)d_in[24];
    const float* ei_w   = (const float*)d_in[25];
    const float* ei_b   = (const float*)d_in[26];

    float* out = (float*)d_out;

    __nv_bfloat16 *h1hi, *h1lo, *h2hi, *h2lo;
    __nv_bfloat16 *w1hi, *w1lo, *w2hi, *w2lo, *w3hi, *w3lo;
    float* h3;
    cudaGetSymbolAddress((void**)&h1hi, g_h1hi);
    cudaGetSymbolAddress((void**)&h1lo, g_h1lo);
    cudaGetSymbolAddress((void**)&h2hi, g_h2hi);
    cudaGetSymbolAddress((void**)&h2lo, g_h2lo);
    cudaGetSymbolAddress((void**)&h3, g_h3);
    cudaGetSymbolAddress((void**)&w1hi, g_w1hi);
    cudaGetSymbolAddress((void**)&w1lo, g_w1lo);
    cudaGetSymbolAddress((void**)&w2hi, g_w2hi);
    cudaGetSymbolAddress((void**)&w2lo, g_w2lo);
    cudaGetSymbolAddress((void**)&w3hi, g_w3hi);
    cudaGetSymbolAddress((void**)&w3lo, g_w3lo);

    cudaFuncSetAttribute(gemm_mma<FDIM, H1, 1, 1, 1>,
                         cudaFuncAttributeMaxDynamicSharedMemorySize, GEMM_SMEM);
    cudaFuncSetAttribute(gemm_mma<H1, H2, 1, 0, 1>,
                         cudaFuncAttributeMaxDynamicSharedMemorySize, GEMM_SMEM);
    cudaFuncSetAttribute(gemm_mma<H2, H3, 0, 0, 0>,
                         cudaFuncAttributeMaxDynamicSharedMemorySize, GEMM_SMEM);

    // weight transpose + split (K x N -> N x K, bf16 hi/lo)
    {
        dim3 b(32, 8);
        transpose_split<<<dim3(H1 / 32, FDIM / 32), b>>>(np_w1, w1hi, w1lo, FDIM, H1);
        transpose_split<<<dim3(H2 / 32, H1 / 32), b>>>(np_w2, w2hi, w2lo, H1, H2);
        transpose_split<<<dim3(H3 / 32, H2 / 32), b>>>(np_w3, w3hi, w3lo, H2, H3);
    }

    // edge path
    edge_kernel<<<NEDGE / 256, 256>>>(bboxes, dirs, prio, eidx,
                                      ep_w1, ep_b1, ep_w2, ep_b2, ei_w, ei_b,
                                      out + NODE_OUT_ELEMS);

    // node MLP chain on mma.sync tensor cores (split-bf16, fp32 accum)
    gemm_mma<FDIM, H1, 1, 1, 1><<<dim3(H1 / 128, NROWS / 128), 256, GEMM_SMEM>>>(
        roi, nullptr, nullptr, w1hi, w1lo,
        np_b1, bn1_g, bn1_b, bn1_rm, bn1_rv, nullptr, h1hi, h1lo);
    gemm_mma<H1, H2, 1, 0, 1><<<dim3(H2 / 128, NROWS / 128), 256, GEMM_SMEM>>>(
        nullptr, h1hi, h1lo, w2hi, w2lo,
        np_b2, bn2_g, bn2_b, bn2_rm, bn2_rv, nullptr, h2hi, h2lo);
    gemm_mma<H2, H3, 0, 0, 0><<<dim3(H3 / 128, NROWS / 128), 256, GEMM_SMEM>>>(
        nullptr, h2hi, h2lo, w3hi, w3lo,
        np_b3, nullptr, nullptr, nullptr, nullptr, h3, nullptr, nullptr);

    node_out_kernel<<<NODE_OUT_ELEMS / 256, 256>>>(h3, ni_w, ni_b, out);
}

// round 4
// speedup vs baseline: 1.6288x; 1.6288x over previous
#include <cuda_runtime.h>
#include <cuda_bf16.h>
#include <cstdint>

// ---------------- problem constants (fixed by setup_inputs) ----------------
#define BATCH   32
#define NNODE   512
#define NROWS   (BATCH*NNODE)      // 16384
#define FDIM    1024
#define H1      512
#define H2      256
#define H3      128
#define NC      8
#define EDGES   32768              // per batch
#define NEDGE   (BATCH*EDGES)      // 1048576
#define EH      64
#define EC      10
#define CATTR   9
#define NODE_OUT_ELEMS (NROWS*NC)  // 131072

// ---------------- scratch (device globals; no allocation allowed) ----------
__device__ float g_h1[NROWS * H1];   // 32 MB
__device__ float g_h2[NROWS * H2];   // 16 MB
__device__ float g_h3[NROWS * H3];   //  8 MB
__device__ __nv_bfloat16 g_ew1t[64 * 32];   // ep_w1^T padded (64 n x 32 k)
__device__ __nv_bfloat16 g_ew2t[64 * 64];   // ep_w2^T (64 n x 64 k)
__device__ __nv_bfloat16 g_ew3t[16 * 64];   // ei_w^T padded (16 n x 64 k)

// ---------------- helpers ----------------------------------------------------
__device__ __forceinline__ uint32_t smem_u32(const void* p) {
    uint32_t a;
    asm("{ .reg .u64 t; cvta.to.shared.u64 t, %1; cvt.u32.u64 %0, t; }"
        : "=r"(a) : "l"(p));
    return a;
}
__device__ __forceinline__ void ldsm4(uint32_t addr, uint32_t* r) {
    asm volatile("ldmatrix.sync.aligned.m8n8.x4.shared.b16 {%0,%1,%2,%3}, [%4];"
                 : "=r"(r[0]), "=r"(r[1]), "=r"(r[2]), "=r"(r[3]) : "r"(addr));
}
__device__ __forceinline__ void mma16816(float* c, const uint32_t* a, const uint32_t* b) {
    asm volatile(
        "mma.sync.aligned.m16n8k16.row.col.f32.bf16.bf16.f32 "
        "{%0,%1,%2,%3}, {%4,%5,%6,%7}, {%8,%9}, {%0,%1,%2,%3};"
        : "+f"(c[0]), "+f"(c[1]), "+f"(c[2]), "+f"(c[3])
        : "r"(a[0]), "r"(a[1]), "r"(a[2]), "r"(a[3]), "r"(b[0]), "r"(b[1]));
}
__device__ __forceinline__ void sts128(uint32_t addr, uint4 v) {
    asm volatile("st.shared.v4.b32 [%0], {%1,%2,%3,%4};"
                 :: "r"(addr), "r"(v.x), "r"(v.y), "r"(v.z), "r"(v.w) : "memory");
}
__device__ __forceinline__ void sts32(uint32_t addr, uint32_t v) {
    asm volatile("st.shared.b32 [%0], %1;" :: "r"(addr), "r"(v) : "memory");
}
__device__ __forceinline__ uint32_t pack_bf2(float a, float b) {
    __nv_bfloat162 h = __floats2bfloat162_rn(a, b);
    uint32_t u; memcpy(&u, &h, 4); return u;
}

// ---------------- node-path fused GEMM + (BN)+ReLU (SIMT, proven R1) --------
template<int M, int N, int K, int EPI>
__global__ __launch_bounds__(256)
void gemm_relu_kernel(const float* __restrict__ A,
                      const float* __restrict__ W,
                      const float* __restrict__ bias,
                      const float* __restrict__ bng,
                      const float* __restrict__ bnb,
                      const float* __restrict__ bnrm,
                      const float* __restrict__ bnrv,
                      float* __restrict__ C)
{
    constexpr int BM = 128, BN = 128, BK = 8;
    __shared__ float As[BK][BM];
    __shared__ float Bs[BK][BN];

    const int bm = blockIdx.y, bn = blockIdx.x;
    const int tid = threadIdx.x;
    const int tx = tid % 16;
    const int ty = tid / 16;

    const int a_row = tid >> 1;
    const int a_kc  = (tid & 1) * 4;
    const int b_kr  = tid >> 5;
    const int b_col = (tid & 31) * 4;

    float acc[8][8];
    #pragma unroll
    for (int i = 0; i < 8; i++)
        #pragma unroll
        for (int j = 0; j < 8; j++) acc[i][j] = 0.f;

    const float* Ap = A + (size_t)(bm * BM + a_row) * K + a_kc;
    const float* Wp = W + (size_t)b_kr * N + bn * BN + b_col;

    for (int kt = 0; kt < K; kt += BK) {
        float4 av = *(const float4*)(Ap + kt);
        As[a_kc + 0][a_row] = av.x;
        As[a_kc + 1][a_row] = av.y;
        As[a_kc + 2][a_row] = av.z;
        As[a_kc + 3][a_row] = av.w;
        float4 bv = *(const float4*)(Wp + (size_t)kt * N);
        *(float4*)&Bs[b_kr][b_col] = bv;
        __syncthreads();

        #pragma unroll
        for (int k = 0; k < BK; k++) {
            float am[8], wn[8];
            *(float4*)&am[0] = *(const float4*)&As[k][ty * 8];
            *(float4*)&am[4] = *(const float4*)&As[k][ty * 8 + 4];
            *(float4*)&wn[0] = *(const float4*)&Bs[k][tx * 8];
            *(float4*)&wn[4] = *(const float4*)&Bs[k][tx * 8 + 4];
            #pragma unroll
            for (int i = 0; i < 8; i++)
                #pragma unroll
                for (int j = 0; j < 8; j++)
                    acc[i][j] += am[i] * wn[j];
        }
        __syncthreads();
    }

    float bb[8], sc[8], sh[8];
    #pragma unroll
    for (int j = 0; j < 8; j++) {
        int col = bn * BN + tx * 8 + j;
        bb[j] = bias[col];
        if (EPI == 1) {
            float s = bng[col] * rsqrtf(bnrv[col] + 1e-5f);
            sc[j] = s;
            sh[j] = bnb[col] - bnrm[col] * s;
        }
    }
    #pragma unroll
    for (int i = 0; i < 8; i++) {
        int row = bm * BM + ty * 8 + i;
        float v[8];
        #pragma unroll
        for (int j = 0; j < 8; j++) {
            float t = acc[i][j] + bb[j];
            if (EPI == 1) t = t * sc[j] + sh[j];
            v[j] = fmaxf(t, 0.f);
        }
        float* cp = C + (size_t)row * N + bn * BN + tx * 8;
        *(float4*)(cp + 0) = make_float4(v[0], v[1], v[2], v[3]);
        *(float4*)(cp + 4) = make_float4(v[4], v[5], v[6], v[7]);
    }
}

// ---------------- node head: h3(16384x128) @ ni_w(128x8) -> sigmoid ---------
__global__ __launch_bounds__(256)
void node_out_kernel(const float* __restrict__ h3,
                     const float* __restrict__ w,
                     const float* __restrict__ b,
                     float* __restrict__ out)
{
    int t = blockIdx.x * 256 + threadIdx.x;
    int row = t >> 3;
    int j = t & 7;
    const float* x = h3 + (size_t)row * H3;
    float acc = b[j];
    #pragma unroll 8
    for (int k = 0; k < H3; k++)
        acc += x[k] * __ldg(&w[k * NC + j]);
    out[t] = 1.f / (1.f + __expf(-acc));
}

// ---------------- edge weight prep: transpose+pad to bf16 -------------------
__global__ void prep_edge_weights(const float* __restrict__ w1,   // (18,64)
                                  const float* __restrict__ w2,   // (64,64)
                                  const float* __restrict__ wi,   // (64,10)
                                  __nv_bfloat16* __restrict__ o1, // (64,32)
                                  __nv_bfloat16* __restrict__ o2, // (64,64)
                                  __nv_bfloat16* __restrict__ o3) // (16,64)
{
    int t = blockIdx.x * 256 + threadIdx.x;
    int stride = gridDim.x * 256;
    for (int i = t; i < 64 * 32; i += stride) {
        int n = i >> 5, k = i & 31;
        o1[i] = (k < 18) ? __float2bfloat16(w1[k * 64 + n]) : __nv_bfloat16(0.f);
    }
    for (int i = t; i < 64 * 64; i += stride) {
        int n = i >> 6, k = i & 63;
        o2[i] = __float2bfloat16(w2[k * 64 + n]);
    }
    for (int i = t; i < 16 * 64; i += stride) {
        int n = i >> 6, k = i & 63;
        o3[i] = (n < EC) ? __float2bfloat16(wi[k * EC + n]) : __nv_bfloat16(0.f);
    }
}

// ---------------- edge MLP on tensor cores ----------------------------------
// CTA = 128 edges of one batch, 4 warps. SMEM: node attrs + weights + tiles.
// A1(128x32 bf16,K pad 18->32) -> h(128x64) -> g(128x64) -> sigmoid out(10).
static constexpr int ESA_ATTR = 0;            // 512*10*2  = 10240
static constexpr int ESA_W1   = 10240;        // 64*64     =  4096
static constexpr int ESA_W2   = 14336;        // 64*128    =  8192
static constexpr int ESA_W3   = 22528;        // 16*128    =  2048
static constexpr int ESA_A1   = 24576;        // 128*64    =  8192
static constexpr int ESA_H    = 32768;        // 128*128   = 16384
static constexpr int ESA_G    = 49152;        // 128*128   = 16384
static constexpr int EDGE_SMEM = 65536;

__global__ __launch_bounds__(128)
void edge_mma_kernel(const float* __restrict__ bboxes,   // (B,N,4)
                     const float* __restrict__ dirs,     // (B,N,4)
                     const float* __restrict__ prio,     // (B,N)
                     const int*   __restrict__ eidx,     // (B,2,E)
                     const __nv_bfloat16* __restrict__ w1t,
                     const __nv_bfloat16* __restrict__ w2t,
                     const __nv_bfloat16* __restrict__ w3t,
                     const float* __restrict__ b1,
                     const float* __restrict__ b2,
                     const float* __restrict__ bi,
                     float* __restrict__ out)            // edge block of d_out
{
    extern __shared__ char sm[];
    const uint32_t sb = smem_u32(sm);
    const int tid = threadIdx.x;
    const int lane = tid & 31, w = tid >> 5;
    const int bt = blockIdx.x >> 8;             // batch (256 CTAs per batch)
    const int e0 = (blockIdx.x & 255) * 128;    // first edge (within batch)

    // ---- stage node attrs of this batch into SMEM (bf16, stride 10) ----
    __nv_bfloat16* sAttr = (__nv_bfloat16*)(sm + ESA_ATTR);
    const float inv = 1.f / 1024.f;
    for (int n = tid; n < NNODE; n += 128) {
        int gn = bt * NNODE + n;
        float4 bb = *(const float4*)&bboxes[(size_t)gn * 4];
        float4 dd = *(const float4*)&dirs[(size_t)gn * 4];
        float pr = prio[gn];
        __nv_bfloat16* a = sAttr + n * 10;
        a[0] = __float2bfloat16(bb.x * inv);
        a[1] = __float2bfloat16(bb.y * inv);
        a[2] = __float2bfloat16(bb.z * inv);
        a[3] = __float2bfloat16(bb.w * inv);
        a[4] = __float2bfloat16(dd.x);
        a[5] = __float2bfloat16(dd.y);
        a[6] = __float2bfloat16(dd.z);
        a[7] = __float2bfloat16(dd.w);
        a[8] = __float2bfloat16(pr);
    }
    // ---- stage weights (swizzled for ldmatrix) ----
    for (int i = tid; i < 64 * 4; i += 128) {          // W1: 64 rows x 4 chunks (64B rows)
        int r = i >> 2, c = i & 3;
        uint4 v = ((const uint4*)w1t)[r * 4 + c];
        sts128(sb + ESA_W1 + r * 64 + ((c ^ ((r >> 1) & 3)) << 4), v);
    }
    for (int i = tid; i < 64 * 8; i += 128) {          // W2: 64 rows x 8 chunks (128B rows)
        int r = i >> 3, c = i & 7;
        uint4 v = ((const uint4*)w2t)[r * 8 + c];
        sts128(sb + ESA_W2 + r * 128 + ((c ^ (r & 7)) << 4), v);
    }
    for (int i = tid; i < 16 * 8; i += 128) {          // W3: 16 rows x 8 chunks
        int r = i >> 3, c = i & 7;
        uint4 v = ((const uint4*)w3t)[r * 8 + c];
        sts128(sb + ESA_W3 + r * 128 + ((c ^ (r & 7)) << 4), v);
    }
    __syncthreads();

    // ---- build A1 row (one edge per thread), K padded 18->32 ----
    {
        const int ebase = bt * 2 * EDGES + e0 + tid;
        const int src = eidx[ebase];
        const int dst = eidx[ebase + EDGES];
        const __nv_bfloat16* as = sAttr + src * 10;
        const __nv_bfloat16* ad = sAttr + dst * 10;
        uint16_t v[32];
        #pragma unroll
        for (int c = 0; c < 9; c++) { memcpy(&v[c], &as[c], 2); memcpy(&v[9 + c], &ad[c], 2); }
        #pragma unroll
        for (int c = 18; c < 32; c++) v[c] = 0;
        const int swz = (tid >> 1) & 3;
        #pragma unroll
        for (int ch = 0; ch < 4; ch++) {
            uint4 p;
            p.x = (uint32_t)v[ch*8+0] | ((uint32_t)v[ch*8+1] << 16);
            p.y = (uint32_t)v[ch*8+2] | ((uint32_t)v[ch*8+3] << 16);
            p.z = (uint32_t)v[ch*8+4] | ((uint32_t)v[ch*8+5] << 16);
            p.w = (uint32_t)v[ch*8+6] | ((uint32_t)v[ch*8+7] << 16);
            sts128(sb + ESA_A1 + tid * 64 + ((ch ^ swz) << 4), p);
        }
    }
    __syncthreads();

    const int m = lane >> 3, rr = lane & 7;
    const int wr = w * 32;

    // ================= layer 1: (128x32) @ (64x32)^T -> h (128x64) =========
    {
        float acc[2][8][4];
        #pragma unroll
        for (int a = 0; a < 2; a++)
            #pragma unroll
            for (int b = 0; b < 8; b++)
                #pragma unroll
                for (int c = 0; c < 4; c++) acc[a][b][c] = 0.f;

        #pragma unroll
        for (int k16 = 0; k16 < 2; k16++) {
            uint32_t a[2][4], b[4][4];
            #pragma unroll
            for (int t2 = 0; t2 < 2; t2++) {
                int r = wr + t2 * 16 + ((m & 1) << 3) + rr;
                int c = k16 * 2 + (m >> 1);
                ldsm4(sb + ESA_A1 + r * 64 + ((c ^ ((r >> 1) & 3)) << 4), a[t2]);
            }
            #pragma unroll
            for (int p = 0; p < 4; p++) {
                int n = p * 16 + ((m >> 1) << 3) + rr;
                int c = k16 * 2 + (m & 1);
                ldsm4(sb + ESA_W1 + n * 64 + ((c ^ ((n >> 1) & 3)) << 4), b[p]);
            }
            #pragma unroll
            for (int t2 = 0; t2 < 2; t2++)
                #pragma unroll
                for (int nt = 0; nt < 8; nt++)
                    mma16816(acc[t2][nt], a[t2], &b[nt >> 1][(nt & 1) * 2]);
        }
        // epilogue -> sH (bf16, swizzled 128B rows)
        #pragma unroll
        for (int t2 = 0; t2 < 2; t2++) {
            int r0 = wr + t2 * 16 + (lane >> 2);
            #pragma unroll
            for (int nt = 0; nt < 8; nt++) {
                int col = nt * 8 + 2 * (lane & 3);
                float bb0 = __ldg(&b1[col]), bb1 = __ldg(&b1[col + 1]);
                float v00 = fmaxf(acc[t2][nt][0] + bb0, 0.f);
                float v01 = fmaxf(acc[t2][nt][1] + bb1, 0.f);
                float v10 = fmaxf(acc[t2][nt][2] + bb0, 0.f);
                float v11 = fmaxf(acc[t2][nt][3] + bb1, 0.f);
                uint32_t inb = (col & 7) * 2;
                sts32(sb + ESA_H + r0 * 128 + (((nt) ^ (r0 & 7)) << 4) + inb,
                      pack_bf2(v00, v01));
                int r1 = r0 + 8;
                sts32(sb + ESA_H + r1 * 128 + (((nt) ^ (r1 & 7)) << 4) + inb,
                      pack_bf2(v10, v11));
            }
        }
    }
    __syncwarp();

    // ================= layer 2: (128x64) @ (64x64)^T -> g (128x64) ==========
    {
        float acc[2][8][4];
        #pragma unroll
        for (int a = 0; a < 2; a++)
            #pragma unroll
            for (int b = 0; b < 8; b++)
                #pragma unroll
                for (int c = 0; c < 4; c++) acc[a][b][c] = 0.f;

        #pragma unroll
        for (int k16 = 0; k16 < 4; k16++) {
            uint32_t a[2][4], b[4][4];
            #pragma unroll
            for (int t2 = 0; t2 < 2; t2++) {
                int r = wr + t2 * 16 + ((m & 1) << 3) + rr;
                int c = k16 * 2 + (m >> 1);
                ldsm4(sb + ESA_H + r * 128 + ((c ^ (r & 7)) << 4), a[t2]);
            }
            #pragma unroll
            for (int p = 0; p < 4; p++) {
                int n = p * 16 + ((m >> 1) << 3) + rr;
                int c = k16 * 2 + (m & 1);
                ldsm4(sb + ESA_W2 + n * 128 + ((c ^ (n & 7)) << 4), b[p]);
            }
            #pragma unroll
            for (int t2 = 0; t2 < 2; t2++)
                #pragma unroll
                for (int nt = 0; nt < 8; nt++)
                    mma16816(acc[t2][nt], a[t2], &b[nt >> 1][(nt & 1) * 2]);
        }
        #pragma unroll
        for (int t2 = 0; t2 < 2; t2++) {
            int r0 = wr + t2 * 16 + (lane >> 2);
            #pragma unroll
            for (int nt = 0; nt < 8; nt++) {
                int col = nt * 8 + 2 * (lane & 3);
                float bb0 = __ldg(&b2[col]), bb1 = __ldg(&b2[col + 1]);
                float v00 = fmaxf(acc[t2][nt][0] + bb0, 0.f);
                float v01 = fmaxf(acc[t2][nt][1] + bb1, 0.f);
                float v10 = fmaxf(acc[t2][nt][2] + bb0, 0.f);
                float v11 = fmaxf(acc[t2][nt][3] + bb1, 0.f);
                uint32_t inb = (col & 7) * 2;
                sts32(sb + ESA_G + r0 * 128 + (((nt) ^ (r0 & 7)) << 4) + inb,
                      pack_bf2(v00, v01));
                int r1 = r0 + 8;
                sts32(sb + ESA_G + r1 * 128 + (((nt) ^ (r1 & 7)) << 4) + inb,
                      pack_bf2(v10, v11));
            }
        }
    }
    __syncwarp();

    // ================= layer 3: (128x64) @ (16x64)^T -> sigmoid out =========
    {
        float acc[2][2][4];
        #pragma unroll
        for (int a = 0; a < 2; a++)
            #pragma unroll
            for (int b = 0; b < 2; b++)
                #pragma unroll
                for (int c = 0; c < 4; c++) acc[a][b][c] = 0.f;

        #pragma unroll
        for (int k16 = 0; k16 < 4; k16++) {
            uint32_t a[2][4], b[4];
            #pragma unroll
            for (int t2 = 0; t2 < 2; t2++) {
                int r = wr + t2 * 16 + ((m & 1) << 3) + rr;
                int c = k16 * 2 + (m >> 1);
                ldsm4(sb + ESA_G + r * 128 + ((c ^ (r & 7)) << 4), a[t2]);
            }
            {
                int n = ((m >> 1) << 3) + rr;      // 16 n rows
                int c = k16 * 2 + (m & 1);
                ldsm4(sb + ESA_W3 + n * 128 + ((c ^ (n & 7)) << 4), b);
            }
            #pragma unroll
            for (int t2 = 0; t2 < 2; t2++) {
                mma16816(acc[t2][0], a[t2], &b[0]);
                mma16816(acc[t2][1], a[t2], &b[2]);
            }
        }
        // sigmoid epilogue -> gmem (cols 0..9 of 16)
        #pragma unroll
        for (int t2 = 0; t2 < 2; t2++) {
            int r0 = wr + t2 * 16 + (lane >> 2);
            long eg = (long)bt * EDGES + e0 + r0;
            #pragma unroll
            for (int nt = 0; nt < 2; nt++) {
                int col = nt * 8 + 2 * (lane & 3);
                if (col < EC) {
                    float bb0 = __ldg(&bi[col]), bb1 = __ldg(&bi[col + 1]);
                    float s00 = 1.f / (1.f + __expf(-(acc[t2][nt][0] + bb0)));
                    float s01 = 1.f / (1.f + __expf(-(acc[t2][nt][1] + bb1)));
                    float s10 = 1.f / (1.f + __expf(-(acc[t2][nt][2] + bb0)));
                    float s11 = 1.f / (1.f + __expf(-(acc[t2][nt][3] + bb1)));
                    *(float2*)(out + eg * EC + col) = make_float2(s00, s01);
                    *(float2*)(out + (eg + 8) * EC + col) = make_float2(s10, s11);
                }
            }
        }
    }
}

// ---------------- launch ----------------------------------------------------
extern "C" void kernel_launch(void* const* d_in, const int* in_sizes, int n_in,
                              void* d_out, int out_size)
{
    const float* roi    = (const float*)d_in[0];
    const float* bboxes = (const float*)d_in[1];
    const float* dirs   = (const float*)d_in[2];
    const float* prio   = (const float*)d_in[3];
    const int*   eidx   = (const int*)  d_in[4];
    const float* np_w1  = (const float*)d_in[5];
    const float* np_b1  = (const float*)d_in[6];
    const float* bn1_g  = (const float*)d_in[7];
    const float* bn1_b  = (const float*)d_in[8];
    const float* bn1_rm = (const float*)d_in[9];
    const float* bn1_rv = (const float*)d_in[10];
    const float* np_w2  = (const float*)d_in[11];
    const float* np_b2  = (const float*)d_in[12];
    const float* bn2_g  = (const float*)d_in[13];
    const float* bn2_b  = (const float*)d_in[14];
    const float* bn2_rm = (const float*)d_in[15];
    const float* bn2_rv = (const float*)d_in[16];
    const float* np_w3  = (const float*)d_in[17];
    const float* np_b3  = (const float*)d_in[18];
    const float* ni_w   = (const float*)d_in[19];
    const float* ni_b   = (const float*)d_in[20];
    const float* ep_w1  = (const float*)d_in[21];
    const float* ep_b1  = (const float*)d_in[22];
    const float* ep_w2  = (const float*)d_in[23];
    const float* ep_b2  = (const float*)d_in[24];
    const float* ei_w   = (const float*)d_in[25];
    const float* ei_b   = (const float*)d_in[26];

    float* out = (float*)d_out;

    float *h1, *h2, *h3;
    __nv_bfloat16 *ew1t, *ew2t, *ew3t;
    cudaGetSymbolAddress((void**)&h1, g_h1);
    cudaGetSymbolAddress((void**)&h2, g_h2);
    cudaGetSymbolAddress((void**)&h3, g_h3);
    cudaGetSymbolAddress((void**)&ew1t, g_ew1t);
    cudaGetSymbolAddress((void**)&ew2t, g_ew2t);
    cudaGetSymbolAddress((void**)&ew3t, g_ew3t);

    cudaFuncSetAttribute(edge_mma_kernel,
                         cudaFuncAttributeMaxDynamicSharedMemorySize, EDGE_SMEM);

    // edge path on tensor cores
    prep_edge_weights<<<8, 256>>>(ep_w1, ep_w2, ei_w, ew1t, ew2t, ew3t);
    edge_mma_kernel<<<NEDGE / 128, 128, EDGE_SMEM>>>(
        bboxes, dirs, prio, eidx, ew1t, ew2t, ew3t,
        ep_b1, ep_b2, ei_b, out + NODE_OUT_ELEMS);

    // node MLP chain (SIMT fp32, measured-best)
    {
        dim3 grid(H1 / 128, NROWS / 128);
        gemm_relu_kernel<NROWS, H1, FDIM, 1><<<grid, 256>>>(
            roi, np_w1, np_b1, bn1_g, bn1_b, bn1_rm, bn1_rv, h1);
    }
    {
        dim3 grid(H2 / 128, NROWS / 128);
        gemm_relu_kernel<NROWS, H2, H1, 1><<<grid, 256>>>(
            h1, np_w2, np_b2, bn2_g, bn2_b, bn2_rm, bn2_rv, h2);
    }
    {
        dim3 grid(H3 / 128, NROWS / 128);
        gemm_relu_kernel<NROWS, H3, H2, 0><<<grid, 256>>>(
            h2, np_w3, np_b3, nullptr, nullptr, nullptr, nullptr, h3);
    }
    node_out_kernel<<<NODE_OUT_ELEMS / 256, 256>>>(h3, ni_w, ni_b, out);
}

// round 5
// speedup vs baseline: 3.0095x; 1.8477x over previous
#include <cuda_runtime.h>
#include <cuda_bf16.h>
#include <cstdint>

// ---------------- problem constants (fixed by setup_inputs) ----------------
#define BATCH   32
#define NNODE   512
#define NROWS   (BATCH*NNODE)      // 16384
#define FDIM    1024
#define H1      512
#define H2      256
#define H3      128
#define NC      8
#define EDGES   32768              // per batch
#define NEDGE   (BATCH*EDGES)      // 1048576
#define EH      64
#define EC      10
#define CATTR   9
#define NODE_OUT_ELEMS (NROWS*NC)  // 131072

// ---------------- scratch (device globals; no allocation allowed) ----------
__device__ __nv_bfloat16 g_xhi[NROWS * FDIM], g_xlo[NROWS * FDIM];  // split roi
__device__ __nv_bfloat16 g_h1hi[NROWS * H1],  g_h1lo[NROWS * H1];
__device__ __nv_bfloat16 g_h2hi[NROWS * H2],  g_h2lo[NROWS * H2];
__device__ float         g_h3[NROWS * H3];
__device__ __nv_bfloat16 g_w1hi[H1 * FDIM],   g_w1lo[H1 * FDIM];
__device__ __nv_bfloat16 g_w2hi[H2 * H1],     g_w2lo[H2 * H1];
__device__ __nv_bfloat16 g_w3hi[H3 * H2],     g_w3lo[H3 * H2];
__device__ __nv_bfloat16 g_ew1t[64 * 32];
__device__ __nv_bfloat16 g_ew2t[64 * 64];
__device__ __nv_bfloat16 g_ew3t[16 * 64];

// ---------------- helpers ----------------------------------------------------
__device__ __forceinline__ uint32_t smem_u32(const void* p) {
    uint32_t a;
    asm("{ .reg .u64 t; cvta.to.shared.u64 t, %1; cvt.u32.u64 %0, t; }"
        : "=r"(a) : "l"(p));
    return a;
}
__device__ __forceinline__ void ldsm4(uint32_t addr, uint32_t* r) {
    asm volatile("ldmatrix.sync.aligned.m8n8.x4.shared.b16 {%0,%1,%2,%3}, [%4];"
                 : "=r"(r[0]), "=r"(r[1]), "=r"(r[2]), "=r"(r[3]) : "r"(addr));
}
__device__ __forceinline__ void mma16816(float* c, const uint32_t* a, const uint32_t* b) {
    asm volatile(
        "mma.sync.aligned.m16n8k16.row.col.f32.bf16.bf16.f32 "
        "{%0,%1,%2,%3}, {%4,%5,%6,%7}, {%8,%9}, {%0,%1,%2,%3};"
        : "+f"(c[0]), "+f"(c[1]), "+f"(c[2]), "+f"(c[3])
        : "r"(a[0]), "r"(a[1]), "r"(a[2]), "r"(a[3]), "r"(b[0]), "r"(b[1]));
}
__device__ __forceinline__ void sts128(uint32_t addr, uint4 v) {
    asm volatile("st.shared.v4.b32 [%0], {%1,%2,%3,%4};"
                 :: "r"(addr), "r"(v.x), "r"(v.y), "r"(v.z), "r"(v.w) : "memory");
}
__device__ __forceinline__ void sts32(uint32_t addr, uint32_t v) {
    asm volatile("st.shared.b32 [%0], %1;" :: "r"(addr), "r"(v) : "memory");
}
__device__ __forceinline__ uint32_t pack_bf2(float a, float b) {
    __nv_bfloat162 h = __floats2bfloat162_rn(a, b);
    uint32_t u; memcpy(&u, &h, 4); return u;
}
__device__ __forceinline__ void cp16(uint32_t dst, const void* src) {
    asm volatile("cp.async.cg.shared.global [%0], [%1], 16;"
                 :: "r"(dst), "l"(src) : "memory");
}
__device__ __forceinline__ void cp_commit() {
    asm volatile("cp.async.commit_group;" ::: "memory");
}
#define CP_WAIT(n) asm volatile("cp.async.wait_group %0;" :: "n"(n) : "memory")

// ---------------- split-bf16 mma GEMM, cp.async 3-stage pipeline ------------
// C = relu((A@B^T + bias)[bn-fold]); A,B pre-split bf16 hi/lo, row-major KxN^T.
// CTA tile 128x128, 8 warps (32x64 warp tiles), K-chunk 32, 3 stages.
static constexpr int STAGE_BYTES = 32768;   // Ahi|Alo|Bhi|Blo x 8KB
static constexpr int GEMM_SMEM = 3 * STAGE_BYTES;

template<int K, int N, int EPI, int OSPLIT>
__global__ __launch_bounds__(256)
void gemm_mma2(const __nv_bfloat16* __restrict__ Ahi, const __nv_bfloat16* __restrict__ Alo,
               const __nv_bfloat16* __restrict__ Bhi, const __nv_bfloat16* __restrict__ Blo,
               const float* __restrict__ bias,
               const float* __restrict__ bng, const float* __restrict__ bnb,
               const float* __restrict__ bnrm, const float* __restrict__ bnrv,
               float* __restrict__ Cf,
               __nv_bfloat16* __restrict__ Chi, __nv_bfloat16* __restrict__ Clo)
{
    extern __shared__ char sm_raw[];
    const uint32_t sb = smem_u32(sm_raw);
    const int tid = threadIdx.x;
    const int lane = tid & 31, w = tid >> 5;
    const int bn = blockIdx.x, bm = blockIdx.y;
    const int wr = (w & 3) * 32;
    const int wc = (w >> 2) * 64;

    // ---- per-thread async-copy slots: 8 x 16B per stage ----
    const __nv_bfloat16* srcs[8];
    uint32_t dsts[8];
    #pragma unroll
    for (int i = 0; i < 8; i++) {
        int idx = i * 256 + tid;          // 0..2047
        int slab = idx >> 9;              // 0:Ahi 1:Alo 2:Bhi 3:Blo
        int within = idx & 511;
        int r = within >> 2, c = within & 3;
        const __nv_bfloat16* base = (slab == 0) ? Ahi : (slab == 1) ? Alo
                                   : (slab == 2) ? Bhi : Blo;
        int row0 = (slab < 2) ? bm * 128 : bn * 128;
        srcs[i] = base + (size_t)(row0 + r) * K + c * 8;
        dsts[i] = slab * 8192 + r * 64 + ((c ^ ((r >> 1) & 3)) << 4);
    }
    auto ISSUE = [&](int ck) {
        const uint32_t st = sb + (ck % 3) * STAGE_BYTES;
        #pragma unroll
        for (int i = 0; i < 8; i++)
            cp16(st + dsts[i], srcs[i] + ck * 32);
    };

    float acc[2][8][4];
    #pragma unroll
    for (int a = 0; a < 2; a++)
        #pragma unroll
        for (int b = 0; b < 8; b++)
            #pragma unroll
            for (int c = 0; c < 4; c++) acc[a][b][c] = 0.f;

    const int m = lane >> 3, rr = lane & 7;

    auto COMPUTE = [&](int stage) {
        const uint32_t aB = sb + stage * STAGE_BYTES;
        const uint32_t bB = aB + 16384;
        #pragma unroll
        for (int ks = 0; ks < 2; ks++) {
            const int ckb = ks * 2;
            uint32_t ah[2][4], al[2][4], bh[4][4], bl[4][4];
            #pragma unroll
            for (int t2 = 0; t2 < 2; t2++) {
                const int r_l = wr + t2 * 16 + ((m & 1) << 3) + rr;
                const int c_l = ckb + (m >> 1);
                const uint32_t off = r_l * 64 + ((c_l ^ ((r_l >> 1) & 3)) << 4);
                ldsm4(aB + off, ah[t2]);
                ldsm4(aB + 8192 + off, al[t2]);
            }
            #pragma unroll
            for (int p = 0; p < 4; p++) {
                const int n_l = wc + p * 16 + ((m >> 1) << 3) + rr;
                const int c_l = ckb + (m & 1);
                const uint32_t off = n_l * 64 + ((c_l ^ ((n_l >> 1) & 3)) << 4);
                ldsm4(bB + off, bh[p]);
                ldsm4(bB + 8192 + off, bl[p]);
            }
            #pragma unroll
            for (int t2 = 0; t2 < 2; t2++)
                #pragma unroll
                for (int nt = 0; nt < 8; nt++) {
                    const uint32_t* Bh = &bh[nt >> 1][(nt & 1) * 2];
                    const uint32_t* Bl = &bl[nt >> 1][(nt & 1) * 2];
                    mma16816(acc[t2][nt], ah[t2], Bh);
                    mma16816(acc[t2][nt], al[t2], Bh);
                    mma16816(acc[t2][nt], ah[t2], Bl);
                }
        }
    };

    constexpr int NCH = K / 32;
    ISSUE(0); cp_commit();
    ISSUE(1); cp_commit();
    for (int c = 0; c < NCH; c++) {
        CP_WAIT(1);
        __syncthreads();
        COMPUTE(c % 3);
        __syncthreads();
        if (c + 2 < NCH) ISSUE(c + 2);
        cp_commit();
    }

    // ---------------- epilogue ----------------
    #pragma unroll
    for (int t2 = 0; t2 < 2; t2++) {
        const int row0 = bm * 128 + wr + t2 * 16 + (lane >> 2);
        #pragma unroll
        for (int nt = 0; nt < 8; nt++) {
            const int col = bn * 128 + wc + nt * 8 + 2 * (lane & 3);
            float b0 = __ldg(&bias[col]), b1 = __ldg(&bias[col + 1]);
            float s0 = 1.f, s1 = 1.f, f0 = 0.f, f1 = 0.f;
            if (EPI) {
                s0 = __ldg(&bng[col]) * rsqrtf(__ldg(&bnrv[col]) + 1e-5f);
                f0 = __ldg(&bnb[col]) - __ldg(&bnrm[col]) * s0;
                s1 = __ldg(&bng[col + 1]) * rsqrtf(__ldg(&bnrv[col + 1]) + 1e-5f);
                f1 = __ldg(&bnb[col + 1]) - __ldg(&bnrm[col + 1]) * s1;
            }
            float v00 = acc[t2][nt][0] + b0, v01 = acc[t2][nt][1] + b1;
            float v10 = acc[t2][nt][2] + b0, v11 = acc[t2][nt][3] + b1;
            if (EPI) {
                v00 = v00 * s0 + f0; v01 = v01 * s1 + f1;
                v10 = v10 * s0 + f0; v11 = v11 * s1 + f1;
            }
            v00 = fmaxf(v00, 0.f); v01 = fmaxf(v01, 0.f);
            v10 = fmaxf(v10, 0.f); v11 = fmaxf(v11, 0.f);
            if (OSPLIT) {
                __nv_bfloat162 h0 = __floats2bfloat162_rn(v00, v01);
                __nv_bfloat162 l0 = __floats2bfloat162_rn(v00 - __bfloat162float(h0.x),
                                                          v01 - __bfloat162float(h0.y));
                __nv_bfloat162 h1 = __floats2bfloat162_rn(v10, v11);
                __nv_bfloat162 l1 = __floats2bfloat162_rn(v10 - __bfloat162float(h1.x),
                                                          v11 - __bfloat162float(h1.y));
                *(__nv_bfloat162*)(Chi + (size_t)row0 * N + col) = h0;
                *(__nv_bfloat162*)(Clo + (size_t)row0 * N + col) = l0;
                *(__nv_bfloat162*)(Chi + (size_t)(row0 + 8) * N + col) = h1;
                *(__nv_bfloat162*)(Clo + (size_t)(row0 + 8) * N + col) = l1;
            } else {
                *(float2*)(Cf + (size_t)row0 * N + col) = make_float2(v00, v01);
                *(float2*)(Cf + (size_t)(row0 + 8) * N + col) = make_float2(v10, v11);
            }
        }
    }
}

// ---------------- fp32 -> bf16 hi/lo split (for roi) ------------------------
__global__ __launch_bounds__(256)
void split_f32(const float4* __restrict__ in,
               uint2* __restrict__ hi, uint2* __restrict__ lo)
{
    int i = blockIdx.x * 256 + threadIdx.x;
    float4 v = in[i];
    __nv_bfloat162 h0 = __floats2bfloat162_rn(v.x, v.y);
    __nv_bfloat162 h1 = __floats2bfloat162_rn(v.z, v.w);
    __nv_bfloat162 l0 = __floats2bfloat162_rn(v.x - __bfloat162float(h0.x),
                                              v.y - __bfloat162float(h0.y));
    __nv_bfloat162 l1 = __floats2bfloat162_rn(v.z - __bfloat162float(h1.x),
                                              v.w - __bfloat162float(h1.y));
    uint2 uh, ul;
    memcpy(&uh.x, &h0, 4); memcpy(&uh.y, &h1, 4);
    memcpy(&ul.x, &l0, 4); memcpy(&ul.y, &l1, 4);
    hi[i] = uh; lo[i] = ul;
}

// ------- weight transpose + bf16 hi/lo split: in (R x C) -> out (C x R) -----
__global__ void transpose_split(const float* __restrict__ in,
                                __nv_bfloat16* __restrict__ ohi,
                                __nv_bfloat16* __restrict__ olo,
                                int R, int C)
{
    __shared__ float t[32][33];
    int x = blockIdx.x * 32 + threadIdx.x;
    int y = blockIdx.y * 32 + threadIdx.y;
    #pragma unroll
    for (int i = 0; i < 32; i += 8)
        t[threadIdx.y + i][threadIdx.x] = in[(size_t)(y + i) * C + x];
    __syncthreads();
    x = blockIdx.y * 32 + threadIdx.x;
    y = blockIdx.x * 32 + threadIdx.y;
    #pragma unroll
    for (int i = 0; i < 32; i += 8) {
        float v = t[threadIdx.x][threadIdx.y + i];
        __nv_bfloat16 h = __float2bfloat16(v);
        ohi[(size_t)(y + i) * R + x] = h;
        olo[(size_t)(y + i) * R + x] = __float2bfloat16(v - __bfloat162float(h));
    }
}

// ---------------- node head: h3(16384x128) @ ni_w(128x8) -> sigmoid ---------
__global__ __launch_bounds__(256)
void node_out_kernel(const float* __restrict__ h3,
                     const float* __restrict__ w,
                     const float* __restrict__ b,
                     float* __restrict__ out)
{
    int t = blockIdx.x * 256 + threadIdx.x;
    int row = t >> 3;
    int j = t & 7;
    const float* x = h3 + (size_t)row * H3;
    float acc = b[j];
    #pragma unroll 8
    for (int k = 0; k < H3; k++)
        acc += x[k] * __ldg(&w[k * NC + j]);
    out[t] = 1.f / (1.f + __expf(-acc));
}

// ---------------- edge weight prep: transpose+pad to bf16 -------------------
__global__ void prep_edge_weights(const float* __restrict__ w1,
                                  const float* __restrict__ w2,
                                  const float* __restrict__ wi,
                                  __nv_bfloat16* __restrict__ o1,
                                  __nv_bfloat16* __restrict__ o2,
                                  __nv_bfloat16* __restrict__ o3)
{
    int t = blockIdx.x * 256 + threadIdx.x;
    int stride = gridDim.x * 256;
    for (int i = t; i < 64 * 32; i += stride) {
        int n = i >> 5, k = i & 31;
        o1[i] = (k < 18) ? __float2bfloat16(w1[k * 64 + n]) : __nv_bfloat16(0.f);
    }
    for (int i = t; i < 64 * 64; i += stride) {
        int n = i >> 6, k = i & 63;
        o2[i] = __float2bfloat16(w2[k * 64 + n]);
    }
    for (int i = t; i < 16 * 64; i += stride) {
        int n = i >> 6, k = i & 63;
        o3[i] = (n < EC) ? __float2bfloat16(wi[k * EC + n]) : __nv_bfloat16(0.f);
    }
}

// ---------------- edge MLP on tensor cores (verified R4) --------------------
static constexpr int ESA_ATTR = 0;
static constexpr int ESA_W1   = 10240;
static constexpr int ESA_W2   = 14336;
static constexpr int ESA_W3   = 22528;
static constexpr int ESA_A1   = 24576;
static constexpr int ESA_H    = 32768;
static constexpr int ESA_G    = 49152;
static constexpr int EDGE_SMEM = 65536;

__global__ __launch_bounds__(128)
void edge_mma_kernel(const float* __restrict__ bboxes,
                     const float* __restrict__ dirs,
                     const float* __restrict__ prio,
                     const int*   __restrict__ eidx,
                     const __nv_bfloat16* __restrict__ w1t,
                     const __nv_bfloat16* __restrict__ w2t,
                     const __nv_bfloat16* __restrict__ w3t,
                     const float* __restrict__ b1,
                     const float* __restrict__ b2,
                     const float* __restrict__ bi,
                     float* __restrict__ out)
{
    extern __shared__ char sm[];
    const uint32_t sb = smem_u32(sm);
    const int tid = threadIdx.x;
    const int lane = tid & 31, w = tid >> 5;
    const int bt = blockIdx.x >> 8;
    const int e0 = (blockIdx.x & 255) * 128;

    __nv_bfloat16* sAttr = (__nv_bfloat16*)(sm + ESA_ATTR);
    const float inv = 1.f / 1024.f;
    for (int n = tid; n < NNODE; n += 128) {
        int gn = bt * NNODE + n;
        float4 bb = *(const float4*)&bboxes[(size_t)gn * 4];
        float4 dd = *(const float4*)&dirs[(size_t)gn * 4];
        float pr = prio[gn];
        __nv_bfloat16* a = sAttr + n * 10;
        a[0] = __float2bfloat16(bb.x * inv);
        a[1] = __float2bfloat16(bb.y * inv);
        a[2] = __float2bfloat16(bb.z * inv);
        a[3] = __float2bfloat16(bb.w * inv);
        a[4] = __float2bfloat16(dd.x);
        a[5] = __float2bfloat16(dd.y);
        a[6] = __float2bfloat16(dd.z);
        a[7] = __float2bfloat16(dd.w);
        a[8] = __float2bfloat16(pr);
    }
    for (int i = tid; i < 64 * 4; i += 128) {
        int r = i >> 2, c = i & 3;
        uint4 v = ((const uint4*)w1t)[r * 4 + c];
        sts128(sb + ESA_W1 + r * 64 + ((c ^ ((r >> 1) & 3)) << 4), v);
    }
    for (int i = tid; i < 64 * 8; i += 128) {
        int r = i >> 3, c = i & 7;
        uint4 v = ((const uint4*)w2t)[r * 8 + c];
        sts128(sb + ESA_W2 + r * 128 + ((c ^ (r & 7)) << 4), v);
    }
    for (int i = tid; i < 16 * 8; i += 128) {
        int r = i >> 3, c = i & 7;
        uint4 v = ((const uint4*)w3t)[r * 8 + c];
        sts128(sb + ESA_W3 + r * 128 + ((c ^ (r & 7)) << 4), v);
    }
    __syncthreads();

    {
        const int ebase = bt * 2 * EDGES + e0 + tid;
        const int src = eidx[ebase];
        const int dst = eidx[ebase + EDGES];
        const __nv_bfloat16* as = sAttr + src * 10;
        const __nv_bfloat16* ad = sAttr + dst * 10;
        uint16_t v[32];
        #pragma unroll
        for (int c = 0; c < 9; c++) { memcpy(&v[c], &as[c], 2); memcpy(&v[9 + c], &ad[c], 2); }
        #pragma unroll
        for (int c = 18; c < 32; c++) v[c] = 0;
        const int swz = (tid >> 1) & 3;
        #pragma unroll
        for (int ch = 0; ch < 4; ch++) {
            uint4 p;
            p.x = (uint32_t)v[ch*8+0] | ((uint32_t)v[ch*8+1] << 16);
            p.y = (uint32_t)v[ch*8+2] | ((uint32_t)v[ch*8+3] << 16);
            p.z = (uint32_t)v[ch*8+4] | ((uint32_t)v[ch*8+5] << 16);
            p.w = (uint32_t)v[ch*8+6] | ((uint32_t)v[ch*8+7] << 16);
            sts128(sb + ESA_A1 + tid * 64 + ((ch ^ swz) << 4), p);
        }
    }
    __syncthreads();

    const int m = lane >> 3, rr = lane & 7;
    const int wr = w * 32;

    {
        float acc[2][8][4];
        #pragma unroll
        for (int a = 0; a < 2; a++)
            #pragma unroll
            for (int b = 0; b < 8; b++)
                #pragma unroll
                for (int c = 0; c < 4; c++) acc[a][b][c] = 0.f;

        #pragma unroll
        for (int k16 = 0; k16 < 2; k16++) {
            uint32_t a[2][4], b[4][4];
            #pragma unroll
            for (int t2 = 0; t2 < 2; t2++) {
                int r = wr + t2 * 16 + ((m & 1) << 3) + rr;
                int c = k16 * 2 + (m >> 1);
                ldsm4(sb + ESA_A1 + r * 64 + ((c ^ ((r >> 1) & 3)) << 4), a[t2]);
            }
            #pragma unroll
            for (int p = 0; p < 4; p++) {
                int n = p * 16 + ((m >> 1) << 3) + rr;
                int c = k16 * 2 + (m & 1);
                ldsm4(sb + ESA_W1 + n * 64 + ((c ^ ((n >> 1) & 3)) << 4), b[p]);
            }
            #pragma unroll
            for (int t2 = 0; t2 < 2; t2++)
                #pragma unroll
                for (int nt = 0; nt < 8; nt++)
                    mma16816(acc[t2][nt], a[t2], &b[nt >> 1][(nt & 1) * 2]);
        }
        #pragma unroll
        for (int t2 = 0; t2 < 2; t2++) {
            int r0 = wr + t2 * 16 + (lane >> 2);
            #pragma unroll
            for (int nt = 0; nt < 8; nt++) {
                int col = nt * 8 + 2 * (lane & 3);
                float bb0 = __ldg(&b1[col]), bb1 = __ldg(&b1[col + 1]);
                float v00 = fmaxf(acc[t2][nt][0] + bb0, 0.f);
                float v01 = fmaxf(acc[t2][nt][1] + bb1, 0.f);
                float v10 = fmaxf(acc[t2][nt][2] + bb0, 0.f);
                float v11 = fmaxf(acc[t2][nt][3] + bb1, 0.f);
                uint32_t inb = (col & 7) * 2;
                sts32(sb + ESA_H + r0 * 128 + (((nt) ^ (r0 & 7)) << 4) + inb,
                      pack_bf2(v00, v01));
                int r1 = r0 + 8;
                sts32(sb + ESA_H + r1 * 128 + (((nt) ^ (r1 & 7)) << 4) + inb,
                      pack_bf2(v10, v11));
            }
        }
    }
    __syncwarp();

    {
        float acc[2][8][4];
        #pragma unroll
        for (int a = 0; a < 2; a++)
            #pragma unroll
            for (int b = 0; b < 8; b++)
                #pragma unroll
                for (int c = 0; c < 4; c++) acc[a][b][c] = 0.f;

        #pragma unroll
        for (int k16 = 0; k16 < 4; k16++) {
            uint32_t a[2][4], b[4][4];
            #pragma unroll
            for (int t2 = 0; t2 < 2; t2++) {
                int r = wr + t2 * 16 + ((m & 1) << 3) + rr;
                int c = k16 * 2 + (m >> 1);
                ldsm4(sb + ESA_H + r * 128 + ((c ^ (r & 7)) << 4), a[t2]);
            }
            #pragma unroll
            for (int p = 0; p < 4; p++) {
                int n = p * 16 + ((m >> 1) << 3) + rr;
                int c = k16 * 2 + (m & 1);
                ldsm4(sb + ESA_W2 + n * 128 + ((c ^ (n & 7)) << 4), b[p]);
            }
            #pragma unroll
            for (int t2 = 0; t2 < 2; t2++)
                #pragma unroll
                for (int nt = 0; nt < 8; nt++)
                    mma16816(acc[t2][nt], a[t2], &b[nt >> 1][(nt & 1) * 2]);
        }
        #pragma unroll
        for (int t2 = 0; t2 < 2; t2++) {
            int r0 = wr + t2 * 16 + (lane >> 2);
            #pragma unroll
            for (int nt = 0; nt < 8; nt++) {
                int col = nt * 8 + 2 * (lane & 3);
                float bb0 = __ldg(&b2[col]), bb1 = __ldg(&b2[col + 1]);
                float v00 = fmaxf(acc[t2][nt][0] + bb0, 0.f);
                float v01 = fmaxf(acc[t2][nt][1] + bb1, 0.f);
                float v10 = fmaxf(acc[t2][nt][2] + bb0, 0.f);
                float v11 = fmaxf(acc[t2][nt][3] + bb1, 0.f);
                uint32_t inb = (col & 7) * 2;
                sts32(sb + ESA_G + r0 * 128 + (((nt) ^ (r0 & 7)) << 4) + inb,
                      pack_bf2(v00, v01));
                int r1 = r0 + 8;
                sts32(sb + ESA_G + r1 * 128 + (((nt) ^ (r1 & 7)) << 4) + inb,
                      pack_bf2(v10, v11));
            }
        }
    }
    __syncwarp();

    {
        float acc[2][2][4];
        #pragma unroll
        for (int a = 0; a < 2; a++)
            #pragma unroll
            for (int b = 0; b < 2; b++)
                #pragma unroll
                for (int c = 0; c < 4; c++) acc[a][b][c] = 0.f;

        #pragma unroll
        for (int k16 = 0; k16 < 4; k16++) {
            uint32_t a[2][4], b[4];
            #pragma unroll
            for (int t2 = 0; t2 < 2; t2++) {
                int r = wr + t2 * 16 + ((m & 1) << 3) + rr;
                int c = k16 * 2 + (m >> 1);
                ldsm4(sb + ESA_G + r * 128 + ((c ^ (r & 7)) << 4), a[t2]);
            }
            {
                int n = ((m >> 1) << 3) + rr;
                int c = k16 * 2 + (m & 1);
                ldsm4(sb + ESA_W3 + n * 128 + ((c ^ (n & 7)) << 4), b);
            }
            #pragma unroll
            for (int t2 = 0; t2 < 2; t2++) {
                mma16816(acc[t2][0], a[t2], &b[0]);
                mma16816(acc[t2][1], a[t2], &b[2]);
            }
        }
        #pragma unroll
        for (int t2 = 0; t2 < 2; t2++) {
            int r0 = wr + t2 * 16 + (lane >> 2);
            long eg = (long)bt * EDGES + e0 + r0;
            #pragma unroll
            for (int nt = 0; nt < 2; nt++) {
                int col = nt * 8 + 2 * (lane & 3);
                if (col < EC) {
                    float bb0 = __ldg(&bi[col]), bb1 = __ldg(&bi[col + 1]);
                    float s00 = 1.f / (1.f + __expf(-(acc[t2][nt][0] + bb0)));
                    float s01 = 1.f / (1.f + __expf(-(acc[t2][nt][1] + bb1)));
                    float s10 = 1.f / (1.f + __expf(-(acc[t2][nt][2] + bb0)));
                    float s11 = 1.f / (1.f + __expf(-(acc[t2][nt][3] + bb1)));
                    *(float2*)(out + eg * EC + col) = make_float2(s00, s01);
                    *(float2*)(out + (eg + 8) * EC + col) = make_float2(s10, s11);
                }
            }
        }
    }
}

// ---------------- launch ----------------------------------------------------
extern "C" void kernel_launch(void* const* d_in, const int* in_sizes, int n_in,
                              void* d_out, int out_size)
{
    const float* roi    = (const float*)d_in[0];
    const float* bboxes = (const float*)d_in[1];
    const float* dirs   = (const float*)d_in[2];
    const float* prio   = (const float*)d_in[3];
    const int*   eidx   = (const int*)  d_in[4];
    const float* np_w1  = (const float*)d_in[5];
    const float* np_b1  = (const float*)d_in[6];
    const float* bn1_g  = (const float*)d_in[7];
    const float* bn1_b  = (const float*)d_in[8];
    const float* bn1_rm = (const float*)d_in[9];
    const float* bn1_rv = (const float*)d_in[10];
    const float* np_w2  = (const float*)d_in[11];
    const float* np_b2  = (const float*)d_in[12];
    const float* bn2_g  = (const float*)d_in[13];
    const float* bn2_b  = (const float*)d_in[14];
    const float* bn2_rm = (const float*)d_in[15];
    const float* bn2_rv = (const float*)d_in[16];
    const float* np_w3  = (const float*)d_in[17];
    const float* np_b3  = (const float*)d_in[18];
    const float* ni_w   = (const float*)d_in[19];
    const float* ni_b   = (const float*)d_in[20];
    const float* ep_w1  = (const float*)d_in[21];
    const float* ep_b1  = (const float*)d_in[22];
    const float* ep_w2  = (const float*)d_in[23];
    const float* ep_b2  = (const float*)d_in[24];
    const float* ei_w   = (const float*)d_in[25];
    const float* ei_b   = (const float*)d_in[26];

    float* out = (float*)d_out;

    __nv_bfloat16 *xhi, *xlo, *h1hi, *h1lo, *h2hi, *h2lo;
    __nv_bfloat16 *w1hi, *w1lo, *w2hi, *w2lo, *w3hi, *w3lo;
    __nv_bfloat16 *ew1t, *ew2t, *ew3t;
    float* h3;
    cudaGetSymbolAddress((void**)&xhi, g_xhi);
    cudaGetSymbolAddress((void**)&xlo, g_xlo);
    cudaGetSymbolAddress((void**)&h1hi, g_h1hi);
    cudaGetSymbolAddress((void**)&h1lo, g_h1lo);
    cudaGetSymbolAddress((void**)&h2hi, g_h2hi);
    cudaGetSymbolAddress((void**)&h2lo, g_h2lo);
    cudaGetSymbolAddress((void**)&h3, g_h3);
    cudaGetSymbolAddress((void**)&w1hi, g_w1hi);
    cudaGetSymbolAddress((void**)&w1lo, g_w1lo);
    cudaGetSymbolAddress((void**)&w2hi, g_w2hi);
    cudaGetSymbolAddress((void**)&w2lo, g_w2lo);
    cudaGetSymbolAddress((void**)&w3hi, g_w3hi);
    cudaGetSymbolAddress((void**)&w3lo, g_w3lo);
    cudaGetSymbolAddress((void**)&ew1t, g_ew1t);
    cudaGetSymbolAddress((void**)&ew2t, g_ew2t);
    cudaGetSymbolAddress((void**)&ew3t, g_ew3t);

    cudaFuncSetAttribute(edge_mma_kernel,
                         cudaFuncAttributeMaxDynamicSharedMemorySize, EDGE_SMEM);
    cudaFuncSetAttribute(gemm_mma2<FDIM, H1, 1, 1>,
                         cudaFuncAttributeMaxDynamicSharedMemorySize, GEMM_SMEM);
    cudaFuncSetAttribute(gemm_mma2<H1, H2, 1, 1>,
                         cudaFuncAttributeMaxDynamicSharedMemorySize, GEMM_SMEM);
    cudaFuncSetAttribute(gemm_mma2<H2, H3, 0, 0>,
                         cudaFuncAttributeMaxDynamicSharedMemorySize, GEMM_SMEM);

    // prep: edge weights, node weight transpose+split, roi split
    prep_edge_weights<<<8, 256>>>(ep_w1, ep_w2, ei_w, ew1t, ew2t, ew3t);
    {
        dim3 b(32, 8);
        transpose_split<<<dim3(H1 / 32, FDIM / 32), b>>>(np_w1, w1hi, w1lo, FDIM, H1);
        transpose_split<<<dim3(H2 / 32, H1 / 32), b>>>(np_w2, w2hi, w2lo, H1, H2);
        transpose_split<<<dim3(H3 / 32, H2 / 32), b>>>(np_w3, w3hi, w3lo, H2, H3);
    }
    split_f32<<<NROWS * FDIM / 4 / 256, 256>>>((const float4*)roi,
                                               (uint2*)xhi, (uint2*)xlo);

    // edge path
    edge_mma_kernel<<<NEDGE / 128, 128, EDGE_SMEM>>>(
        bboxes, dirs, prio, eidx, ew1t, ew2t, ew3t,
        ep_b1, ep_b2, ei_b, out + NODE_OUT_ELEMS);

    // node MLP chain on tensor cores (split-bf16, cp.async pipeline)
    gemm_mma2<FDIM, H1, 1, 1><<<dim3(H1 / 128, NROWS / 128), 256, GEMM_SMEM>>>(
        xhi, xlo, w1hi, w1lo,
        np_b1, bn1_g, bn1_b, bn1_rm, bn1_rv, nullptr, h1hi, h1lo);
    gemm_mma2<H1, H2, 1, 1><<<dim3(H2 / 128, NROWS / 128), 256, GEMM_SMEM>>>(
        h1hi, h1lo, w2hi, w2lo,
        np_b2, bn2_g, bn2_b, bn2_rm, bn2_rv, nullptr, h2hi, h2lo);
    gemm_mma2<H2, H3, 0, 0><<<dim3(H3 / 128, NROWS / 128), 256, GEMM_SMEM>>>(
        h2hi, h2lo, w3hi, w3lo,
        np_b3, nullptr, nullptr, nullptr, nullptr, h3, nullptr, nullptr);

    node_out_kernel<<<NODE_OUT_ELEMS / 256, 256>>>(h3, ni_w, ni_b, out);
}

// round 6
// speedup vs baseline: 3.3609x; 1.1168x over previous
#include <cuda_runtime.h>
#include <cuda_bf16.h>
#include <cstdint>

// ---------------- problem constants (fixed by setup_inputs) ----------------
#define BATCH   32
#define NNODE   512
#define NROWS   (BATCH*NNODE)      // 16384
#define FDIM    1024
#define H1      512
#define H2      256
#define H3      128
#define NC      8
#define EDGES   32768              // per batch
#define NEDGE   (BATCH*EDGES)      // 1048576
#define EH      64
#define EC      10
#define CATTR   9
#define NODE_OUT_ELEMS (NROWS*NC)  // 131072

// ---------------- scratch (device globals; no allocation allowed) ----------
__device__ __nv_bfloat16 g_xhi[NROWS * FDIM], g_xlo[NROWS * FDIM];  // split roi
__device__ __nv_bfloat16 g_h1hi[NROWS * H1],  g_h1lo[NROWS * H1];
__device__ __nv_bfloat16 g_h2hi[NROWS * H2],  g_h2lo[NROWS * H2];
__device__ float         g_h3[NROWS * H3];
__device__ __nv_bfloat16 g_w1hi[H1 * FDIM],   g_w1lo[H1 * FDIM];
__device__ __nv_bfloat16 g_w2hi[H2 * H1],     g_w2lo[H2 * H1];
__device__ __nv_bfloat16 g_w3hi[H3 * H2],     g_w3lo[H3 * H2];
__device__ __nv_bfloat16 g_ew1t[64 * 32];
__device__ __nv_bfloat16 g_ew2t[64 * 64];
__device__ __nv_bfloat16 g_ew3t[16 * 64];

// ---------------- helpers ----------------------------------------------------
__device__ __forceinline__ uint32_t smem_u32(const void* p) {
    uint32_t a;
    asm("{ .reg .u64 t; cvta.to.shared.u64 t, %1; cvt.u32.u64 %0, t; }"
        : "=r"(a) : "l"(p));
    return a;
}
__device__ __forceinline__ void ldsm4(uint32_t addr, uint32_t* r) {
    asm volatile("ldmatrix.sync.aligned.m8n8.x4.shared.b16 {%0,%1,%2,%3}, [%4];"
                 : "=r"(r[0]), "=r"(r[1]), "=r"(r[2]), "=r"(r[3]) : "r"(addr));
}
__device__ __forceinline__ void mma16816(float* c, const uint32_t* a, const uint32_t* b) {
    asm volatile(
        "mma.sync.aligned.m16n8k16.row.col.f32.bf16.bf16.f32 "
        "{%0,%1,%2,%3}, {%4,%5,%6,%7}, {%8,%9}, {%0,%1,%2,%3};"
        : "+f"(c[0]), "+f"(c[1]), "+f"(c[2]), "+f"(c[3])
        : "r"(a[0]), "r"(a[1]), "r"(a[2]), "r"(a[3]), "r"(b[0]), "r"(b[1]));
}
__device__ __forceinline__ void sts128(uint32_t addr, uint4 v) {
    asm volatile("st.shared.v4.b32 [%0], {%1,%2,%3,%4};"
                 :: "r"(addr), "r"(v.x), "r"(v.y), "r"(v.z), "r"(v.w) : "memory");
}
__device__ __forceinline__ void sts32(uint32_t addr, uint32_t v) {
    asm volatile("st.shared.b32 [%0], %1;" :: "r"(addr), "r"(v) : "memory");
}
__device__ __forceinline__ uint32_t pack_bf2(float a, float b) {
    __nv_bfloat162 h = __floats2bfloat162_rn(a, b);
    uint32_t u; memcpy(&u, &h, 4); return u;
}
__device__ __forceinline__ void cp16(uint32_t dst, const void* src) {
    asm volatile("cp.async.cg.shared.global [%0], [%1], 16;"
                 :: "r"(dst), "l"(src) : "memory");
}
__device__ __forceinline__ void cp_commit() {
    asm volatile("cp.async.commit_group;" ::: "memory");
}
#define CP_WAIT(n) asm volatile("cp.async.wait_group %0;" :: "n"(n) : "memory")

// ---------------- split-bf16 mma GEMM, cp.async 3-stage pipeline ------------
// C = relu((A@B^T + bias)[bn-fold]); A,B pre-split bf16 hi/lo.
// CTA tile 128x128, 8 warps (32x64 warp tiles), K-chunk 32, 3 stages,
// ONE barrier per chunk (issue c+2 right after the barrier, then compute c).
static constexpr int STAGE_BYTES = 32768;   // Ahi|Alo|Bhi|Blo x 8KB
static constexpr int GEMM_SMEM = 3 * STAGE_BYTES;

template<int K, int N, int EPI, int OSPLIT>
__global__ __launch_bounds__(256)
void gemm_mma2(const __nv_bfloat16* __restrict__ Ahi, const __nv_bfloat16* __restrict__ Alo,
               const __nv_bfloat16* __restrict__ Bhi, const __nv_bfloat16* __restrict__ Blo,
               const float* __restrict__ bias,
               const float* __restrict__ bng, const float* __restrict__ bnb,
               const float* __restrict__ bnrm, const float* __restrict__ bnrv,
               float* __restrict__ Cf,
               __nv_bfloat16* __restrict__ Chi, __nv_bfloat16* __restrict__ Clo)
{
    extern __shared__ char sm_raw[];
    const uint32_t sb = smem_u32(sm_raw);
    const int tid = threadIdx.x;
    const int lane = tid & 31, w = tid >> 5;
    const int bn = blockIdx.x, bm = blockIdx.y;
    const int wr = (w & 3) * 32;
    const int wc = (w >> 2) * 64;

    // ---- per-thread async-copy slots: 8 x 16B per stage ----
    const __nv_bfloat16* srcs[8];
    uint32_t dsts[8];
    #pragma unroll
    for (int i = 0; i < 8; i++) {
        int idx = i * 256 + tid;          // 0..2047
        int slab = idx >> 9;              // 0:Ahi 1:Alo 2:Bhi 3:Blo
        int within = idx & 511;
        int r = within >> 2, c = within & 3;
        const __nv_bfloat16* base = (slab == 0) ? Ahi : (slab == 1) ? Alo
                                   : (slab == 2) ? Bhi : Blo;
        int row0 = (slab < 2) ? bm * 128 : bn * 128;
        srcs[i] = base + (size_t)(row0 + r) * K + c * 8;
        dsts[i] = slab * 8192 + r * 64 + ((c ^ ((r >> 1) & 3)) << 4);
    }
    auto ISSUE = [&](int ck) {
        const uint32_t st = sb + (ck % 3) * STAGE_BYTES;
        #pragma unroll
        for (int i = 0; i < 8; i++)
            cp16(st + dsts[i], srcs[i] + ck * 32);
    };

    float acc[2][8][4];
    #pragma unroll
    for (int a = 0; a < 2; a++)
        #pragma unroll
        for (int b = 0; b < 8; b++)
            #pragma unroll
            for (int c = 0; c < 4; c++) acc[a][b][c] = 0.f;

    const int m = lane >> 3, rr = lane & 7;

    auto COMPUTE = [&](int stage) {
        const uint32_t aB = sb + stage * STAGE_BYTES;
        const uint32_t bB = aB + 16384;
        #pragma unroll
        for (int ks = 0; ks < 2; ks++) {
            const int ckb = ks * 2;
            uint32_t ah[2][4], al[2][4], bh[4][4], bl[4][4];
            #pragma unroll
            for (int t2 = 0; t2 < 2; t2++) {
                const int r_l = wr + t2 * 16 + ((m & 1) << 3) + rr;
                const int c_l = ckb + (m >> 1);
                const uint32_t off = r_l * 64 + ((c_l ^ ((r_l >> 1) & 3)) << 4);
                ldsm4(aB + off, ah[t2]);
                ldsm4(aB + 8192 + off, al[t2]);
            }
            #pragma unroll
            for (int p = 0; p < 4; p++) {
                const int n_l = wc + p * 16 + ((m >> 1) << 3) + rr;
                const int c_l = ckb + (m & 1);
                const uint32_t off = n_l * 64 + ((c_l ^ ((n_l >> 1) & 3)) << 4);
                ldsm4(bB + off, bh[p]);
                ldsm4(bB + 8192 + off, bl[p]);
            }
            #pragma unroll
            for (int t2 = 0; t2 < 2; t2++)
                #pragma unroll
                for (int nt = 0; nt < 8; nt++) {
                    const uint32_t* Bh = &bh[nt >> 1][(nt & 1) * 2];
                    const uint32_t* Bl = &bl[nt >> 1][(nt & 1) * 2];
                    mma16816(acc[t2][nt], ah[t2], Bh);
                    mma16816(acc[t2][nt], al[t2], Bh);
                    mma16816(acc[t2][nt], ah[t2], Bl);
                }
        }
    };

    constexpr int NCH = K / 32;
    ISSUE(0); cp_commit();
    ISSUE(1); cp_commit();
    for (int c = 0; c < NCH; c++) {
        CP_WAIT(1);
        __syncthreads();          // orders prior-chunk reads vs. the new writes
        if (c + 2 < NCH) ISSUE(c + 2);
        cp_commit();
        COMPUTE(c % 3);
    }

    // ---------------- epilogue ----------------
    #pragma unroll
    for (int t2 = 0; t2 < 2; t2++) {
        const int row0 = bm * 128 + wr + t2 * 16 + (lane >> 2);
        #pragma unroll
        for (int nt = 0; nt < 8; nt++) {
            const int col = bn * 128 + wc + nt * 8 + 2 * (lane & 3);
            float b0 = __ldg(&bias[col]), b1 = __ldg(&bias[col + 1]);
            float s0 = 1.f, s1 = 1.f, f0 = 0.f, f1 = 0.f;
            if (EPI) {
                s0 = __ldg(&bng[col]) * rsqrtf(__ldg(&bnrv[col]) + 1e-5f);
                f0 = __ldg(&bnb[col]) - __ldg(&bnrm[col]) * s0;
                s1 = __ldg(&bng[col + 1]) * rsqrtf(__ldg(&bnrv[col + 1]) + 1e-5f);
                f1 = __ldg(&bnb[col + 1]) - __ldg(&bnrm[col + 1]) * s1;
            }
            float v00 = acc[t2][nt][0] + b0, v01 = acc[t2][nt][1] + b1;
            float v10 = acc[t2][nt][2] + b0, v11 = acc[t2][nt][3] + b1;
            if (EPI) {
                v00 = v00 * s0 + f0; v01 = v01 * s1 + f1;
                v10 = v10 * s0 + f0; v11 = v11 * s1 + f1;
            }
            v00 = fmaxf(v00, 0.f); v01 = fmaxf(v01, 0.f);
            v10 = fmaxf(v10, 0.f); v11 = fmaxf(v11, 0.f);
            if (OSPLIT) {
                __nv_bfloat162 h0 = __floats2bfloat162_rn(v00, v01);
                __nv_bfloat162 l0 = __floats2bfloat162_rn(v00 - __bfloat162float(h0.x),
                                                          v01 - __bfloat162float(h0.y));
                __nv_bfloat162 h1 = __floats2bfloat162_rn(v10, v11);
                __nv_bfloat162 l1 = __floats2bfloat162_rn(v10 - __bfloat162float(h1.x),
                                                          v11 - __bfloat162float(h1.y));
                *(__nv_bfloat162*)(Chi + (size_t)row0 * N + col) = h0;
                *(__nv_bfloat162*)(Clo + (size_t)row0 * N + col) = l0;
                *(__nv_bfloat162*)(Chi + (size_t)(row0 + 8) * N + col) = h1;
                *(__nv_bfloat162*)(Clo + (size_t)(row0 + 8) * N + col) = l1;
            } else {
                *(float2*)(Cf + (size_t)row0 * N + col) = make_float2(v00, v01);
                *(float2*)(Cf + (size_t)(row0 + 8) * N + col) = make_float2(v10, v11);
            }
        }
    }
}

// ---------------- fp32 -> bf16 hi/lo split (for roi) ------------------------
__global__ __launch_bounds__(256)
void split_f32(const float4* __restrict__ in,
               uint2* __restrict__ hi, uint2* __restrict__ lo)
{
    int i = blockIdx.x * 256 + threadIdx.x;
    float4 v = in[i];
    __nv_bfloat162 h0 = __floats2bfloat162_rn(v.x, v.y);
    __nv_bfloat162 h1 = __floats2bfloat162_rn(v.z, v.w);
    __nv_bfloat162 l0 = __floats2bfloat162_rn(v.x - __bfloat162float(h0.x),
                                              v.y - __bfloat162float(h0.y));
    __nv_bfloat162 l1 = __floats2bfloat162_rn(v.z - __bfloat162float(h1.x),
                                              v.w - __bfloat162float(h1.y));
    uint2 uh, ul;
    memcpy(&uh.x, &h0, 4); memcpy(&uh.y, &h1, 4);
    memcpy(&ul.x, &l0, 4); memcpy(&ul.y, &l1, 4);
    hi[i] = uh; lo[i] = ul;
}

// ------- weight transpose + bf16 hi/lo split: in (R x C) -> out (C x R) -----
__global__ void transpose_split(const float* __restrict__ in,
                                __nv_bfloat16* __restrict__ ohi,
                                __nv_bfloat16* __restrict__ olo,
                                int R, int C)
{
    __shared__ float t[32][33];
    int x = blockIdx.x * 32 + threadIdx.x;
    int y = blockIdx.y * 32 + threadIdx.y;
    #pragma unroll
    for (int i = 0; i < 32; i += 8)
        t[threadIdx.y + i][threadIdx.x] = in[(size_t)(y + i) * C + x];
    __syncthreads();
    x = blockIdx.y * 32 + threadIdx.x;
    y = blockIdx.x * 32 + threadIdx.y;
    #pragma unroll
    for (int i = 0; i < 32; i += 8) {
        float v = t[threadIdx.x][threadIdx.y + i];
        __nv_bfloat16 h = __float2bfloat16(v);
        ohi[(size_t)(y + i) * R + x] = h;
        olo[(size_t)(y + i) * R + x] = __float2bfloat16(v - __bfloat162float(h));
    }
}

// ---------------- node head: h3(16384x128) @ ni_w(128x8) -> sigmoid ---------
__global__ __launch_bounds__(256)
void node_out_kernel(const float* __restrict__ h3,
                     const float* __restrict__ w,
                     const float* __restrict__ b,
                     float* __restrict__ out)
{
    int t = blockIdx.x * 256 + threadIdx.x;
    int row = t >> 3;
    int j = t & 7;
    const float* x = h3 + (size_t)row * H3;
    float acc = b[j];
    #pragma unroll 8
    for (int k = 0; k < H3; k++)
        acc += x[k] * __ldg(&w[k * NC + j]);
    out[t] = 1.f / (1.f + __expf(-acc));
}

// ---------------- edge weight prep: transpose+pad to bf16 -------------------
__global__ void prep_edge_weights(const float* __restrict__ w1,
                                  const float* __restrict__ w2,
                                  const float* __restrict__ wi,
                                  __nv_bfloat16* __restrict__ o1,
                                  __nv_bfloat16* __restrict__ o2,
                                  __nv_bfloat16* __restrict__ o3)
{
    int t = blockIdx.x * 256 + threadIdx.x;
    int stride = gridDim.x * 256;
    for (int i = t; i < 64 * 32; i += stride) {
        int n = i >> 5, k = i & 31;
        o1[i] = (k < 18) ? __float2bfloat16(w1[k * 64 + n]) : __nv_bfloat16(0.f);
    }
    for (int i = t; i < 64 * 64; i += stride) {
        int n = i >> 6, k = i & 63;
        o2[i] = __float2bfloat16(w2[k * 64 + n]);
    }
    for (int i = t; i < 16 * 64; i += stride) {
        int n = i >> 6, k = i & 63;
        o3[i] = (n < EC) ? __float2bfloat16(wi[k * EC + n]) : __nv_bfloat16(0.f);
    }
}

// ---------------- edge MLP on tensor cores (verified R4) --------------------
static constexpr int ESA_ATTR = 0;
static constexpr int ESA_W1   = 10240;
static constexpr int ESA_W2   = 14336;
static constexpr int ESA_W3   = 22528;
static constexpr int ESA_A1   = 24576;
static constexpr int ESA_H    = 32768;
static constexpr int ESA_G    = 49152;
static constexpr int EDGE_SMEM = 65536;

__global__ __launch_bounds__(128)
void edge_mma_kernel(const float* __restrict__ bboxes,
                     const float* __restrict__ dirs,
                     const float* __restrict__ prio,
                     const int*   __restrict__ eidx,
                     const __nv_bfloat16* __restrict__ w1t,
                     const __nv_bfloat16* __restrict__ w2t,
                     const __nv_bfloat16* __restrict__ w3t,
                     const float* __restrict__ b1,
                     const float* __restrict__ b2,
                     const float* __restrict__ bi,
                     float* __restrict__ out)
{
    extern __shared__ char sm[];
    const uint32_t sb = smem_u32(sm);
    const int tid = threadIdx.x;
    const int lane = tid & 31, w = tid >> 5;
    const int bt = blockIdx.x >> 8;
    const int e0 = (blockIdx.x & 255) * 128;

    __nv_bfloat16* sAttr = (__nv_bfloat16*)(sm + ESA_ATTR);
    const float inv = 1.f / 1024.f;
    for (int n = tid; n < NNODE; n += 128) {
        int gn = bt * NNODE + n;
        float4 bb = *(const float4*)&bboxes[(size_t)gn * 4];
        float4 dd = *(const float4*)&dirs[(size_t)gn * 4];
        float pr = prio[gn];
        __nv_bfloat16* a = sAttr + n * 10;
        a[0] = __float2bfloat16(bb.x * inv);
        a[1] = __float2bfloat16(bb.y * inv);
        a[2] = __float2bfloat16(bb.z * inv);
        a[3] = __float2bfloat16(bb.w * inv);
        a[4] = __float2bfloat16(dd.x);
        a[5] = __float2bfloat16(dd.y);
        a[6] = __float2bfloat16(dd.z);
        a[7] = __float2bfloat16(dd.w);
        a[8] = __float2bfloat16(pr);
    }
    for (int i = tid; i < 64 * 4; i += 128) {
        int r = i >> 2, c = i & 3;
        uint4 v = ((const uint4*)w1t)[r * 4 + c];
        sts128(sb + ESA_W1 + r * 64 + ((c ^ ((r >> 1) & 3)) << 4), v);
    }
    for (int i = tid; i < 64 * 8; i += 128) {
        int r = i >> 3, c = i & 7;
        uint4 v = ((const uint4*)w2t)[r * 8 + c];
        sts128(sb + ESA_W2 + r * 128 + ((c ^ (r & 7)) << 4), v);
    }
    for (int i = tid; i < 16 * 8; i += 128) {
        int r = i >> 3, c = i & 7;
        uint4 v = ((const uint4*)w3t)[r * 8 + c];
        sts128(sb + ESA_W3 + r * 128 + ((c ^ (r & 7)) << 4), v);
    }
    __syncthreads();

    {
        const int ebase = bt * 2 * EDGES + e0 + tid;
        const int src = eidx[ebase];
        const int dst = eidx[ebase + EDGES];
        const __nv_bfloat16* as = sAttr + src * 10;
        const __nv_bfloat16* ad = sAttr + dst * 10;
        uint16_t v[32];
        #pragma unroll
        for (int c = 0; c < 9; c++) { memcpy(&v[c], &as[c], 2); memcpy(&v[9 + c], &ad[c], 2); }
        #pragma unroll
        for (int c = 18; c < 32; c++) v[c] = 0;
        const int swz = (tid >> 1) & 3;
        #pragma unroll
        for (int ch = 0; ch < 4; ch++) {
            uint4 p;
            p.x = (uint32_t)v[ch*8+0] | ((uint32_t)v[ch*8+1] << 16);
            p.y = (uint32_t)v[ch*8+2] | ((uint32_t)v[ch*8+3] << 16);
            p.z = (uint32_t)v[ch*8+4] | ((uint32_t)v[ch*8+5] << 16);
            p.w = (uint32_t)v[ch*8+6] | ((uint32_t)v[ch*8+7] << 16);
            sts128(sb + ESA_A1 + tid * 64 + ((ch ^ swz) << 4), p);
        }
    }
    __syncthreads();

    const int m = lane >> 3, rr = lane & 7;
    const int wr = w * 32;

    {
        float acc[2][8][4];
        #pragma unroll
        for (int a = 0; a < 2; a++)
            #pragma unroll
            for (int b = 0; b < 8; b++)
                #pragma unroll
                for (int c = 0; c < 4; c++) acc[a][b][c] = 0.f;

        #pragma unroll
        for (int k16 = 0; k16 < 2; k16++) {
            uint32_t a[2][4], b[4][4];
            #pragma unroll
            for (int t2 = 0; t2 < 2; t2++) {
                int r = wr + t2 * 16 + ((m & 1) << 3) + rr;
                int c = k16 * 2 + (m >> 1);
                ldsm4(sb + ESA_A1 + r * 64 + ((c ^ ((r >> 1) & 3)) << 4), a[t2]);
            }
            #pragma unroll
            for (int p = 0; p < 4; p++) {
                int n = p * 16 + ((m >> 1) << 3) + rr;
                int c = k16 * 2 + (m & 1);
                ldsm4(sb + ESA_W1 + n * 64 + ((c ^ ((n >> 1) & 3)) << 4), b[p]);
            }
            #pragma unroll
            for (int t2 = 0; t2 < 2; t2++)
                #pragma unroll
                for (int nt = 0; nt < 8; nt++)
                    mma16816(acc[t2][nt], a[t2], &b[nt >> 1][(nt & 1) * 2]);
        }
        #pragma unroll
        for (int t2 = 0; t2 < 2; t2++) {
            int r0 = wr + t2 * 16 + (lane >> 2);
            #pragma unroll
            for (int nt = 0; nt < 8; nt++) {
                int col = nt * 8 + 2 * (lane & 3);
                float bb0 = __ldg(&b1[col]), bb1 = __ldg(&b1[col + 1]);
                float v00 = fmaxf(acc[t2][nt][0] + bb0, 0.f);
                float v01 = fmaxf(acc[t2][nt][1] + bb1, 0.f);
                float v10 = fmaxf(acc[t2][nt][2] + bb0, 0.f);
                float v11 = fmaxf(acc[t2][nt][3] + bb1, 0.f);
                uint32_t inb = (col & 7) * 2;
                sts32(sb + ESA_H + r0 * 128 + (((nt) ^ (r0 & 7)) << 4) + inb,
                      pack_bf2(v00, v01));
                int r1 = r0 + 8;
                sts32(sb + ESA_H + r1 * 128 + (((nt) ^ (r1 & 7)) << 4) + inb,
                      pack_bf2(v10, v11));
            }
        }
    }
    __syncwarp();

    {
        float acc[2][8][4];
        #pragma unroll
        for (int a = 0; a < 2; a++)
            #pragma unroll
            for (int b = 0; b < 8; b++)
                #pragma unroll
                for (int c = 0; c < 4; c++) acc[a][b][c] = 0.f;

        #pragma unroll
        for (int k16 = 0; k16 < 4; k16++) {
            uint32_t a[2][4], b[4][4];
            #pragma unroll
            for (int t2 = 0; t2 < 2; t2++) {
                int r = wr + t2 * 16 + ((m & 1) << 3) + rr;
                int c = k16 * 2 + (m >> 1);
                ldsm4(sb + ESA_H + r * 128 + ((c ^ (r & 7)) << 4), a[t2]);
            }
            #pragma unroll
            for (int p = 0; p < 4; p++) {
                int n = p * 16 + ((m >> 1) << 3) + rr;
                int c = k16 * 2 + (m & 1);
                ldsm4(sb + ESA_W2 + n * 128 + ((c ^ (n & 7)) << 4), b[p]);
            }
            #pragma unroll
            for (int t2 = 0; t2 < 2; t2++)
                #pragma unroll
                for (int nt = 0; nt < 8; nt++)
                    mma16816(acc[t2][nt], a[t2], &b[nt >> 1][(nt & 1) * 2]);
        }
        #pragma unroll
        for (int t2 = 0; t2 < 2; t2++) {
            int r0 = wr + t2 * 16 + (lane >> 2);
            #pragma unroll
            for (int nt = 0; nt < 8; nt++) {
                int col = nt * 8 + 2 * (lane & 3);
                float bb0 = __ldg(&b2[col]), bb1 = __ldg(&b2[col + 1]);
                float v00 = fmaxf(acc[t2][nt][0] + bb0, 0.f);
                float v01 = fmaxf(acc[t2][nt][1] + bb1, 0.f);
                float v10 = fmaxf(acc[t2][nt][2] + bb0, 0.f);
                float v11 = fmaxf(acc[t2][nt][3] + bb1, 0.f);
                uint32_t inb = (col & 7) * 2;
                sts32(sb + ESA_G + r0 * 128 + (((nt) ^ (r0 & 7)) << 4) + inb,
                      pack_bf2(v00, v01));
                int r1 = r0 + 8;
                sts32(sb + ESA_G + r1 * 128 + (((nt) ^ (r1 & 7)) << 4) + inb,
                      pack_bf2(v10, v11));
            }
        }
    }
    __syncwarp();

    {
        float acc[2][2][4];
        #pragma unroll
        for (int a = 0; a < 2; a++)
            #pragma unroll
            for (int b = 0; b < 2; b++)
                #pragma unroll
                for (int c = 0; c < 4; c++) acc[a][b][c] = 0.f;

        #pragma unroll
        for (int k16 = 0; k16 < 4; k16++) {
            uint32_t a[2][4], b[4];
            #pragma unroll
            for (int t2 = 0; t2 < 2; t2++) {
                int r = wr + t2 * 16 + ((m & 1) << 3) + rr;
                int c = k16 * 2 + (m >> 1);
                ldsm4(sb + ESA_G + r * 128 + ((c ^ (r & 7)) << 4), a[t2]);
            }
            {
                int n = ((m >> 1) << 3) + rr;
                int c = k16 * 2 + (m & 1);
                ldsm4(sb + ESA_W3 + n * 128 + ((c ^ (n & 7)) << 4), b);
            }
            #pragma unroll
            for (int t2 = 0; t2 < 2; t2++) {
                mma16816(acc[t2][0], a[t2], &b[0]);
                mma16816(acc[t2][1], a[t2], &b[2]);
            }
        }
        #pragma unroll
        for (int t2 = 0; t2 < 2; t2++) {
            int r0 = wr + t2 * 16 + (lane >> 2);
            long eg = (long)bt * EDGES + e0 + r0;
            #pragma unroll
            for (int nt = 0; nt < 2; nt++) {
                int col = nt * 8 + 2 * (lane & 3);
                if (col < EC) {
                    float bb0 = __ldg(&bi[col]), bb1 = __ldg(&bi[col + 1]);
                    float s00 = 1.f / (1.f + __expf(-(acc[t2][nt][0] + bb0)));
                    float s01 = 1.f / (1.f + __expf(-(acc[t2][nt][1] + bb1)));
                    float s10 = 1.f / (1.f + __expf(-(acc[t2][nt][2] + bb0)));
                    float s11 = 1.f / (1.f + __expf(-(acc[t2][nt][3] + bb1)));
                    *(float2*)(out + eg * EC + col) = make_float2(s00, s01);
                    *(float2*)(out + (eg + 8) * EC + col) = make_float2(s10, s11);
                }
            }
        }
    }
}

// ---------------- launch ----------------------------------------------------
extern "C" void kernel_launch(void* const* d_in, const int* in_sizes, int n_in,
                              void* d_out, int out_size)
{
    const float* roi    = (const float*)d_in[0];
    const float* bboxes = (const float*)d_in[1];
    const float* dirs   = (const float*)d_in[2];
    const float* prio   = (const float*)d_in[3];
    const int*   eidx   = (const int*)  d_in[4];
    const float* np_w1  = (const float*)d_in[5];
    const float* np_b1  = (const float*)d_in[6];
    const float* bn1_g  = (const float*)d_in[7];
    const float* bn1_b  = (const float*)d_in[8];
    const float* bn1_rm = (const float*)d_in[9];
    const float* bn1_rv = (const float*)d_in[10];
    const float* np_w2  = (const float*)d_in[11];
    const float* np_b2  = (const float*)d_in[12];
    const float* bn2_g  = (const float*)d_in[13];
    const float* bn2_b  = (const float*)d_in[14];
    const float* bn2_rm = (const float*)d_in[15];
    const float* bn2_rv = (const float*)d_in[16];
    const float* np_w3  = (const float*)d_in[17];
    const float* np_b3  = (const float*)d_in[18];
    const float* ni_w   = (const float*)d_in[19];
    const float* ni_b   = (const float*)d_in[20];
    const float* ep_w1  = (const float*)d_in[21];
    const float* ep_b1  = (const float*)d_in[22];
    const float* ep_w2  = (const float*)d_in[23];
    const float* ep_b2  = (const float*)d_in[24];
    const float* ei_w   = (const float*)d_in[25];
    const float* ei_b   = (const float*)d_in[26];

    float* out = (float*)d_out;

    __nv_bfloat16 *xhi, *xlo, *h1hi, *h1lo, *h2hi, *h2lo;
    __nv_bfloat16 *w1hi, *w1lo, *w2hi, *w2lo, *w3hi, *w3lo;
    __nv_bfloat16 *ew1t, *ew2t, *ew3t;
    float* h3;
    cudaGetSymbolAddress((void**)&xhi, g_xhi);
    cudaGetSymbolAddress((void**)&xlo, g_xlo);
    cudaGetSymbolAddress((void**)&h1hi, g_h1hi);
    cudaGetSymbolAddress((void**)&h1lo, g_h1lo);
    cudaGetSymbolAddress((void**)&h2hi, g_h2hi);
    cudaGetSymbolAddress((void**)&h2lo, g_h2lo);
    cudaGetSymbolAddress((void**)&h3, g_h3);
    cudaGetSymbolAddress((void**)&w1hi, g_w1hi);
    cudaGetSymbolAddress((void**)&w1lo, g_w1lo);
    cudaGetSymbolAddress((void**)&w2hi, g_w2hi);
    cudaGetSymbolAddress((void**)&w2lo, g_w2lo);
    cudaGetSymbolAddress((void**)&w3hi, g_w3hi);
    cudaGetSymbolAddress((void**)&w3lo, g_w3lo);
    cudaGetSymbolAddress((void**)&ew1t, g_ew1t);
    cudaGetSymbolAddress((void**)&ew2t, g_ew2t);
    cudaGetSymbolAddress((void**)&ew3t, g_ew3t);

    cudaFuncSetAttribute(edge_mma_kernel,
                         cudaFuncAttributeMaxDynamicSharedMemorySize, EDGE_SMEM);
    cudaFuncSetAttribute(gemm_mma2<FDIM, H1, 1, 1>,
                         cudaFuncAttributeMaxDynamicSharedMemorySize, GEMM_SMEM);
    cudaFuncSetAttribute(gemm_mma2<H1, H2, 1, 1>,
                         cudaFuncAttributeMaxDynamicSharedMemorySize, GEMM_SMEM);
    cudaFuncSetAttribute(gemm_mma2<H2, H3, 0, 0>,
                         cudaFuncAttributeMaxDynamicSharedMemorySize, GEMM_SMEM);

    // one-time stream/event setup (host-side resources; no device memory)
    static cudaStream_t s_edge = nullptr;
    static cudaEvent_t  ev_fork = nullptr, ev_join = nullptr;
    if (s_edge == nullptr) {
        cudaStreamCreateWithFlags(&s_edge, cudaStreamNonBlocking);
        cudaEventCreateWithFlags(&ev_fork, cudaEventDisableTiming);
        cudaEventCreateWithFlags(&ev_join, cudaEventDisableTiming);
    }

    // ---- fork: edge branch runs concurrently on s_edge ----
    cudaEventRecord(ev_fork, 0);
    cudaStreamWaitEvent(s_edge, ev_fork, 0);

    prep_edge_weights<<<8, 256, 0, s_edge>>>(ep_w1, ep_w2, ei_w, ew1t, ew2t, ew3t);
    edge_mma_kernel<<<NEDGE / 128, 128, EDGE_SMEM, s_edge>>>(
        bboxes, dirs, prio, eidx, ew1t, ew2t, ew3t,
        ep_b1, ep_b2, ei_b, out + NODE_OUT_ELEMS);
    cudaEventRecord(ev_join, s_edge);

    // ---- node branch on the capture stream ----
    split_f32<<<NROWS * FDIM / 4 / 256, 256>>>((const float4*)roi,
                                               (uint2*)xhi, (uint2*)xlo);
    {
        dim3 b(32, 8);
        transpose_split<<<dim3(H1 / 32, FDIM / 32), b>>>(np_w1, w1hi, w1lo, FDIM, H1);
        transpose_split<<<dim3(H2 / 32, H1 / 32), b>>>(np_w2, w2hi, w2lo, H1, H2);
        transpose_split<<<dim3(H3 / 32, H2 / 32), b>>>(np_w3, w3hi, w3lo, H2, H3);
    }

    gemm_mma2<FDIM, H1, 1, 1><<<dim3(H1 / 128, NROWS / 128), 256, GEMM_SMEM>>>(
        xhi, xlo, w1hi, w1lo,
        np_b1, bn1_g, bn1_b, bn1_rm, bn1_rv, nullptr, h1hi, h1lo);
    gemm_mma2<H1, H2, 1, 1><<<dim3(H2 / 128, NROWS / 128), 256, GEMM_SMEM>>>(
        h1hi, h1lo, w2hi, w2lo,
        np_b2, bn2_g, bn2_b, bn2_rm, bn2_rv, nullptr, h2hi, h2lo);
    gemm_mma2<H2, H3, 0, 0><<<dim3(H3 / 128, NROWS / 128), 256, GEMM_SMEM>>>(
        h2hi, h2lo, w3hi, w3lo,
        np_b3, nullptr, nullptr, nullptr, nullptr, h3, nullptr, nullptr);

    node_out_kernel<<<NODE_OUT_ELEMS / 256, 256>>>(h3, ni_w, ni_b, out);

    // ---- join: capture stream waits for the edge branch ----
    cudaStreamWaitEvent(0, ev_join, 0);
}

// round 7
// speedup vs baseline: 3.4099x; 1.0146x over previous
#include <cuda_runtime.h>
#include <cuda_bf16.h>
#include <cstdint>

// ---------------- problem constants (fixed by setup_inputs) ----------------
#define BATCH   32
#define NNODE   512
#define NROWS   (BATCH*NNODE)      // 16384
#define FDIM    1024
#define H1      512
#define H2      256
#define H3      128
#define NC      8
#define EDGES   32768              // per batch
#define NEDGE   (BATCH*EDGES)      // 1048576
#define EH      64
#define EC      10
#define CATTR   9
#define NODE_OUT_ELEMS (NROWS*NC)  // 131072

// ---------------- scratch (device globals; no allocation allowed) ----------
__device__ __nv_bfloat16 g_xhi[NROWS * FDIM], g_xlo[NROWS * FDIM];  // split roi
__device__ __nv_bfloat16 g_h1hi[NROWS * H1],  g_h1lo[NROWS * H1];
__device__ __nv_bfloat16 g_h2hi[NROWS * H2],  g_h2lo[NROWS * H2];
__device__ __nv_bfloat16 g_w1hi[H1 * FDIM],   g_w1lo[H1 * FDIM];
__device__ __nv_bfloat16 g_w2hi[H2 * H1],     g_w2lo[H2 * H1];
__device__ __nv_bfloat16 g_w3hi[H3 * H2],     g_w3lo[H3 * H2];
__device__ __nv_bfloat16 g_ew1t[64 * 32];
__device__ __nv_bfloat16 g_ew2t[64 * 64];
__device__ __nv_bfloat16 g_ew3t[16 * 64];

// ---------------- helpers ----------------------------------------------------
__device__ __forceinline__ uint32_t smem_u32(const void* p) {
    uint32_t a;
    asm("{ .reg .u64 t; cvta.to.shared.u64 t, %1; cvt.u32.u64 %0, t; }"
        : "=r"(a) : "l"(p));
    return a;
}
__device__ __forceinline__ void ldsm4(uint32_t addr, uint32_t* r) {
    asm volatile("ldmatrix.sync.aligned.m8n8.x4.shared.b16 {%0,%1,%2,%3}, [%4];"
                 : "=r"(r[0]), "=r"(r[1]), "=r"(r[2]), "=r"(r[3]) : "r"(addr));
}
__device__ __forceinline__ void mma16816(float* c, const uint32_t* a, const uint32_t* b) {
    asm volatile(
        "mma.sync.aligned.m16n8k16.row.col.f32.bf16.bf16.f32 "
        "{%0,%1,%2,%3}, {%4,%5,%6,%7}, {%8,%9}, {%0,%1,%2,%3};"
        : "+f"(c[0]), "+f"(c[1]), "+f"(c[2]), "+f"(c[3])
        : "r"(a[0]), "r"(a[1]), "r"(a[2]), "r"(a[3]), "r"(b[0]), "r"(b[1]));
}
__device__ __forceinline__ void sts128(uint32_t addr, uint4 v) {
    asm volatile("st.shared.v4.b32 [%0], {%1,%2,%3,%4};"
                 :: "r"(addr), "r"(v.x), "r"(v.y), "r"(v.z), "r"(v.w) : "memory");
}
__device__ __forceinline__ void sts32(uint32_t addr, uint32_t v) {
    asm volatile("st.shared.b32 [%0], %1;" :: "r"(addr), "r"(v) : "memory");
}
__device__ __forceinline__ uint32_t pack_bf2(float a, float b) {
    __nv_bfloat162 h = __floats2bfloat162_rn(a, b);
    uint32_t u; memcpy(&u, &h, 4); return u;
}
__device__ __forceinline__ void cp16(uint32_t dst, const void* src) {
    asm volatile("cp.async.cg.shared.global [%0], [%1], 16;"
                 :: "r"(dst), "l"(src) : "memory");
}
__device__ __forceinline__ void cp_commit() {
    asm volatile("cp.async.commit_group;" ::: "memory");
}
#define CP_WAIT(n) asm volatile("cp.async.wait_group %0;" :: "n"(n) : "memory")

// ---------------- split-bf16 mma GEMM, cp.async 3-stage pipeline ------------
// C = relu((A@B^T + bias)[bn-fold]); A,B pre-split bf16 hi/lo.
// CTA tile 128x128, 8 warps (32x64 warp tiles), K-chunk 32, 3 stages.
// OSPLIT: 0 = fp32 out, 1 = bf16 hi/lo pair out,
//         2 = fused node head: relu tile -> SMEM -> sigmoid(h3@ni_w+ni_b)
//             (requires N==128, gridDim.x==1; Cf = final out base).
static constexpr int STAGE_BYTES = 32768;   // Ahi|Alo|Bhi|Blo x 8KB
static constexpr int GEMM_SMEM = 3 * STAGE_BYTES;

template<int K, int N, int EPI, int OSPLIT>
__global__ __launch_bounds__(256)
void gemm_mma2(const __nv_bfloat16* __restrict__ Ahi, const __nv_bfloat16* __restrict__ Alo,
               const __nv_bfloat16* __restrict__ Bhi, const __nv_bfloat16* __restrict__ Blo,
               const float* __restrict__ bias,
               const float* __restrict__ bng, const float* __restrict__ bnb,
               const float* __restrict__ bnrm, const float* __restrict__ bnrv,
               const float* __restrict__ hw,  const float* __restrict__ hb,
               float* __restrict__ Cf,
               __nv_bfloat16* __restrict__ Chi, __nv_bfloat16* __restrict__ Clo)
{
    extern __shared__ char sm_raw[];
    const uint32_t sb = smem_u32(sm_raw);
    const int tid = threadIdx.x;
    const int lane = tid & 31, w = tid >> 5;
    const int bn = blockIdx.x, bm = blockIdx.y;
    const int wr = (w & 3) * 32;
    const int wc = (w >> 2) * 64;

    // ---- per-thread async-copy slots: 8 x 16B per stage ----
    const __nv_bfloat16* srcs[8];
    uint32_t dsts[8];
    #pragma unroll
    for (int i = 0; i < 8; i++) {
        int idx = i * 256 + tid;          // 0..2047
        int slab = idx >> 9;              // 0:Ahi 1:Alo 2:Bhi 3:Blo
        int within = idx & 511;
        int r = within >> 2, c = within & 3;
        const __nv_bfloat16* base = (slab == 0) ? Ahi : (slab == 1) ? Alo
                                   : (slab == 2) ? Bhi : Blo;
        int row0 = (slab < 2) ? bm * 128 : bn * 128;
        srcs[i] = base + (size_t)(row0 + r) * K + c * 8;
        dsts[i] = slab * 8192 + r * 64 + ((c ^ ((r >> 1) & 3)) << 4);
    }
    auto ISSUE = [&](int ck) {
        const uint32_t st = sb + (ck % 3) * STAGE_BYTES;
        #pragma unroll
        for (int i = 0; i < 8; i++)
            cp16(st + dsts[i], srcs[i] + ck * 32);
    };

    float acc[2][8][4];
    #pragma unroll
    for (int a = 0; a < 2; a++)
        #pragma unroll
        for (int b = 0; b < 8; b++)
            #pragma unroll
            for (int c = 0; c < 4; c++) acc[a][b][c] = 0.f;

    const int m = lane >> 3, rr = lane & 7;

    auto COMPUTE = [&](int stage) {
        const uint32_t aB = sb + stage * STAGE_BYTES;
        const uint32_t bB = aB + 16384;
        #pragma unroll
        for (int ks = 0; ks < 2; ks++) {
            const int ckb = ks * 2;
            uint32_t ah[2][4], al[2][4], bh[4][4], bl[4][4];
            #pragma unroll
            for (int t2 = 0; t2 < 2; t2++) {
                const int r_l = wr + t2 * 16 + ((m & 1) << 3) + rr;
                const int c_l = ckb + (m >> 1);
                const uint32_t off = r_l * 64 + ((c_l ^ ((r_l >> 1) & 3)) << 4);
                ldsm4(aB + off, ah[t2]);
                ldsm4(aB + 8192 + off, al[t2]);
            }
            #pragma unroll
            for (int p = 0; p < 4; p++) {
                const int n_l = wc + p * 16 + ((m >> 1) << 3) + rr;
                const int c_l = ckb + (m & 1);
                const uint32_t off = n_l * 64 + ((c_l ^ ((n_l >> 1) & 3)) << 4);
                ldsm4(bB + off, bh[p]);
                ldsm4(bB + 8192 + off, bl[p]);
            }
            #pragma unroll
            for (int t2 = 0; t2 < 2; t2++)
                #pragma unroll
                for (int nt = 0; nt < 8; nt++) {
                    const uint32_t* Bh = &bh[nt >> 1][(nt & 1) * 2];
                    const uint32_t* Bl = &bl[nt >> 1][(nt & 1) * 2];
                    mma16816(acc[t2][nt], ah[t2], Bh);
                    mma16816(acc[t2][nt], al[t2], Bh);
                    mma16816(acc[t2][nt], ah[t2], Bl);
                }
        }
    };

    constexpr int NCH = K / 32;
    ISSUE(0); cp_commit();
    ISSUE(1); cp_commit();
    for (int c = 0; c < NCH; c++) {
        CP_WAIT(1);
        __syncthreads();          // orders prior-chunk reads vs. the new writes
        if (c + 2 < NCH) ISSUE(c + 2);
        cp_commit();
        COMPUTE(c % 3);
    }

    // ---------------- epilogue ----------------
    float* sh3 = (float*)sm_raw;             // OSPLIT==2: 128 x 132 fp32 tile
    if (OSPLIT == 2) __syncthreads();        // pipeline reads done before reuse

    #pragma unroll
    for (int t2 = 0; t2 < 2; t2++) {
        const int rloc = wr + t2 * 16 + (lane >> 2);
        const int row0 = bm * 128 + rloc;
        #pragma unroll
        for (int nt = 0; nt < 8; nt++) {
            const int cloc = wc + nt * 8 + 2 * (lane & 3);
            const int col = bn * 128 + cloc;
            float b0 = __ldg(&bias[col]), b1 = __ldg(&bias[col + 1]);
            float s0 = 1.f, s1 = 1.f, f0 = 0.f, f1 = 0.f;
            if (EPI) {
                s0 = __ldg(&bng[col]) * rsqrtf(__ldg(&bnrv[col]) + 1e-5f);
                f0 = __ldg(&bnb[col]) - __ldg(&bnrm[col]) * s0;
                s1 = __ldg(&bng[col + 1]) * rsqrtf(__ldg(&bnrv[col + 1]) + 1e-5f);
                f1 = __ldg(&bnb[col + 1]) - __ldg(&bnrm[col + 1]) * s1;
            }
            float v00 = acc[t2][nt][0] + b0, v01 = acc[t2][nt][1] + b1;
            float v10 = acc[t2][nt][2] + b0, v11 = acc[t2][nt][3] + b1;
            if (EPI) {
                v00 = v00 * s0 + f0; v01 = v01 * s1 + f1;
                v10 = v10 * s0 + f0; v11 = v11 * s1 + f1;
            }
            v00 = fmaxf(v00, 0.f); v01 = fmaxf(v01, 0.f);
            v10 = fmaxf(v10, 0.f); v11 = fmaxf(v11, 0.f);
            if (OSPLIT == 1) {
                __nv_bfloat162 h0 = __floats2bfloat162_rn(v00, v01);
                __nv_bfloat162 l0 = __floats2bfloat162_rn(v00 - __bfloat162float(h0.x),
                                                          v01 - __bfloat162float(h0.y));
                __nv_bfloat162 h1 = __floats2bfloat162_rn(v10, v11);
                __nv_bfloat162 l1 = __floats2bfloat162_rn(v10 - __bfloat162float(h1.x),
                                                          v11 - __bfloat162float(h1.y));
                *(__nv_bfloat162*)(Chi + (size_t)row0 * N + col) = h0;
                *(__nv_bfloat162*)(Clo + (size_t)row0 * N + col) = l0;
                *(__nv_bfloat162*)(Chi + (size_t)(row0 + 8) * N + col) = h1;
                *(__nv_bfloat162*)(Clo + (size_t)(row0 + 8) * N + col) = l1;
            } else if (OSPLIT == 2) {
                sh3[rloc * 132 + cloc]       = v00;
                sh3[rloc * 132 + cloc + 1]   = v01;
                sh3[(rloc + 8) * 132 + cloc]     = v10;
                sh3[(rloc + 8) * 132 + cloc + 1] = v11;
            } else {
                *(float2*)(Cf + (size_t)row0 * N + col) = make_float2(v00, v01);
                *(float2*)(Cf + (size_t)(row0 + 8) * N + col) = make_float2(v10, v11);
            }
        }
    }

    if (OSPLIT == 2) {
        // ---- fused node head: out = sigmoid(h3 @ ni_w + ni_b), NC=8 -------
        __syncthreads();
        const int base = tid * 4;               // 4 outputs/thread, 1024 total
        #pragma unroll
        for (int i = 0; i < 4; i++) {
            const int idx = base + i;
            const int row = idx >> 3;
            const int j = idx & 7;
            const float* xr = &sh3[row * 132];
            float a = __ldg(&hb[j]);
            #pragma unroll 8
            for (int k = 0; k < H3; k++)
                a += xr[k] * __ldg(&hw[k * NC + j]);
            Cf[(size_t)(bm * 128 + row) * NC + j] = 1.f / (1.f + __expf(-a));
        }
    }
}

// ---------------- fp32 -> bf16 hi/lo split (for roi) ------------------------
__global__ __launch_bounds__(256)
void split_f32(const float4* __restrict__ in,
               uint2* __restrict__ hi, uint2* __restrict__ lo)
{
    int i = blockIdx.x * 256 + threadIdx.x;
    float4 v = in[i];
    __nv_bfloat162 h0 = __floats2bfloat162_rn(v.x, v.y);
    __nv_bfloat162 h1 = __floats2bfloat162_rn(v.z, v.w);
    __nv_bfloat162 l0 = __floats2bfloat162_rn(v.x - __bfloat162float(h0.x),
                                              v.y - __bfloat162float(h0.y));
    __nv_bfloat162 l1 = __floats2bfloat162_rn(v.z - __bfloat162float(h1.x),
                                              v.w - __bfloat162float(h1.y));
    uint2 uh, ul;
    memcpy(&uh.x, &h0, 4); memcpy(&uh.y, &h1, 4);
    memcpy(&ul.x, &l0, 4); memcpy(&ul.y, &l1, 4);
    hi[i] = uh; lo[i] = ul;
}

// ------- weight transpose + bf16 hi/lo split: in (R x C) -> out (C x R) -----
__global__ void transpose_split(const float* __restrict__ in,
                                __nv_bfloat16* __restrict__ ohi,
                                __nv_bfloat16* __restrict__ olo,
                                int R, int C)
{
    __shared__ float t[32][33];
    int x = blockIdx.x * 32 + threadIdx.x;
    int y = blockIdx.y * 32 + threadIdx.y;
    #pragma unroll
    for (int i = 0; i < 32; i += 8)
        t[threadIdx.y + i][threadIdx.x] = in[(size_t)(y + i) * C + x];
    __syncthreads();
    x = blockIdx.y * 32 + threadIdx.x;
    y = blockIdx.x * 32 + threadIdx.y;
    #pragma unroll
    for (int i = 0; i < 32; i += 8) {
        float v = t[threadIdx.x][threadIdx.y + i];
        __nv_bfloat16 h = __float2bfloat16(v);
        ohi[(size_t)(y + i) * R + x] = h;
        olo[(size_t)(y + i) * R + x] = __float2bfloat16(v - __bfloat162float(h));
    }
}

// ---------------- edge weight prep: transpose+pad to bf16 -------------------
__global__ void prep_edge_weights(const float* __restrict__ w1,
                                  const float* __restrict__ w2,
                                  const float* __restrict__ wi,
                                  __nv_bfloat16* __restrict__ o1,
                                  __nv_bfloat16* __restrict__ o2,
                                  __nv_bfloat16* __restrict__ o3)
{
    int t = blockIdx.x * 256 + threadIdx.x;
    int stride = gridDim.x * 256;
    for (int i = t; i < 64 * 32; i += stride) {
        int n = i >> 5, k = i & 31;
        o1[i] = (k < 18) ? __float2bfloat16(w1[k * 64 + n]) : __nv_bfloat16(0.f);
    }
    for (int i = t; i < 64 * 64; i += stride) {
        int n = i >> 6, k = i & 63;
        o2[i] = __float2bfloat16(w2[k * 64 + n]);
    }
    for (int i = t; i < 16 * 64; i += stride) {
        int n = i >> 6, k = i & 63;
        o3[i] = (n < EC) ? __float2bfloat16(wi[k * EC + n]) : __nv_bfloat16(0.f);
    }
}

// ---------------- edge MLP on tensor cores (verified R4) --------------------
static constexpr int ESA_ATTR = 0;
static constexpr int ESA_W1   = 10240;
static constexpr int ESA_W2   = 14336;
static constexpr int ESA_W3   = 22528;
static constexpr int ESA_A1   = 24576;
static constexpr int ESA_H    = 32768;
static constexpr int ESA_G    = 49152;
static constexpr int EDGE_SMEM = 65536;

__global__ __launch_bounds__(128)
void edge_mma_kernel(const float* __restrict__ bboxes,
                     const float* __restrict__ dirs,
                     const float* __restrict__ prio,
                     const int*   __restrict__ eidx,
                     const __nv_bfloat16* __restrict__ w1t,
                     const __nv_bfloat16* __restrict__ w2t,
                     const __nv_bfloat16* __restrict__ w3t,
                     const float* __restrict__ b1,
                     const float* __restrict__ b2,
                     const float* __restrict__ bi,
                     float* __restrict__ out)
{
    extern __shared__ char sm[];
    const uint32_t sb = smem_u32(sm);
    const int tid = threadIdx.x;
    const int lane = tid & 31, w = tid >> 5;
    const int bt = blockIdx.x >> 8;
    const int e0 = (blockIdx.x & 255) * 128;

    __nv_bfloat16* sAttr = (__nv_bfloat16*)(sm + ESA_ATTR);
    const float inv = 1.f / 1024.f;
    for (int n = tid; n < NNODE; n += 128) {
        int gn = bt * NNODE + n;
        float4 bb = *(const float4*)&bboxes[(size_t)gn * 4];
        float4 dd = *(const float4*)&dirs[(size_t)gn * 4];
        float pr = prio[gn];
        __nv_bfloat16* a = sAttr + n * 10;
        a[0] = __float2bfloat16(bb.x * inv);
        a[1] = __float2bfloat16(bb.y * inv);
        a[2] = __float2bfloat16(bb.z * inv);
        a[3] = __float2bfloat16(bb.w * inv);
        a[4] = __float2bfloat16(dd.x);
        a[5] = __float2bfloat16(dd.y);
        a[6] = __float2bfloat16(dd.z);
        a[7] = __float2bfloat16(dd.w);
        a[8] = __float2bfloat16(pr);
    }
    for (int i = tid; i < 64 * 4; i += 128) {
        int r = i >> 2, c = i & 3;
        uint4 v = ((const uint4*)w1t)[r * 4 + c];
        sts128(sb + ESA_W1 + r * 64 + ((c ^ ((r >> 1) & 3)) << 4), v);
    }
    for (int i = tid; i < 64 * 8; i += 128) {
        int r = i >> 3, c = i & 7;
        uint4 v = ((const uint4*)w2t)[r * 8 + c];
        sts128(sb + ESA_W2 + r * 128 + ((c ^ (r & 7)) << 4), v);
    }
    for (int i = tid; i < 16 * 8; i += 128) {
        int r = i >> 3, c = i & 7;
        uint4 v = ((const uint4*)w3t)[r * 8 + c];
        sts128(sb + ESA_W3 + r * 128 + ((c ^ (r & 7)) << 4), v);
    }
    __syncthreads();

    {
        const int ebase = bt * 2 * EDGES + e0 + tid;
        const int src = eidx[ebase];
        const int dst = eidx[ebase + EDGES];
        const __nv_bfloat16* as = sAttr + src * 10;
        const __nv_bfloat16* ad = sAttr + dst * 10;
        uint16_t v[32];
        #pragma unroll
        for (int c = 0; c < 9; c++) { memcpy(&v[c], &as[c], 2); memcpy(&v[9 + c], &ad[c], 2); }
        #pragma unroll
        for (int c = 18; c < 32; c++) v[c] = 0;
        const int swz = (tid >> 1) & 3;
        #pragma unroll
        for (int ch = 0; ch < 4; ch++) {
            uint4 p;
            p.x = (uint32_t)v[ch*8+0] | ((uint32_t)v[ch*8+1] << 16);
            p.y = (uint32_t)v[ch*8+2] | ((uint32_t)v[ch*8+3] << 16);
            p.z = (uint32_t)v[ch*8+4] | ((uint32_t)v[ch*8+5] << 16);
            p.w = (uint32_t)v[ch*8+6] | ((uint32_t)v[ch*8+7] << 16);
            sts128(sb + ESA_A1 + tid * 64 + ((ch ^ swz) << 4), p);
        }
    }
    __syncthreads();

    const int m = lane >> 3, rr = lane & 7;
    const int wr = w * 32;

    {
        float acc[2][8][4];
        #pragma unroll
        for (int a = 0; a < 2; a++)
            #pragma unroll
            for (int b = 0; b < 8; b++)
                #pragma unroll
                for (int c = 0; c < 4; c++) acc[a][b][c] = 0.f;

        #pragma unroll
        for (int k16 = 0; k16 < 2; k16++) {
            uint32_t a[2][4], b[4][4];
            #pragma unroll
            for (int t2 = 0; t2 < 2; t2++) {
                int r = wr + t2 * 16 + ((m & 1) << 3) + rr;
                int c = k16 * 2 + (m >> 1);
                ldsm4(sb + ESA_A1 + r * 64 + ((c ^ ((r >> 1) & 3)) << 4), a[t2]);
            }
            #pragma unroll
            for (int p = 0; p < 4; p++) {
                int n = p * 16 + ((m >> 1) << 3) + rr;
                int c = k16 * 2 + (m & 1);
                ldsm4(sb + ESA_W1 + n * 64 + ((c ^ ((n >> 1) & 3)) << 4), b[p]);
            }
            #pragma unroll
            for (int t2 = 0; t2 < 2; t2++)
                #pragma unroll
                for (int nt = 0; nt < 8; nt++)
                    mma16816(acc[t2][nt], a[t2], &b[nt >> 1][(nt & 1) * 2]);
        }
        #pragma unroll
        for (int t2 = 0; t2 < 2; t2++) {
            int r0 = wr + t2 * 16 + (lane >> 2);
            #pragma unroll
            for (int nt = 0; nt < 8; nt++) {
                int col = nt * 8 + 2 * (lane & 3);
                float bb0 = __ldg(&b1[col]), bb1 = __ldg(&b1[col + 1]);
                float v00 = fmaxf(acc[t2][nt][0] + bb0, 0.f);
                float v01 = fmaxf(acc[t2][nt][1] + bb1, 0.f);
                float v10 = fmaxf(acc[t2][nt][2] + bb0, 0.f);
                float v11 = fmaxf(acc[t2][nt][3] + bb1, 0.f);
                uint32_t inb = (col & 7) * 2;
                sts32(sb + ESA_H + r0 * 128 + (((nt) ^ (r0 & 7)) << 4) + inb,
                      pack_bf2(v00, v01));
                int r1 = r0 + 8;
                sts32(sb + ESA_H + r1 * 128 + (((nt) ^ (r1 & 7)) << 4) + inb,
                      pack_bf2(v10, v11));
            }
        }
    }
    __syncwarp();

    {
        float acc[2][8][4];
        #pragma unroll
        for (int a = 0; a < 2; a++)
            #pragma unroll
            for (int b = 0; b < 8; b++)
                #pragma unroll
                for (int c = 0; c < 4; c++) acc[a][b][c] = 0.f;

        #pragma unroll
        for (int k16 = 0; k16 < 4; k16++) {
            uint32_t a[2][4], b[4][4];
            #pragma unroll
            for (int t2 = 0; t2 < 2; t2++) {
                int r = wr + t2 * 16 + ((m & 1) << 3) + rr;
                int c = k16 * 2 + (m >> 1);
                ldsm4(sb + ESA_H + r * 128 + ((c ^ (r & 7)) << 4), a[t2]);
            }
            #pragma unroll
            for (int p = 0; p < 4; p++) {
                int n = p * 16 + ((m >> 1) << 3) + rr;
                int c = k16 * 2 + (m & 1);
                ldsm4(sb + ESA_W2 + n * 128 + ((c ^ (n & 7)) << 4), b[p]);
            }
            #pragma unroll
            for (int t2 = 0; t2 < 2; t2++)
                #pragma unroll
                for (int nt = 0; nt < 8; nt++)
                    mma16816(acc[t2][nt], a[t2], &b[nt >> 1][(nt & 1) * 2]);
        }
        #pragma unroll
        for (int t2 = 0; t2 < 2; t2++) {
            int r0 = wr + t2 * 16 + (lane >> 2);
            #pragma unroll
            for (int nt = 0; nt < 8; nt++) {
                int col = nt * 8 + 2 * (lane & 3);
                float bb0 = __ldg(&b2[col]), bb1 = __ldg(&b2[col + 1]);
                float v00 = fmaxf(acc[t2][nt][0] + bb0, 0.f);
                float v01 = fmaxf(acc[t2][nt][1] + bb1, 0.f);
                float v10 = fmaxf(acc[t2][nt][2] + bb0, 0.f);
                float v11 = fmaxf(acc[t2][nt][3] + bb1, 0.f);
                uint32_t inb = (col & 7) * 2;
                sts32(sb + ESA_G + r0 * 128 + (((nt) ^ (r0 & 7)) << 4) + inb,
                      pack_bf2(v00, v01));
                int r1 = r0 + 8;
                sts32(sb + ESA_G + r1 * 128 + (((nt) ^ (r1 & 7)) << 4) + inb,
                      pack_bf2(v10, v11));
            }
        }
    }
    __syncwarp();

    {
        float acc[2][2][4];
        #pragma unroll
        for (int a = 0; a < 2; a++)
            #pragma unroll
            for (int b = 0; b < 2; b++)
                #pragma unroll
                for (int c = 0; c < 4; c++) acc[a][b][c] = 0.f;

        #pragma unroll
        for (int k16 = 0; k16 < 4; k16++) {
            uint32_t a[2][4], b[4];
            #pragma unroll
            for (int t2 = 0; t2 < 2; t2++) {
                int r = wr + t2 * 16 + ((m & 1) << 3) + rr;
                int c = k16 * 2 + (m >> 1);
                ldsm4(sb + ESA_G + r * 128 + ((c ^ (r & 7)) << 4), a[t2]);
            }
            {
                int n = ((m >> 1) << 3) + rr;
                int c = k16 * 2 + (m & 1);
                ldsm4(sb + ESA_W3 + n * 128 + ((c ^ (n & 7)) << 4), b);
            }
            #pragma unroll
            for (int t2 = 0; t2 < 2; t2++) {
                mma16816(acc[t2][0], a[t2], &b[0]);
                mma16816(acc[t2][1], a[t2], &b[2]);
            }
        }
        #pragma unroll
        for (int t2 = 0; t2 < 2; t2++) {
            int r0 = wr + t2 * 16 + (lane >> 2);
            long eg = (long)bt * EDGES + e0 + r0;
            #pragma unroll
            for (int nt = 0; nt < 2; nt++) {
                int col = nt * 8 + 2 * (lane & 3);
                if (col < EC) {
                    float bb0 = __ldg(&bi[col]), bb1 = __ldg(&bi[col + 1]);
                    float s00 = 1.f / (1.f + __expf(-(acc[t2][nt][0] + bb0)));
                    float s01 = 1.f / (1.f + __expf(-(acc[t2][nt][1] + bb1)));
                    float s10 = 1.f / (1.f + __expf(-(acc[t2][nt][2] + bb0)));
                    float s11 = 1.f / (1.f + __expf(-(acc[t2][nt][3] + bb1)));
                    *(float2*)(out + eg * EC + col) = make_float2(s00, s01);
                    *(float2*)(out + (eg + 8) * EC + col) = make_float2(s10, s11);
                }
            }
        }
    }
}

// ---------------- launch ----------------------------------------------------
extern "C" void kernel_launch(void* const* d_in, const int* in_sizes, int n_in,
                              void* d_out, int out_size)
{
    const float* roi    = (const float*)d_in[0];
    const float* bboxes = (const float*)d_in[1];
    const float* dirs   = (const float*)d_in[2];
    const float* prio   = (const float*)d_in[3];
    const int*   eidx   = (const int*)  d_in[4];
    const float* np_w1  = (const float*)d_in[5];
    const float* np_b1  = (const float*)d_in[6];
    const float* bn1_g  = (const float*)d_in[7];
    const float* bn1_b  = (const float*)d_in[8];
    const float* bn1_rm = (const float*)d_in[9];
    const float* bn1_rv = (const float*)d_in[10];
    const float* np_w2  = (const float*)d_in[11];
    const float* np_b2  = (const float*)d_in[12];
    const float* bn2_g  = (const float*)d_in[13];
    const float* bn2_b  = (const float*)d_in[14];
    const float* bn2_rm = (const float*)d_in[15];
    const float* bn2_rv = (const float*)d_in[16];
    const float* np_w3  = (const float*)d_in[17];
    const float* np_b3  = (const float*)d_in[18];
    const float* ni_w   = (const float*)d_in[19];
    const float* ni_b   = (const float*)d_in[20];
    const float* ep_w1  = (const float*)d_in[21];
    const float* ep_b1  = (const float*)d_in[22];
    const float* ep_w2  = (const float*)d_in[23];
    const float* ep_b2  = (const float*)d_in[24];
    const float* ei_w   = (const float*)d_in[25];
    const float* ei_b   = (const float*)d_in[26];

    float* out = (float*)d_out;

    __nv_bfloat16 *xhi, *xlo, *h1hi, *h1lo, *h2hi, *h2lo;
    __nv_bfloat16 *w1hi, *w1lo, *w2hi, *w2lo, *w3hi, *w3lo;
    __nv_bfloat16 *ew1t, *ew2t, *ew3t;
    cudaGetSymbolAddress((void**)&xhi, g_xhi);
    cudaGetSymbolAddress((void**)&xlo, g_xlo);
    cudaGetSymbolAddress((void**)&h1hi, g_h1hi);
    cudaGetSymbolAddress((void**)&h1lo, g_h1lo);
    cudaGetSymbolAddress((void**)&h2hi, g_h2hi);
    cudaGetSymbolAddress((void**)&h2lo, g_h2lo);
    cudaGetSymbolAddress((void**)&w1hi, g_w1hi);
    cudaGetSymbolAddress((void**)&w1lo, g_w1lo);
    cudaGetSymbolAddress((void**)&w2hi, g_w2hi);
    cudaGetSymbolAddress((void**)&w2lo, g_w2lo);
    cudaGetSymbolAddress((void**)&w3hi, g_w3hi);
    cudaGetSymbolAddress((void**)&w3lo, g_w3lo);
    cudaGetSymbolAddress((void**)&ew1t, g_ew1t);
    cudaGetSymbolAddress((void**)&ew2t, g_ew2t);
    cudaGetSymbolAddress((void**)&ew3t, g_ew3t);

    cudaFuncSetAttribute(edge_mma_kernel,
                         cudaFuncAttributeMaxDynamicSharedMemorySize, EDGE_SMEM);
    cudaFuncSetAttribute(gemm_mma2<FDIM, H1, 1, 1>,
                         cudaFuncAttributeMaxDynamicSharedMemorySize, GEMM_SMEM);
    cudaFuncSetAttribute(gemm_mma2<H1, H2, 1, 1>,
                         cudaFuncAttributeMaxDynamicSharedMemorySize, GEMM_SMEM);
    cudaFuncSetAttribute(gemm_mma2<H2, H3, 0, 2>,
                         cudaFuncAttributeMaxDynamicSharedMemorySize, GEMM_SMEM);

    // one-time stream/event setup (host-side resources; no device memory)
    static cudaStream_t s_edge = nullptr;
    static cudaEvent_t  ev_fork = nullptr, ev_join = nullptr;
    if (s_edge == nullptr) {
        cudaStreamCreateWithFlags(&s_edge, cudaStreamNonBlocking);
        cudaEventCreateWithFlags(&ev_fork, cudaEventDisableTiming);
        cudaEventCreateWithFlags(&ev_join, cudaEventDisableTiming);
    }

    // ---- critical-path prep first: roi split gets a head start ----
    split_f32<<<NROWS * FDIM / 4 / 256, 256>>>((const float4*)roi,
                                               (uint2*)xhi, (uint2*)xlo);

    // ---- fork: edge branch runs concurrently on s_edge ----
    cudaEventRecord(ev_fork, 0);
    cudaStreamWaitEvent(s_edge, ev_fork, 0);
    prep_edge_weights<<<8, 256, 0, s_edge>>>(ep_w1, ep_w2, ei_w, ew1t, ew2t, ew3t);
    edge_mma_kernel<<<NEDGE / 128, 128, EDGE_SMEM, s_edge>>>(
        bboxes, dirs, prio, eidx, ew1t, ew2t, ew3t,
        ep_b1, ep_b2, ei_b, out + NODE_OUT_ELEMS);
    cudaEventRecord(ev_join, s_edge);

    // ---- node branch on the capture stream ----
    {
        dim3 b(32, 8);
        transpose_split<<<dim3(H1 / 32, FDIM / 32), b>>>(np_w1, w1hi, w1lo, FDIM, H1);
        transpose_split<<<dim3(H2 / 32, H1 / 32), b>>>(np_w2, w2hi, w2lo, H1, H2);
        transpose_split<<<dim3(H3 / 32, H2 / 32), b>>>(np_w3, w3hi, w3lo, H2, H3);
    }

    gemm_mma2<FDIM, H1, 1, 1><<<dim3(H1 / 128, NROWS / 128), 256, GEMM_SMEM>>>(
        xhi, xlo, w1hi, w1lo,
        np_b1, bn1_g, bn1_b, bn1_rm, bn1_rv, nullptr, nullptr, nullptr, h1hi, h1lo);
    gemm_mma2<H1, H2, 1, 1><<<dim3(H2 / 128, NROWS / 128), 256, GEMM_SMEM>>>(
        h1hi, h1lo, w2hi, w2lo,
        np_b2, bn2_g, bn2_b, bn2_rm, bn2_rv, nullptr, nullptr, nullptr, h2hi, h2lo);
    gemm_mma2<H2, H3, 0, 2><<<dim3(H3 / 128, NROWS / 128), 256, GEMM_SMEM>>>(
        h2hi, h2lo, w3hi, w3lo,
        np_b3, nullptr, nullptr, nullptr, nullptr, ni_w, ni_b, out, nullptr, nullptr);

    // ---- join: capture stream waits for the edge branch ----
    cudaStreamWaitEvent(0, ev_join, 0);
}

// round 8
// speedup vs baseline: 3.9548x; 1.1598x over previous
#include <cuda_runtime.h>
#include <cuda_bf16.h>
#include <cstdint>

// ---------------- problem constants (fixed by setup_inputs) ----------------
#define BATCH   32
#define NNODE   512
#define NROWS   (BATCH*NNODE)      // 16384
#define FDIM    1024
#define H1      512
#define H2      256
#define H3      128
#define NC      8
#define EDGES   32768              // per batch
#define NEDGE   (BATCH*EDGES)      // 1048576
#define EH      64
#define EC      10
#define CATTR   9
#define NODE_OUT_ELEMS (NROWS*NC)  // 131072

// ---------------- scratch (device globals; no allocation allowed) ----------
__device__ __nv_bfloat16 g_xhi[NROWS * FDIM], g_xlo[NROWS * FDIM];  // split roi
__device__ __nv_bfloat16 g_h1hi[NROWS * H1],  g_h1lo[NROWS * H1];
__device__ __nv_bfloat16 g_h2hi[NROWS * H2],  g_h2lo[NROWS * H2];
__device__ __nv_bfloat16 g_w1hi[H1 * FDIM],   g_w1lo[H1 * FDIM];
__device__ __nv_bfloat16 g_w2hi[H2 * H1],     g_w2lo[H2 * H1];
__device__ __nv_bfloat16 g_w3hi[H3 * H2],     g_w3lo[H3 * H2];
__device__ __nv_bfloat16 g_ew1t[64 * 32];
__device__ __nv_bfloat16 g_ew2t[64 * 64];
__device__ __nv_bfloat16 g_ew3t[16 * 64];

// ---------------- helpers ----------------------------------------------------
__device__ __forceinline__ uint32_t smem_u32(const void* p) {
    uint32_t a;
    asm("{ .reg .u64 t; cvta.to.shared.u64 t, %1; cvt.u32.u64 %0, t; }"
        : "=r"(a) : "l"(p));
    return a;
}
__device__ __forceinline__ void ldsm4(uint32_t addr, uint32_t* r) {
    asm volatile("ldmatrix.sync.aligned.m8n8.x4.shared.b16 {%0,%1,%2,%3}, [%4];"
                 : "=r"(r[0]), "=r"(r[1]), "=r"(r[2]), "=r"(r[3]) : "r"(addr));
}
__device__ __forceinline__ void mma16816(float* c, const uint32_t* a, const uint32_t* b) {
    asm volatile(
        "mma.sync.aligned.m16n8k16.row.col.f32.bf16.bf16.f32 "
        "{%0,%1,%2,%3}, {%4,%5,%6,%7}, {%8,%9}, {%0,%1,%2,%3};"
        : "+f"(c[0]), "+f"(c[1]), "+f"(c[2]), "+f"(c[3])
        : "r"(a[0]), "r"(a[1]), "r"(a[2]), "r"(a[3]), "r"(b[0]), "r"(b[1]));
}
__device__ __forceinline__ void sts128(uint32_t addr, uint4 v) {
    asm volatile("st.shared.v4.b32 [%0], {%1,%2,%3,%4};"
                 :: "r"(addr), "r"(v.x), "r"(v.y), "r"(v.z), "r"(v.w) : "memory");
}
__device__ __forceinline__ void sts32(uint32_t addr, uint32_t v) {
    asm volatile("st.shared.b32 [%0], %1;" :: "r"(addr), "r"(v) : "memory");
}
__device__ __forceinline__ uint32_t pack_bf2(float a, float b) {
    __nv_bfloat162 h = __floats2bfloat162_rn(a, b);
    uint32_t u; memcpy(&u, &h, 4); return u;
}
__device__ __forceinline__ void cp16(uint32_t dst, const void* src) {
    asm volatile("cp.async.cg.shared.global [%0], [%1], 16;"
                 :: "r"(dst), "l"(src) : "memory");
}
__device__ __forceinline__ void cp_commit() {
    asm volatile("cp.async.commit_group;" ::: "memory");
}
#define CP_WAIT(n) asm volatile("cp.async.wait_group %0;" :: "n"(n) : "memory")

// ---------------- split-bf16 mma GEMM, cp.async 3-stage pipeline ------------
// (verified R5-R7 structure; OSPLIT==2 fuses the node head)
static constexpr int STAGE_BYTES = 32768;   // Ahi|Alo|Bhi|Blo x 8KB
static constexpr int GEMM_SMEM = 3 * STAGE_BYTES;

template<int K, int N, int EPI, int OSPLIT>
__global__ __launch_bounds__(256)
void gemm_mma2(const __nv_bfloat16* __restrict__ Ahi, const __nv_bfloat16* __restrict__ Alo,
               const __nv_bfloat16* __restrict__ Bhi, const __nv_bfloat16* __restrict__ Blo,
               const float* __restrict__ bias,
               const float* __restrict__ bng, const float* __restrict__ bnb,
               const float* __restrict__ bnrm, const float* __restrict__ bnrv,
               const float* __restrict__ hw,  const float* __restrict__ hb,
               float* __restrict__ Cf,
               __nv_bfloat16* __restrict__ Chi, __nv_bfloat16* __restrict__ Clo)
{
    extern __shared__ char sm_raw[];
    const uint32_t sb = smem_u32(sm_raw);
    const int tid = threadIdx.x;
    const int lane = tid & 31, w = tid >> 5;
    const int bn = blockIdx.x, bm = blockIdx.y;
    const int wr = (w & 3) * 32;
    const int wc = (w >> 2) * 64;

    const __nv_bfloat16* srcs[8];
    uint32_t dsts[8];
    #pragma unroll
    for (int i = 0; i < 8; i++) {
        int idx = i * 256 + tid;
        int slab = idx >> 9;
        int within = idx & 511;
        int r = within >> 2, c = within & 3;
        const __nv_bfloat16* base = (slab == 0) ? Ahi : (slab == 1) ? Alo
                                   : (slab == 2) ? Bhi : Blo;
        int row0 = (slab < 2) ? bm * 128 : bn * 128;
        srcs[i] = base + (size_t)(row0 + r) * K + c * 8;
        dsts[i] = slab * 8192 + r * 64 + ((c ^ ((r >> 1) & 3)) << 4);
    }
    auto ISSUE = [&](int ck) {
        const uint32_t st = sb + (ck % 3) * STAGE_BYTES;
        #pragma unroll
        for (int i = 0; i < 8; i++)
            cp16(st + dsts[i], srcs[i] + ck * 32);
    };

    float acc[2][8][4];
    #pragma unroll
    for (int a = 0; a < 2; a++)
        #pragma unroll
        for (int b = 0; b < 8; b++)
            #pragma unroll
            for (int c = 0; c < 4; c++) acc[a][b][c] = 0.f;

    const int m = lane >> 3, rr = lane & 7;

    auto COMPUTE = [&](int stage) {
        const uint32_t aB = sb + stage * STAGE_BYTES;
        const uint32_t bB = aB + 16384;
        #pragma unroll
        for (int ks = 0; ks < 2; ks++) {
            const int ckb = ks * 2;
            uint32_t ah[2][4], al[2][4], bh[4][4], bl[4][4];
            #pragma unroll
            for (int t2 = 0; t2 < 2; t2++) {
                const int r_l = wr + t2 * 16 + ((m & 1) << 3) + rr;
                const int c_l = ckb + (m >> 1);
                const uint32_t off = r_l * 64 + ((c_l ^ ((r_l >> 1) & 3)) << 4);
                ldsm4(aB + off, ah[t2]);
                ldsm4(aB + 8192 + off, al[t2]);
            }
            #pragma unroll
            for (int p = 0; p < 4; p++) {
                const int n_l = wc + p * 16 + ((m >> 1) << 3) + rr;
                const int c_l = ckb + (m & 1);
                const uint32_t off = n_l * 64 + ((c_l ^ ((n_l >> 1) & 3)) << 4);
                ldsm4(bB + off, bh[p]);
                ldsm4(bB + 8192 + off, bl[p]);
            }
            #pragma unroll
            for (int t2 = 0; t2 < 2; t2++)
                #pragma unroll
                for (int nt = 0; nt < 8; nt++) {
                    const uint32_t* Bh = &bh[nt >> 1][(nt & 1) * 2];
                    const uint32_t* Bl = &bl[nt >> 1][(nt & 1) * 2];
                    mma16816(acc[t2][nt], ah[t2], Bh);
                    mma16816(acc[t2][nt], al[t2], Bh);
                    mma16816(acc[t2][nt], ah[t2], Bl);
                }
        }
    };

    constexpr int NCH = K / 32;
    ISSUE(0); cp_commit();
    ISSUE(1); cp_commit();
    for (int c = 0; c < NCH; c++) {
        CP_WAIT(1);
        __syncthreads();
        if (c + 2 < NCH) ISSUE(c + 2);
        cp_commit();
        COMPUTE(c % 3);
    }

    float* sh3 = (float*)sm_raw;
    if (OSPLIT == 2) __syncthreads();

    #pragma unroll
    for (int t2 = 0; t2 < 2; t2++) {
        const int rloc = wr + t2 * 16 + (lane >> 2);
        const int row0 = bm * 128 + rloc;
        #pragma unroll
        for (int nt = 0; nt < 8; nt++) {
            const int cloc = wc + nt * 8 + 2 * (lane & 3);
            const int col = bn * 128 + cloc;
            float b0 = __ldg(&bias[col]), b1 = __ldg(&bias[col + 1]);
            float s0 = 1.f, s1 = 1.f, f0 = 0.f, f1 = 0.f;
            if (EPI) {
                s0 = __ldg(&bng[col]) * rsqrtf(__ldg(&bnrv[col]) + 1e-5f);
                f0 = __ldg(&bnb[col]) - __ldg(&bnrm[col]) * s0;
                s1 = __ldg(&bng[col + 1]) * rsqrtf(__ldg(&bnrv[col + 1]) + 1e-5f);
                f1 = __ldg(&bnb[col + 1]) - __ldg(&bnrm[col + 1]) * s1;
            }
            float v00 = acc[t2][nt][0] + b0, v01 = acc[t2][nt][1] + b1;
            float v10 = acc[t2][nt][2] + b0, v11 = acc[t2][nt][3] + b1;
            if (EPI) {
                v00 = v00 * s0 + f0; v01 = v01 * s1 + f1;
                v10 = v10 * s0 + f0; v11 = v11 * s1 + f1;
            }
            v00 = fmaxf(v00, 0.f); v01 = fmaxf(v01, 0.f);
            v10 = fmaxf(v10, 0.f); v11 = fmaxf(v11, 0.f);
            if (OSPLIT == 1) {
                __nv_bfloat162 h0 = __floats2bfloat162_rn(v00, v01);
                __nv_bfloat162 l0 = __floats2bfloat162_rn(v00 - __bfloat162float(h0.x),
                                                          v01 - __bfloat162float(h0.y));
                __nv_bfloat162 h1 = __floats2bfloat162_rn(v10, v11);
                __nv_bfloat162 l1 = __floats2bfloat162_rn(v10 - __bfloat162float(h1.x),
                                                          v11 - __bfloat162float(h1.y));
                *(__nv_bfloat162*)(Chi + (size_t)row0 * N + col) = h0;
                *(__nv_bfloat162*)(Clo + (size_t)row0 * N + col) = l0;
                *(__nv_bfloat162*)(Chi + (size_t)(row0 + 8) * N + col) = h1;
                *(__nv_bfloat162*)(Clo + (size_t)(row0 + 8) * N + col) = l1;
            } else if (OSPLIT == 2) {
                sh3[rloc * 132 + cloc]       = v00;
                sh3[rloc * 132 + cloc + 1]   = v01;
                sh3[(rloc + 8) * 132 + cloc]     = v10;
                sh3[(rloc + 8) * 132 + cloc + 1] = v11;
            } else {
                *(float2*)(Cf + (size_t)row0 * N + col) = make_float2(v00, v01);
                *(float2*)(Cf + (size_t)(row0 + 8) * N + col) = make_float2(v10, v11);
            }
        }
    }

    if (OSPLIT == 2) {
        __syncthreads();
        const int base = tid * 4;
        #pragma unroll
        for (int i = 0; i < 4; i++) {
            const int idx = base + i;
            const int row = idx >> 3;
            const int j = idx & 7;
            const float* xr = &sh3[row * 132];
            float a = __ldg(&hb[j]);
            #pragma unroll 8
            for (int k = 0; k < H3; k++)
                a += xr[k] * __ldg(&hw[k * NC + j]);
            Cf[(size_t)(bm * 128 + row) * NC + j] = 1.f / (1.f + __expf(-a));
        }
    }
}

// ---------------- fp32 -> bf16 hi/lo split (for roi) ------------------------
__global__ __launch_bounds__(256)
void split_f32(const float4* __restrict__ in,
               uint2* __restrict__ hi, uint2* __restrict__ lo)
{
    int i = blockIdx.x * 256 + threadIdx.x;
    float4 v = in[i];
    __nv_bfloat162 h0 = __floats2bfloat162_rn(v.x, v.y);
    __nv_bfloat162 h1 = __floats2bfloat162_rn(v.z, v.w);
    __nv_bfloat162 l0 = __floats2bfloat162_rn(v.x - __bfloat162float(h0.x),
                                              v.y - __bfloat162float(h0.y));
    __nv_bfloat162 l1 = __floats2bfloat162_rn(v.z - __bfloat162float(h1.x),
                                              v.w - __bfloat162float(h1.y));
    uint2 uh, ul;
    memcpy(&uh.x, &h0, 4); memcpy(&uh.y, &h1, 4);
    memcpy(&ul.x, &l0, 4); memcpy(&ul.y, &l1, 4);
    hi[i] = uh; lo[i] = ul;
}

// ------- weight transpose + bf16 hi/lo split: in (R x C) -> out (C x R) -----
__global__ void transpose_split(const float* __restrict__ in,
                                __nv_bfloat16* __restrict__ ohi,
                                __nv_bfloat16* __restrict__ olo,
                                int R, int C)
{
    __shared__ float t[32][33];
    int x = blockIdx.x * 32 + threadIdx.x;
    int y = blockIdx.y * 32 + threadIdx.y;
    #pragma unroll
    for (int i = 0; i < 32; i += 8)
        t[threadIdx.y + i][threadIdx.x] = in[(size_t)(y + i) * C + x];
    __syncthreads();
    x = blockIdx.y * 32 + threadIdx.x;
    y = blockIdx.x * 32 + threadIdx.y;
    #pragma unroll
    for (int i = 0; i < 32; i += 8) {
        float v = t[threadIdx.x][threadIdx.y + i];
        __nv_bfloat16 h = __float2bfloat16(v);
        ohi[(size_t)(y + i) * R + x] = h;
        olo[(size_t)(y + i) * R + x] = __float2bfloat16(v - __bfloat162float(h));
    }
}

// ---------------- edge weight prep: transpose+pad to bf16 -------------------
__global__ void prep_edge_weights(const float* __restrict__ w1,
                                  const float* __restrict__ w2,
                                  const float* __restrict__ wi,
                                  __nv_bfloat16* __restrict__ o1,
                                  __nv_bfloat16* __restrict__ o2,
                                  __nv_bfloat16* __restrict__ o3)
{
    int t = blockIdx.x * 256 + threadIdx.x;
    int stride = gridDim.x * 256;
    for (int i = t; i < 64 * 32; i += stride) {
        int n = i >> 5, k = i & 31;
        o1[i] = (k < 18) ? __float2bfloat16(w1[k * 64 + n]) : __nv_bfloat16(0.f);
    }
    for (int i = t; i < 64 * 64; i += stride) {
        int n = i >> 6, k = i & 63;
        o2[i] = __float2bfloat16(w2[k * 64 + n]);
    }
    for (int i = t; i < 16 * 64; i += stride) {
        int n = i >> 6, k = i & 63;
        o3[i] = (n < EC) ? __float2bfloat16(wi[k * EC + n]) : __nv_bfloat16(0.f);
    }
}

// ---------------- edge MLP on tensor cores: 256 edges / 8 warps per CTA -----
// Warp w handles rows [wrow, wrow+32) with wrow = (w>>2)*128 + (w&3)*32.
// Each warp reads only rows it wrote -> __syncwarp between layers suffices.
static constexpr int ESA_ATTR = 0;            // 512*10*2  = 10240
static constexpr int ESA_W1   = 10240;        //           =  4096
static constexpr int ESA_W2   = 14336;        //           =  8192
static constexpr int ESA_W3   = 22528;        //           =  2048
static constexpr int ESA_A1   = 24576;        // 256*64    = 16384
static constexpr int ESA_H    = 40960;        // 256*128   = 32768
static constexpr int ESA_G    = 73728;        // 256*128   = 32768
static constexpr int EDGE_SMEM = 106496;

__global__ __launch_bounds__(256)
void edge_mma_kernel(const float* __restrict__ bboxes,
                     const float* __restrict__ dirs,
                     const float* __restrict__ prio,
                     const int*   __restrict__ eidx,
                     const __nv_bfloat16* __restrict__ w1t,
                     const __nv_bfloat16* __restrict__ w2t,
                     const __nv_bfloat16* __restrict__ w3t,
                     const float* __restrict__ b1,
                     const float* __restrict__ b2,
                     const float* __restrict__ bi,
                     float* __restrict__ out)
{
    extern __shared__ char sm[];
    const uint32_t sb = smem_u32(sm);
    const int tid = threadIdx.x;
    const int lane = tid & 31, w = tid >> 5;
    const int bt = blockIdx.x >> 7;             // 128 CTAs per batch
    const int e0 = (blockIdx.x & 127) * 256;    // first edge (within batch)

    __nv_bfloat16* sAttr = (__nv_bfloat16*)(sm + ESA_ATTR);
    const float inv = 1.f / 1024.f;
    for (int n = tid; n < NNODE; n += 256) {
        int gn = bt * NNODE + n;
        float4 bb = *(const float4*)&bboxes[(size_t)gn * 4];
        float4 dd = *(const float4*)&dirs[(size_t)gn * 4];
        float pr = prio[gn];
        __nv_bfloat16* a = sAttr + n * 10;
        a[0] = __float2bfloat16(bb.x * inv);
        a[1] = __float2bfloat16(bb.y * inv);
        a[2] = __float2bfloat16(bb.z * inv);
        a[3] = __float2bfloat16(bb.w * inv);
        a[4] = __float2bfloat16(dd.x);
        a[5] = __float2bfloat16(dd.y);
        a[6] = __float2bfloat16(dd.z);
        a[7] = __float2bfloat16(dd.w);
        a[8] = __float2bfloat16(pr);
    }
    for (int i = tid; i < 64 * 4; i += 256) {
        int r = i >> 2, c = i & 3;
        uint4 v = ((const uint4*)w1t)[r * 4 + c];
        sts128(sb + ESA_W1 + r * 64 + ((c ^ ((r >> 1) & 3)) << 4), v);
    }
    for (int i = tid; i < 64 * 8; i += 256) {
        int r = i >> 3, c = i & 7;
        uint4 v = ((const uint4*)w2t)[r * 8 + c];
        sts128(sb + ESA_W2 + r * 128 + ((c ^ (r & 7)) << 4), v);
    }
    for (int i = tid; i < 16 * 8; i += 256) {
        int r = i >> 3, c = i & 7;
        uint4 v = ((const uint4*)w3t)[r * 8 + c];
        sts128(sb + ESA_W3 + r * 128 + ((c ^ (r & 7)) << 4), v);
    }
    __syncthreads();

    // build A1: thread tid builds edge e0+tid (row tid of a 256x32 tile)
    {
        const int ebase = bt * 2 * EDGES + e0 + tid;
        const int src = eidx[ebase];
        const int dst = eidx[ebase + EDGES];
        const __nv_bfloat16* as = sAttr + src * 10;
        const __nv_bfloat16* ad = sAttr + dst * 10;
        uint16_t v[32];
        #pragma unroll
        for (int c = 0; c < 9; c++) { memcpy(&v[c], &as[c], 2); memcpy(&v[9 + c], &ad[c], 2); }
        #pragma unroll
        for (int c = 18; c < 32; c++) v[c] = 0;
        const int swz = (tid >> 1) & 3;
        #pragma unroll
        for (int ch = 0; ch < 4; ch++) {
            uint4 p;
            p.x = (uint32_t)v[ch*8+0] | ((uint32_t)v[ch*8+1] << 16);
            p.y = (uint32_t)v[ch*8+2] | ((uint32_t)v[ch*8+3] << 16);
            p.z = (uint32_t)v[ch*8+4] | ((uint32_t)v[ch*8+5] << 16);
            p.w = (uint32_t)v[ch*8+6] | ((uint32_t)v[ch*8+7] << 16);
            sts128(sb + ESA_A1 + tid * 64 + ((ch ^ swz) << 4), p);
        }
    }
    __syncthreads();

    const int m = lane >> 3, rr = lane & 7;
    const int wrow = (w >> 2) * 128 + (w & 3) * 32;   // this warp's 32-row block

    // ================= layer 1: (256x32) @ (64x32)^T -> H (256x64) ==========
    {
        float acc[2][8][4];
        #pragma unroll
        for (int a = 0; a < 2; a++)
            #pragma unroll
            for (int b = 0; b < 8; b++)
                #pragma unroll
                for (int c = 0; c < 4; c++) acc[a][b][c] = 0.f;

        #pragma unroll
        for (int k16 = 0; k16 < 2; k16++) {
            uint32_t a[2][4], b[4][4];
            #pragma unroll
            for (int t2 = 0; t2 < 2; t2++) {
                int r = wrow + t2 * 16 + ((m & 1) << 3) + rr;
                int c = k16 * 2 + (m >> 1);
                ldsm4(sb + ESA_A1 + r * 64 + ((c ^ ((r >> 1) & 3)) << 4), a[t2]);
            }
            #pragma unroll
            for (int p = 0; p < 4; p++) {
                int n = p * 16 + ((m >> 1) << 3) + rr;
                int c = k16 * 2 + (m & 1);
                ldsm4(sb + ESA_W1 + n * 64 + ((c ^ ((n >> 1) & 3)) << 4), b[p]);
            }
            #pragma unroll
            for (int t2 = 0; t2 < 2; t2++)
                #pragma unroll
                for (int nt = 0; nt < 8; nt++)
                    mma16816(acc[t2][nt], a[t2], &b[nt >> 1][(nt & 1) * 2]);
        }
        #pragma unroll
        for (int t2 = 0; t2 < 2; t2++) {
            int r0 = wrow + t2 * 16 + (lane >> 2);
            #pragma unroll
            for (int nt = 0; nt < 8; nt++) {
                int col = nt * 8 + 2 * (lane & 3);
                float bb0 = __ldg(&b1[col]), bb1 = __ldg(&b1[col + 1]);
                float v00 = fmaxf(acc[t2][nt][0] + bb0, 0.f);
                float v01 = fmaxf(acc[t2][nt][1] + bb1, 0.f);
                float v10 = fmaxf(acc[t2][nt][2] + bb0, 0.f);
                float v11 = fmaxf(acc[t2][nt][3] + bb1, 0.f);
                uint32_t inb = (col & 7) * 2;
                sts32(sb + ESA_H + r0 * 128 + (((nt) ^ (r0 & 7)) << 4) + inb,
                      pack_bf2(v00, v01));
                int r1 = r0 + 8;
                sts32(sb + ESA_H + r1 * 128 + (((nt) ^ (r1 & 7)) << 4) + inb,
                      pack_bf2(v10, v11));
            }
        }
    }
    __syncwarp();

    // ================= layer 2: (256x64) @ (64x64)^T -> G (256x64) ==========
    {
        float acc[2][8][4];
        #pragma unroll
        for (int a = 0; a < 2; a++)
            #pragma unroll
            for (int b = 0; b < 8; b++)
                #pragma unroll
                for (int c = 0; c < 4; c++) acc[a][b][c] = 0.f;

        #pragma unroll
        for (int k16 = 0; k16 < 4; k16++) {
            uint32_t a[2][4], b[4][4];
            #pragma unroll
            for (int t2 = 0; t2 < 2; t2++) {
                int r = wrow + t2 * 16 + ((m & 1) << 3) + rr;
                int c = k16 * 2 + (m >> 1);
                ldsm4(sb + ESA_H + r * 128 + ((c ^ (r & 7)) << 4), a[t2]);
            }
            #pragma unroll
            for (int p = 0; p < 4; p++) {
                int n = p * 16 + ((m >> 1) << 3) + rr;
                int c = k16 * 2 + (m & 1);
                ldsm4(sb + ESA_W2 + n * 128 + ((c ^ (n & 7)) << 4), b[p]);
            }
            #pragma unroll
            for (int t2 = 0; t2 < 2; t2++)
                #pragma unroll
                for (int nt = 0; nt < 8; nt++)
                    mma16816(acc[t2][nt], a[t2], &b[nt >> 1][(nt & 1) * 2]);
        }
        #pragma unroll
        for (int t2 = 0; t2 < 2; t2++) {
            int r0 = wrow + t2 * 16 + (lane >> 2);
            #pragma unroll
            for (int nt = 0; nt < 8; nt++) {
                int col = nt * 8 + 2 * (lane & 3);
                float bb0 = __ldg(&b2[col]), bb1 = __ldg(&b2[col + 1]);
                float v00 = fmaxf(acc[t2][nt][0] + bb0, 0.f);
                float v01 = fmaxf(acc[t2][nt][1] + bb1, 0.f);
                float v10 = fmaxf(acc[t2][nt][2] + bb0, 0.f);
                float v11 = fmaxf(acc[t2][nt][3] + bb1, 0.f);
                uint32_t inb = (col & 7) * 2;
                sts32(sb + ESA_G + r0 * 128 + (((nt) ^ (r0 & 7)) << 4) + inb,
                      pack_bf2(v00, v01));
                int r1 = r0 + 8;
                sts32(sb + ESA_G + r1 * 128 + (((nt) ^ (r1 & 7)) << 4) + inb,
                      pack_bf2(v10, v11));
            }
        }
    }
    __syncwarp();

    // ================= layer 3: (256x64) @ (16x64)^T -> sigmoid out =========
    {
        float acc[2][2][4];
        #pragma unroll
        for (int a = 0; a < 2; a++)
            #pragma unroll
            for (int b = 0; b < 2; b++)
                #pragma unroll
                for (int c = 0; c < 4; c++) acc[a][b][c] = 0.f;

        #pragma unroll
        for (int k16 = 0; k16 < 4; k16++) {
            uint32_t a[2][4], b[4];
            #pragma unroll
            for (int t2 = 0; t2 < 2; t2++) {
                int r = wrow + t2 * 16 + ((m & 1) << 3) + rr;
                int c = k16 * 2 + (m >> 1);
                ldsm4(sb + ESA_G + r * 128 + ((c ^ (r & 7)) << 4), a[t2]);
            }
            {
                int n = ((m >> 1) << 3) + rr;
                int c = k16 * 2 + (m & 1);
                ldsm4(sb + ESA_W3 + n * 128 + ((c ^ (n & 7)) << 4), b);
            }
            #pragma unroll
            for (int t2 = 0; t2 < 2; t2++) {
                mma16816(acc[t2][0], a[t2], &b[0]);
                mma16816(acc[t2][1], a[t2], &b[2]);
            }
        }
        #pragma unroll
        for (int t2 = 0; t2 < 2; t2++) {
            int r0 = wrow + t2 * 16 + (lane >> 2);
            long eg = (long)bt * EDGES + e0 + r0;
            #pragma unroll
            for (int nt = 0; nt < 2; nt++) {
                int col = nt * 8 + 2 * (lane & 3);
                if (col < EC) {
                    float bb0 = __ldg(&bi[col]), bb1 = __ldg(&bi[col + 1]);
                    float s00 = 1.f / (1.f + __expf(-(acc[t2][nt][0] + bb0)));
                    float s01 = 1.f / (1.f + __expf(-(acc[t2][nt][1] + bb1)));
                    float s10 = 1.f / (1.f + __expf(-(acc[t2][nt][2] + bb0)));
                    float s11 = 1.f / (1.f + __expf(-(acc[t2][nt][3] + bb1)));
                    *(float2*)(out + eg * EC + col) = make_float2(s00, s01);
                    *(float2*)(out + (eg + 8) * EC + col) = make_float2(s10, s11);
                }
            }
        }
    }
}

// ---------------- launch ----------------------------------------------------
extern "C" void kernel_launch(void* const* d_in, const int* in_sizes, int n_in,
                              void* d_out, int out_size)
{
    const float* roi    = (const float*)d_in[0];
    const float* bboxes = (const float*)d_in[1];
    const float* dirs   = (const float*)d_in[2];
    const float* prio   = (const float*)d_in[3];
    const int*   eidx   = (const int*)  d_in[4];
    const float* np_w1  = (const float*)d_in[5];
    const float* np_b1  = (const float*)d_in[6];
    const float* bn1_g  = (const float*)d_in[7];
    const float* bn1_b  = (const float*)d_in[8];
    const float* bn1_rm = (const float*)d_in[9];
    const float* bn1_rv = (const float*)d_in[10];
    const float* np_w2  = (const float*)d_in[11];
    const float* np_b2  = (const float*)d_in[12];
    const float* bn2_g  = (const float*)d_in[13];
    const float* bn2_b  = (const float*)d_in[14];
    const float* bn2_rm = (const float*)d_in[15];
    const float* bn2_rv = (const float*)d_in[16];
    const float* np_w3  = (const float*)d_in[17];
    const float* np_b3  = (const float*)d_in[18];
    const float* ni_w   = (const float*)d_in[19];
    const float* ni_b   = (const float*)d_in[20];
    const float* ep_w1  = (const float*)d_in[21];
    const float* ep_b1  = (const float*)d_in[22];
    const float* ep_w2  = (const float*)d_in[23];
    const float* ep_b2  = (const float*)d_in[24];
    const float* ei_w   = (const float*)d_in[25];
    const float* ei_b   = (const float*)d_in[26];

    float* out = (float*)d_out;

    __nv_bfloat16 *xhi, *xlo, *h1hi, *h1lo, *h2hi, *h2lo;
    __nv_bfloat16 *w1hi, *w1lo, *w2hi, *w2lo, *w3hi, *w3lo;
    __nv_bfloat16 *ew1t, *ew2t, *ew3t;
    cudaGetSymbolAddress((void**)&xhi, g_xhi);
    cudaGetSymbolAddress((void**)&xlo, g_xlo);
    cudaGetSymbolAddress((void**)&h1hi, g_h1hi);
    cudaGetSymbolAddress((void**)&h1lo, g_h1lo);
    cudaGetSymbolAddress((void**)&h2hi, g_h2hi);
    cudaGetSymbolAddress((void**)&h2lo, g_h2lo);
    cudaGetSymbolAddress((void**)&w1hi, g_w1hi);
    cudaGetSymbolAddress((void**)&w1lo, g_w1lo);
    cudaGetSymbolAddress((void**)&w2hi, g_w2hi);
    cudaGetSymbolAddress((void**)&w2lo, g_w2lo);
    cudaGetSymbolAddress((void**)&w3hi, g_w3hi);
    cudaGetSymbolAddress((void**)&w3lo, g_w3lo);
    cudaGetSymbolAddress((void**)&ew1t, g_ew1t);
    cudaGetSymbolAddress((void**)&ew2t, g_ew2t);
    cudaGetSymbolAddress((void**)&ew3t, g_ew3t);

    cudaFuncSetAttribute(edge_mma_kernel,
                         cudaFuncAttributeMaxDynamicSharedMemorySize, EDGE_SMEM);
    cudaFuncSetAttribute(gemm_mma2<FDIM, H1, 1, 1>,
                         cudaFuncAttributeMaxDynamicSharedMemorySize, GEMM_SMEM);
    cudaFuncSetAttribute(gemm_mma2<H1, H2, 1, 1>,
                         cudaFuncAttributeMaxDynamicSharedMemorySize, GEMM_SMEM);
    cudaFuncSetAttribute(gemm_mma2<H2, H3, 0, 2>,
                         cudaFuncAttributeMaxDynamicSharedMemorySize, GEMM_SMEM);

    // one-time stream/event setup (host-side resources; no device memory)
    static cudaStream_t s_edge = nullptr;
    static cudaEvent_t  ev_fork = nullptr, ev_w = nullptr, ev_join = nullptr;
    if (s_edge == nullptr) {
        cudaStreamCreateWithFlags(&s_edge, cudaStreamNonBlocking);
        cudaEventCreateWithFlags(&ev_fork, cudaEventDisableTiming);
        cudaEventCreateWithFlags(&ev_w, cudaEventDisableTiming);
        cudaEventCreateWithFlags(&ev_join, cudaEventDisableTiming);
    }

    // ---- fork immediately; side stream does weight prep + edge branch ----
    cudaEventRecord(ev_fork, 0);
    cudaStreamWaitEvent(s_edge, ev_fork, 0);

    // main stream: roi split (critical path for GEMM1's A operand)
    split_f32<<<NROWS * FDIM / 4 / 256, 256>>>((const float4*)roi,
                                               (uint2*)xhi, (uint2*)xlo);

    // side stream: node-weight transposes (overlap with split), then edges
    {
        dim3 b(32, 8);
        transpose_split<<<dim3(H1 / 32, FDIM / 32), b, 0, s_edge>>>(np_w1, w1hi, w1lo, FDIM, H1);
        transpose_split<<<dim3(H2 / 32, H1 / 32), b, 0, s_edge>>>(np_w2, w2hi, w2lo, H1, H2);
        transpose_split<<<dim3(H3 / 32, H2 / 32), b, 0, s_edge>>>(np_w3, w3hi, w3lo, H2, H3);
    }
    cudaEventRecord(ev_w, s_edge);
    prep_edge_weights<<<8, 256, 0, s_edge>>>(ep_w1, ep_w2, ei_w, ew1t, ew2t, ew3t);
    edge_mma_kernel<<<NEDGE / 256, 256, EDGE_SMEM, s_edge>>>(
        bboxes, dirs, prio, eidx, ew1t, ew2t, ew3t,
        ep_b1, ep_b2, ei_b, out + NODE_OUT_ELEMS);
    cudaEventRecord(ev_join, s_edge);

    // main stream: node GEMM chain (needs transposed weights)
    cudaStreamWaitEvent(0, ev_w, 0);
    gemm_mma2<FDIM, H1, 1, 1><<<dim3(H1 / 128, NROWS / 128), 256, GEMM_SMEM>>>(
        xhi, xlo, w1hi, w1lo,
        np_b1, bn1_g, bn1_b, bn1_rm, bn1_rv, nullptr, nullptr, nullptr, h1hi, h1lo);
    gemm_mma2<H1, H2, 1, 1><<<dim3(H2 / 128, NROWS / 128), 256, GEMM_SMEM>>>(
        h1hi, h1lo, w2hi, w2lo,
        np_b2, bn2_g, bn2_b, bn2_rm, bn2_rv, nullptr, nullptr, nullptr, h2hi, h2lo);
    gemm_mma2<H2, H3, 0, 2><<<dim3(H3 / 128, NROWS / 128), 256, GEMM_SMEM>>>(
        h2hi, h2lo, w3hi, w3lo,
        np_b3, nullptr, nullptr, nullptr, nullptr, ni_w, ni_b, out, nullptr, nullptr);

    // join
    cudaStreamWaitEvent(0, ev_join, 0);
}

// round 9
// speedup vs baseline: 6.0558x; 1.5312x over previous
#include <cuda_runtime.h>
#include <cuda_bf16.h>
#include <cstdint>

// ---------------- problem constants (fixed by setup_inputs) ----------------
#define BATCH   32
#define NNODE   512
#define NROWS   (BATCH*NNODE)      // 16384
#define FDIM    1024
#define H1      512
#define H2      256
#define H3      128
#define NC      8
#define EDGES   32768              // per batch
#define NEDGE   (BATCH*EDGES)      // 1048576
#define EH      64
#define EC      10
#define CATTR   9
#define NODE_OUT_ELEMS (NROWS*NC)  // 131072

// ---------------- scratch (device globals; no allocation allowed) ----------
__device__ __nv_bfloat16 g_x[NROWS * FDIM];     // bf16 roi
__device__ __nv_bfloat16 g_h1[NROWS * H1];
__device__ __nv_bfloat16 g_h2[NROWS * H2];
__device__ __nv_bfloat16 g_w1t[H1 * FDIM];
__device__ __nv_bfloat16 g_w2t[H2 * H1];
__device__ __nv_bfloat16 g_w3t[H3 * H2];
__device__ __nv_bfloat16 g_ew1t[64 * 32];
__device__ __nv_bfloat16 g_ew2t[64 * 64];
__device__ __nv_bfloat16 g_ew3t[16 * 64];

// ---------------- helpers ----------------------------------------------------
__device__ __forceinline__ uint32_t smem_u32(const void* p) {
    uint32_t a;
    asm("{ .reg .u64 t; cvta.to.shared.u64 t, %1; cvt.u32.u64 %0, t; }"
        : "=r"(a) : "l"(p));
    return a;
}
__device__ __forceinline__ void ldsm4(uint32_t addr, uint32_t* r) {
    asm volatile("ldmatrix.sync.aligned.m8n8.x4.shared.b16 {%0,%1,%2,%3}, [%4];"
                 : "=r"(r[0]), "=r"(r[1]), "=r"(r[2]), "=r"(r[3]) : "r"(addr));
}
__device__ __forceinline__ void mma16816(float* c, const uint32_t* a, const uint32_t* b) {
    asm volatile(
        "mma.sync.aligned.m16n8k16.row.col.f32.bf16.bf16.f32 "
        "{%0,%1,%2,%3}, {%4,%5,%6,%7}, {%8,%9}, {%0,%1,%2,%3};"
        : "+f"(c[0]), "+f"(c[1]), "+f"(c[2]), "+f"(c[3])
        : "r"(a[0]), "r"(a[1]), "r"(a[2]), "r"(a[3]), "r"(b[0]), "r"(b[1]));
}
__device__ __forceinline__ void sts128(uint32_t addr, uint4 v) {
    asm volatile("st.shared.v4.b32 [%0], {%1,%2,%3,%4};"
                 :: "r"(addr), "r"(v.x), "r"(v.y), "r"(v.z), "r"(v.w) : "memory");
}
__device__ __forceinline__ void sts32(uint32_t addr, uint32_t v) {
    asm volatile("st.shared.b32 [%0], %1;" :: "r"(addr), "r"(v) : "memory");
}
__device__ __forceinline__ uint32_t pack_bf2(float a, float b) {
    __nv_bfloat162 h = __floats2bfloat162_rn(a, b);
    uint32_t u; memcpy(&u, &h, 4); return u;
}
__device__ __forceinline__ void cp16(uint32_t dst, const void* src) {
    asm volatile("cp.async.cg.shared.global [%0], [%1], 16;"
                 :: "r"(dst), "l"(src) : "memory");
}
__device__ __forceinline__ void cp_commit() {
    asm volatile("cp.async.commit_group;" ::: "memory");
}
#define CP_WAIT(n) asm volatile("cp.async.wait_group %0;" :: "n"(n) : "memory")

// ---------------- single-pass bf16 mma GEMM, cp.async 3-stage pipeline ------
// C = relu((A@B^T + bias)[bn-fold]); A,B bf16 (row-major K).
// CTA tile 128x128, 8 warps (32x64 warp tiles), K-chunk 32, 3 stages.
// OMODE: 0 = fp32 out, 1 = bf16 out,
//        2 = fused node head: relu tile -> SMEM -> sigmoid(h3@ni_w+ni_b)
static constexpr int STAGE_BYTES = 16384;   // A|B x 8KB
static constexpr int GEMM_SMEM = 3 * STAGE_BYTES;       // 48KB (pipeline)
static constexpr int GEMM3_SMEM = 128 * 132 * 4;        // 67584 (head tile)

template<int K, int N, int EPI, int OMODE>
__global__ __launch_bounds__(256)
void gemm_mma2(const __nv_bfloat16* __restrict__ A,
               const __nv_bfloat16* __restrict__ B,
               const float* __restrict__ bias,
               const float* __restrict__ bng, const float* __restrict__ bnb,
               const float* __restrict__ bnrm, const float* __restrict__ bnrv,
               const float* __restrict__ hw,  const float* __restrict__ hb,
               float* __restrict__ Cf,
               __nv_bfloat16* __restrict__ Cb)
{
    extern __shared__ char sm_raw[];
    const uint32_t sb = smem_u32(sm_raw);
    const int tid = threadIdx.x;
    const int lane = tid & 31, w = tid >> 5;
    const int bn = blockIdx.x, bm = blockIdx.y;
    const int wr = (w & 3) * 32;
    const int wc = (w >> 2) * 64;

    // ---- per-thread async-copy slots: 4 x 16B per stage ----
    const __nv_bfloat16* srcs[4];
    uint32_t dsts[4];
    #pragma unroll
    for (int i = 0; i < 4; i++) {
        int idx = i * 256 + tid;          // 0..1023
        int slab = idx >> 9;              // 0:A 1:B
        int within = idx & 511;
        int r = within >> 2, c = within & 3;
        const __nv_bfloat16* base = (slab == 0) ? A : B;
        int row0 = (slab == 0) ? bm * 128 : bn * 128;
        srcs[i] = base + (size_t)(row0 + r) * K + c * 8;
        dsts[i] = slab * 8192 + r * 64 + ((c ^ ((r >> 1) & 3)) << 4);
    }
    auto ISSUE = [&](int ck) {
        const uint32_t st = sb + (ck % 3) * STAGE_BYTES;
        #pragma unroll
        for (int i = 0; i < 4; i++)
            cp16(st + dsts[i], srcs[i] + ck * 32);
    };

    float acc[2][8][4];
    #pragma unroll
    for (int a = 0; a < 2; a++)
        #pragma unroll
        for (int b = 0; b < 8; b++)
            #pragma unroll
            for (int c = 0; c < 4; c++) acc[a][b][c] = 0.f;

    const int m = lane >> 3, rr = lane & 7;

    auto COMPUTE = [&](int stage) {
        const uint32_t aB = sb + stage * STAGE_BYTES;
        const uint32_t bB = aB + 8192;
        #pragma unroll
        for (int ks = 0; ks < 2; ks++) {
            const int ckb = ks * 2;
            uint32_t ah[2][4], bh[4][4];
            #pragma unroll
            for (int t2 = 0; t2 < 2; t2++) {
                const int r_l = wr + t2 * 16 + ((m & 1) << 3) + rr;
                const int c_l = ckb + (m >> 1);
                const uint32_t off = r_l * 64 + ((c_l ^ ((r_l >> 1) & 3)) << 4);
                ldsm4(aB + off, ah[t2]);
            }
            #pragma unroll
            for (int p = 0; p < 4; p++) {
                const int n_l = wc + p * 16 + ((m >> 1) << 3) + rr;
                const int c_l = ckb + (m & 1);
                const uint32_t off = n_l * 64 + ((c_l ^ ((n_l >> 1) & 3)) << 4);
                ldsm4(bB + off, bh[p]);
            }
            #pragma unroll
            for (int t2 = 0; t2 < 2; t2++)
                #pragma unroll
                for (int nt = 0; nt < 8; nt++)
                    mma16816(acc[t2][nt], ah[t2], &bh[nt >> 1][(nt & 1) * 2]);
        }
    };

    constexpr int NCH = K / 32;
    ISSUE(0); cp_commit();
    ISSUE(1); cp_commit();
    for (int c = 0; c < NCH; c++) {
        CP_WAIT(1);
        __syncthreads();
        if (c + 2 < NCH) ISSUE(c + 2);
        cp_commit();
        COMPUTE(c % 3);
    }

    float* sh3 = (float*)sm_raw;
    if (OMODE == 2) __syncthreads();

    #pragma unroll
    for (int t2 = 0; t2 < 2; t2++) {
        const int rloc = wr + t2 * 16 + (lane >> 2);
        const int row0 = bm * 128 + rloc;
        #pragma unroll
        for (int nt = 0; nt < 8; nt++) {
            const int cloc = wc + nt * 8 + 2 * (lane & 3);
            const int col = bn * 128 + cloc;
            float b0 = __ldg(&bias[col]), b1 = __ldg(&bias[col + 1]);
            float s0 = 1.f, s1 = 1.f, f0 = 0.f, f1 = 0.f;
            if (EPI) {
                s0 = __ldg(&bng[col]) * rsqrtf(__ldg(&bnrv[col]) + 1e-5f);
                f0 = __ldg(&bnb[col]) - __ldg(&bnrm[col]) * s0;
                s1 = __ldg(&bng[col + 1]) * rsqrtf(__ldg(&bnrv[col + 1]) + 1e-5f);
                f1 = __ldg(&bnb[col + 1]) - __ldg(&bnrm[col + 1]) * s1;
            }
            float v00 = acc[t2][nt][0] + b0, v01 = acc[t2][nt][1] + b1;
            float v10 = acc[t2][nt][2] + b0, v11 = acc[t2][nt][3] + b1;
            if (EPI) {
                v00 = v00 * s0 + f0; v01 = v01 * s1 + f1;
                v10 = v10 * s0 + f0; v11 = v11 * s1 + f1;
            }
            v00 = fmaxf(v00, 0.f); v01 = fmaxf(v01, 0.f);
            v10 = fmaxf(v10, 0.f); v11 = fmaxf(v11, 0.f);
            if (OMODE == 1) {
                __nv_bfloat162 h0 = __floats2bfloat162_rn(v00, v01);
                __nv_bfloat162 h1 = __floats2bfloat162_rn(v10, v11);
                *(__nv_bfloat162*)(Cb + (size_t)row0 * N + col) = h0;
                *(__nv_bfloat162*)(Cb + (size_t)(row0 + 8) * N + col) = h1;
            } else if (OMODE == 2) {
                sh3[rloc * 132 + cloc]       = v00;
                sh3[rloc * 132 + cloc + 1]   = v01;
                sh3[(rloc + 8) * 132 + cloc]     = v10;
                sh3[(rloc + 8) * 132 + cloc + 1] = v11;
            } else {
                *(float2*)(Cf + (size_t)row0 * N + col) = make_float2(v00, v01);
                *(float2*)(Cf + (size_t)(row0 + 8) * N + col) = make_float2(v10, v11);
            }
        }
    }

    if (OMODE == 2) {
        __syncthreads();
        const int base = tid * 4;
        #pragma unroll
        for (int i = 0; i < 4; i++) {
            const int idx = base + i;
            const int row = idx >> 3;
            const int j = idx & 7;
            const float* xr = &sh3[row * 132];
            float a = __ldg(&hb[j]);
            #pragma unroll 8
            for (int k = 0; k < H3; k++)
                a += xr[k] * __ldg(&hw[k * NC + j]);
            Cf[(size_t)(bm * 128 + row) * NC + j] = 1.f / (1.f + __expf(-a));
        }
    }
}

// ---------------- fp32 -> bf16 convert (for roi) ----------------------------
__global__ __launch_bounds__(256)
void convert_f32(const float4* __restrict__ in, uint2* __restrict__ ob)
{
    int i = blockIdx.x * 256 + threadIdx.x;
    float4 v = in[i];
    __nv_bfloat162 h0 = __floats2bfloat162_rn(v.x, v.y);
    __nv_bfloat162 h1 = __floats2bfloat162_rn(v.z, v.w);
    uint2 u;
    memcpy(&u.x, &h0, 4); memcpy(&u.y, &h1, 4);
    ob[i] = u;
}

// ------- weight transpose to bf16: in (R x C) -> out (C x R) ----------------
__global__ void transpose_bf16(const float* __restrict__ in,
                               __nv_bfloat16* __restrict__ ob,
                               int R, int C)
{
    __shared__ float t[32][33];
    int x = blockIdx.x * 32 + threadIdx.x;
    int y = blockIdx.y * 32 + threadIdx.y;
    #pragma unroll
    for (int i = 0; i < 32; i += 8)
        t[threadIdx.y + i][threadIdx.x] = in[(size_t)(y + i) * C + x];
    __syncthreads();
    x = blockIdx.y * 32 + threadIdx.x;
    y = blockIdx.x * 32 + threadIdx.y;
    #pragma unroll
    for (int i = 0; i < 32; i += 8)
        ob[(size_t)(y + i) * R + x] = __float2bfloat16(t[threadIdx.x][threadIdx.y + i]);
}

// ---------------- edge weight prep: transpose+pad to bf16 -------------------
__global__ void prep_edge_weights(const float* __restrict__ w1,
                                  const float* __restrict__ w2,
                                  const float* __restrict__ wi,
                                  __nv_bfloat16* __restrict__ o1,
                                  __nv_bfloat16* __restrict__ o2,
                                  __nv_bfloat16* __restrict__ o3)
{
    int t = blockIdx.x * 256 + threadIdx.x;
    int stride = gridDim.x * 256;
    for (int i = t; i < 64 * 32; i += stride) {
        int n = i >> 5, k = i & 31;
        o1[i] = (k < 18) ? __float2bfloat16(w1[k * 64 + n]) : __nv_bfloat16(0.f);
    }
    for (int i = t; i < 64 * 64; i += stride) {
        int n = i >> 6, k = i & 63;
        o2[i] = __float2bfloat16(w2[k * 64 + n]);
    }
    for (int i = t; i < 16 * 64; i += stride) {
        int n = i >> 6, k = i & 63;
        o3[i] = (n < EC) ? __float2bfloat16(wi[k * EC + n]) : __nv_bfloat16(0.f);
    }
}

// ---------------- edge MLP on tensor cores: 256 edges / 8 warps per CTA -----
static constexpr int ESA_ATTR = 0;            // 512*10*2  = 10240
static constexpr int ESA_W1   = 10240;
static constexpr int ESA_W2   = 14336;
static constexpr int ESA_W3   = 22528;
static constexpr int ESA_A1   = 24576;        // 256*64    = 16384
static constexpr int ESA_H    = 40960;        // 256*128   = 32768
static constexpr int ESA_G    = 73728;        // 256*128   = 32768
static constexpr int EDGE_SMEM = 106496;

__global__ __launch_bounds__(256)
void edge_mma_kernel(const float* __restrict__ bboxes,
                     const float* __restrict__ dirs,
                     const float* __restrict__ prio,
                     const int*   __restrict__ eidx,
                     const __nv_bfloat16* __restrict__ w1t,
                     const __nv_bfloat16* __restrict__ w2t,
                     const __nv_bfloat16* __restrict__ w3t,
                     const float* __restrict__ b1,
                     const float* __restrict__ b2,
                     const float* __restrict__ bi,
                     float* __restrict__ out)
{
    extern __shared__ char sm[];
    const uint32_t sb = smem_u32(sm);
    const int tid = threadIdx.x;
    const int lane = tid & 31, w = tid >> 5;
    const int bt = blockIdx.x >> 7;
    const int e0 = (blockIdx.x & 127) * 256;

    __nv_bfloat16* sAttr = (__nv_bfloat16*)(sm + ESA_ATTR);
    const float inv = 1.f / 1024.f;
    for (int n = tid; n < NNODE; n += 256) {
        int gn = bt * NNODE + n;
        float4 bb = *(const float4*)&bboxes[(size_t)gn * 4];
        float4 dd = *(const float4*)&dirs[(size_t)gn * 4];
        float pr = prio[gn];
        __nv_bfloat16* a = sAttr + n * 10;
        a[0] = __float2bfloat16(bb.x * inv);
        a[1] = __float2bfloat16(bb.y * inv);
        a[2] = __float2bfloat16(bb.z * inv);
        a[3] = __float2bfloat16(bb.w * inv);
        a[4] = __float2bfloat16(dd.x);
        a[5] = __float2bfloat16(dd.y);
        a[6] = __float2bfloat16(dd.z);
        a[7] = __float2bfloat16(dd.w);
        a[8] = __float2bfloat16(pr);
    }
    for (int i = tid; i < 64 * 4; i += 256) {
        int r = i >> 2, c = i & 3;
        uint4 v = ((const uint4*)w1t)[r * 4 + c];
        sts128(sb + ESA_W1 + r * 64 + ((c ^ ((r >> 1) & 3)) << 4), v);
    }
    for (int i = tid; i < 64 * 8; i += 256) {
        int r = i >> 3, c = i & 7;
        uint4 v = ((const uint4*)w2t)[r * 8 + c];
        sts128(sb + ESA_W2 + r * 128 + ((c ^ (r & 7)) << 4), v);
    }
    for (int i = tid; i < 16 * 8; i += 256) {
        int r = i >> 3, c = i & 7;
        uint4 v = ((const uint4*)w3t)[r * 8 + c];
        sts128(sb + ESA_W3 + r * 128 + ((c ^ (r & 7)) << 4), v);
    }
    __syncthreads();

    {
        const int ebase = bt * 2 * EDGES + e0 + tid;
        const int src = eidx[ebase];
        const int dst = eidx[ebase + EDGES];
        const __nv_bfloat16* as = sAttr + src * 10;
        const __nv_bfloat16* ad = sAttr + dst * 10;
        uint16_t v[32];
        #pragma unroll
        for (int c = 0; c < 9; c++) { memcpy(&v[c], &as[c], 2); memcpy(&v[9 + c], &ad[c], 2); }
        #pragma unroll
        for (int c = 18; c < 32; c++) v[c] = 0;
        const int swz = (tid >> 1) & 3;
        #pragma unroll
        for (int ch = 0; ch < 4; ch++) {
            uint4 p;
            p.x = (uint32_t)v[ch*8+0] | ((uint32_t)v[ch*8+1] << 16);
            p.y = (uint32_t)v[ch*8+2] | ((uint32_t)v[ch*8+3] << 16);
            p.z = (uint32_t)v[ch*8+4] | ((uint32_t)v[ch*8+5] << 16);
            p.w = (uint32_t)v[ch*8+6] | ((uint32_t)v[ch*8+7] << 16);
            sts128(sb + ESA_A1 + tid * 64 + ((ch ^ swz) << 4), p);
        }
    }
    __syncthreads();

    const int m = lane >> 3, rr = lane & 7;
    const int wrow = (w >> 2) * 128 + (w & 3) * 32;

    {
        float acc[2][8][4];
        #pragma unroll
        for (int a = 0; a < 2; a++)
            #pragma unroll
            for (int b = 0; b < 8; b++)
                #pragma unroll
                for (int c = 0; c < 4; c++) acc[a][b][c] = 0.f;

        #pragma unroll
        for (int k16 = 0; k16 < 2; k16++) {
            uint32_t a[2][4], b[4][4];
            #pragma unroll
            for (int t2 = 0; t2 < 2; t2++) {
                int r = wrow + t2 * 16 + ((m & 1) << 3) + rr;
                int c = k16 * 2 + (m >> 1);
                ldsm4(sb + ESA_A1 + r * 64 + ((c ^ ((r >> 1) & 3)) << 4), a[t2]);
            }
            #pragma unroll
            for (int p = 0; p < 4; p++) {
                int n = p * 16 + ((m >> 1) << 3) + rr;
                int c = k16 * 2 + (m & 1);
                ldsm4(sb + ESA_W1 + n * 64 + ((c ^ ((n >> 1) & 3)) << 4), b[p]);
            }
            #pragma unroll
            for (int t2 = 0; t2 < 2; t2++)
                #pragma unroll
                for (int nt = 0; nt < 8; nt++)
                    mma16816(acc[t2][nt], a[t2], &b[nt >> 1][(nt & 1) * 2]);
        }
        #pragma unroll
        for (int t2 = 0; t2 < 2; t2++) {
            int r0 = wrow + t2 * 16 + (lane >> 2);
            #pragma unroll
            for (int nt = 0; nt < 8; nt++) {
                int col = nt * 8 + 2 * (lane & 3);
                float bb0 = __ldg(&b1[col]), bb1 = __ldg(&b1[col + 1]);
                float v00 = fmaxf(acc[t2][nt][0] + bb0, 0.f);
                float v01 = fmaxf(acc[t2][nt][1] + bb1, 0.f);
                float v10 = fmaxf(acc[t2][nt][2] + bb0, 0.f);
                float v11 = fmaxf(acc[t2][nt][3] + bb1, 0.f);
                uint32_t inb = (col & 7) * 2;
                sts32(sb + ESA_H + r0 * 128 + (((nt) ^ (r0 & 7)) << 4) + inb,
                      pack_bf2(v00, v01));
                int r1 = r0 + 8;
                sts32(sb + ESA_H + r1 * 128 + (((nt) ^ (r1 & 7)) << 4) + inb,
                      pack_bf2(v10, v11));
            }
        }
    }
    __syncwarp();

    {
        float acc[2][8][4];
        #pragma unroll
        for (int a = 0; a < 2; a++)
            #pragma unroll
            for (int b = 0; b < 8; b++)
                #pragma unroll
                for (int c = 0; c < 4; c++) acc[a][b][c] = 0.f;

        #pragma unroll
        for (int k16 = 0; k16 < 4; k16++) {
            uint32_t a[2][4], b[4][4];
            #pragma unroll
            for (int t2 = 0; t2 < 2; t2++) {
                int r = wrow + t2 * 16 + ((m & 1) << 3) + rr;
                int c = k16 * 2 + (m >> 1);
                ldsm4(sb + ESA_H + r * 128 + ((c ^ (r & 7)) << 4), a[t2]);
            }
            #pragma unroll
            for (int p = 0; p < 4; p++) {
                int n = p * 16 + ((m >> 1) << 3) + rr;
                int c = k16 * 2 + (m & 1);
                ldsm4(sb + ESA_W2 + n * 128 + ((c ^ (n & 7)) << 4), b[p]);
            }
            #pragma unroll
            for (int t2 = 0; t2 < 2; t2++)
                #pragma unroll
                for (int nt = 0; nt < 8; nt++)
                    mma16816(acc[t2][nt], a[t2], &b[nt >> 1][(nt & 1) * 2]);
        }
        #pragma unroll
        for (int t2 = 0; t2 < 2; t2++) {
            int r0 = wrow + t2 * 16 + (lane >> 2);
            #pragma unroll
            for (int nt = 0; nt < 8; nt++) {
                int col = nt * 8 + 2 * (lane & 3);
                float bb0 = __ldg(&b2[col]), bb1 = __ldg(&b2[col + 1]);
                float v00 = fmaxf(acc[t2][nt][0] + bb0, 0.f);
                float v01 = fmaxf(acc[t2][nt][1] + bb1, 0.f);
                float v10 = fmaxf(acc[t2][nt][2] + bb0, 0.f);
                float v11 = fmaxf(acc[t2][nt][3] + bb1, 0.f);
                uint32_t inb = (col & 7) * 2;
                sts32(sb + ESA_G + r0 * 128 + (((nt) ^ (r0 & 7)) << 4) + inb,
                      pack_bf2(v00, v01));
                int r1 = r0 + 8;
                sts32(sb + ESA_G + r1 * 128 + (((nt) ^ (r1 & 7)) << 4) + inb,
                      pack_bf2(v10, v11));
            }
        }
    }
    __syncwarp();

    {
        float acc[2][2][4];
        #pragma unroll
        for (int a = 0; a < 2; a++)
            #pragma unroll
            for (int b = 0; b < 2; b++)
                #pragma unroll
                for (int c = 0; c < 4; c++) acc[a][b][c] = 0.f;

        #pragma unroll
        for (int k16 = 0; k16 < 4; k16++) {
            uint32_t a[2][4], b[4];
            #pragma unroll
            for (int t2 = 0; t2 < 2; t2++) {
                int r = wrow + t2 * 16 + ((m & 1) << 3) + rr;
                int c = k16 * 2 + (m >> 1);
                ldsm4(sb + ESA_G + r * 128 + ((c ^ (r & 7)) << 4), a[t2]);
            }
            {
                int n = ((m >> 1) << 3) + rr;
                int c = k16 * 2 + (m & 1);
                ldsm4(sb + ESA_W3 + n * 128 + ((c ^ (n & 7)) << 4), b);
            }
            #pragma unroll
            for (int t2 = 0; t2 < 2; t2++) {
                mma16816(acc[t2][0], a[t2], &b[0]);
                mma16816(acc[t2][1], a[t2], &b[2]);
            }
        }
        #pragma unroll
        for (int t2 = 0; t2 < 2; t2++) {
            int r0 = wrow + t2 * 16 + (lane >> 2);
            long eg = (long)bt * EDGES + e0 + r0;
            #pragma unroll
            for (int nt = 0; nt < 2; nt++) {
                int col = nt * 8 + 2 * (lane & 3);
                if (col < EC) {
                    float bb0 = __ldg(&bi[col]), bb1 = __ldg(&bi[col + 1]);
                    float s00 = 1.f / (1.f + __expf(-(acc[t2][nt][0] + bb0)));
                    float s01 = 1.f / (1.f + __expf(-(acc[t2][nt][1] + bb1)));
                    float s10 = 1.f / (1.f + __expf(-(acc[t2][nt][2] + bb0)));
                    float s11 = 1.f / (1.f + __expf(-(acc[t2][nt][3] + bb1)));
                    *(float2*)(out + eg * EC + col) = make_float2(s00, s01);
                    *(float2*)(out + (eg + 8) * EC + col) = make_float2(s10, s11);
                }
            }
        }
    }
}

// ---------------- launch ----------------------------------------------------
extern "C" void kernel_launch(void* const* d_in, const int* in_sizes, int n_in,
                              void* d_out, int out_size)
{
    const float* roi    = (const float*)d_in[0];
    const float* bboxes = (const float*)d_in[1];
    const float* dirs   = (const float*)d_in[2];
    const float* prio   = (const float*)d_in[3];
    const int*   eidx   = (const int*)  d_in[4];
    const float* np_w1  = (const float*)d_in[5];
    const float* np_b1  = (const float*)d_in[6];
    const float* bn1_g  = (const float*)d_in[7];
    const float* bn1_b  = (const float*)d_in[8];
    const float* bn1_rm = (const float*)d_in[9];
    const float* bn1_rv = (const float*)d_in[10];
    const float* np_w2  = (const float*)d_in[11];
    const float* np_b2  = (const float*)d_in[12];
    const float* bn2_g  = (const float*)d_in[13];
    const float* bn2_b  = (const float*)d_in[14];
    const float* bn2_rm = (const float*)d_in[15];
    const float* bn2_rv = (const float*)d_in[16];
    const float* np_w3  = (const float*)d_in[17];
    const float* np_b3  = (const float*)d_in[18];
    const float* ni_w   = (const float*)d_in[19];
    const float* ni_b   = (const float*)d_in[20];
    const float* ep_w1  = (const float*)d_in[21];
    const float* ep_b1  = (const float*)d_in[22];
    const float* ep_w2  = (const float*)d_in[23];
    const float* ep_b2  = (const float*)d_in[24];
    const float* ei_w   = (const float*)d_in[25];
    const float* ei_b   = (const float*)d_in[26];

    float* out = (float*)d_out;

    __nv_bfloat16 *x, *h1, *h2, *w1t, *w2t, *w3t, *ew1t, *ew2t, *ew3t;
    cudaGetSymbolAddress((void**)&x, g_x);
    cudaGetSymbolAddress((void**)&h1, g_h1);
    cudaGetSymbolAddress((void**)&h2, g_h2);
    cudaGetSymbolAddress((void**)&w1t, g_w1t);
    cudaGetSymbolAddress((void**)&w2t, g_w2t);
    cudaGetSymbolAddress((void**)&w3t, g_w3t);
    cudaGetSymbolAddress((void**)&ew1t, g_ew1t);
    cudaGetSymbolAddress((void**)&ew2t, g_ew2t);
    cudaGetSymbolAddress((void**)&ew3t, g_ew3t);

    cudaFuncSetAttribute(edge_mma_kernel,
                         cudaFuncAttributeMaxDynamicSharedMemorySize, EDGE_SMEM);
    cudaFuncSetAttribute(gemm_mma2<FDIM, H1, 1, 1>,
                         cudaFuncAttributeMaxDynamicSharedMemorySize, GEMM_SMEM);
    cudaFuncSetAttribute(gemm_mma2<H1, H2, 1, 1>,
                         cudaFuncAttributeMaxDynamicSharedMemorySize, GEMM_SMEM);
    cudaFuncSetAttribute(gemm_mma2<H2, H3, 0, 2>,
                         cudaFuncAttributeMaxDynamicSharedMemorySize, GEMM3_SMEM);

    // one-time stream/event setup (host-side resources; no device memory)
    static cudaStream_t s_edge = nullptr;
    static cudaEvent_t  ev_fork = nullptr, ev_w = nullptr, ev_join = nullptr;
    if (s_edge == nullptr) {
        cudaStreamCreateWithFlags(&s_edge, cudaStreamNonBlocking);
        cudaEventCreateWithFlags(&ev_fork, cudaEventDisableTiming);
        cudaEventCreateWithFlags(&ev_w, cudaEventDisableTiming);
        cudaEventCreateWithFlags(&ev_join, cudaEventDisableTiming);
    }

    // ---- fork immediately; side stream does weight prep + edge branch ----
    cudaEventRecord(ev_fork, 0);
    cudaStreamWaitEvent(s_edge, ev_fork, 0);

    // main stream: roi convert (critical path for GEMM1's A operand)
    convert_f32<<<NROWS * FDIM / 4 / 256, 256>>>((const float4*)roi, (uint2*)x);

    // side stream: node-weight transposes (overlap with convert), then edges
    {
        dim3 b(32, 8);
        transpose_bf16<<<dim3(H1 / 32, FDIM / 32), b, 0, s_edge>>>(np_w1, w1t, FDIM, H1);
        transpose_bf16<<<dim3(H2 / 32, H1 / 32), b, 0, s_edge>>>(np_w2, w2t, H1, H2);
        transpose_bf16<<<dim3(H3 / 32, H2 / 32), b, 0, s_edge>>>(np_w3, w3t, H2, H3);
    }
    cudaEventRecord(ev_w, s_edge);
    prep_edge_weights<<<8, 256, 0, s_edge>>>(ep_w1, ep_w2, ei_w, ew1t, ew2t, ew3t);
    edge_mma_kernel<<<NEDGE / 256, 256, EDGE_SMEM, s_edge>>>(
        bboxes, dirs, prio, eidx, ew1t, ew2t, ew3t,
        ep_b1, ep_b2, ei_b, out + NODE_OUT_ELEMS);
    cudaEventRecord(ev_join, s_edge);

    // main stream: node GEMM chain (needs transposed weights)
    cudaStreamWaitEvent(0, ev_w, 0);
    gemm_mma2<FDIM, H1, 1, 1><<<dim3(H1 / 128, NROWS / 128), 256, GEMM_SMEM>>>(
        x, w1t, np_b1, bn1_g, bn1_b, bn1_rm, bn1_rv,
        nullptr, nullptr, nullptr, h1);
    gemm_mma2<H1, H2, 1, 1><<<dim3(H2 / 128, NROWS / 128), 256, GEMM_SMEM>>>(
        h1, w2t, np_b2, bn2_g, bn2_b, bn2_rm, bn2_rv,
        nullptr, nullptr, nullptr, h2);
    gemm_mma2<H2, H3, 0, 2><<<dim3(H3 / 128, NROWS / 128), 256, GEMM3_SMEM>>>(
        h2, w3t, np_b3, nullptr, nullptr, nullptr, nullptr,
        ni_w, ni_b, out, nullptr);

    // join
    cudaStreamWaitEvent(0, ev_join, 0);
}

// round 10
// speedup vs baseline: 6.9193x; 1.1426x over previous
#include <cuda_runtime.h>
#include <cuda_bf16.h>
#include <cstdint>

// ---------------- problem constants (fixed by setup_inputs) ----------------
#define BATCH   32
#define NNODE   512
#define NROWS   (BATCH*NNODE)      // 16384
#define FDIM    1024
#define H1      512
#define H2      256
#define H3      128
#define NC      8
#define EDGES   32768              // per batch
#define NEDGE   (BATCH*EDGES)      // 1048576
#define EH      64
#define EC      10
#define CATTR   9
#define NODE_OUT_ELEMS (NROWS*NC)  // 131072

// ---------------- scratch (device globals; no allocation allowed) ----------
__device__ __nv_bfloat16 g_x[NROWS * FDIM];     // bf16 roi
__device__ __nv_bfloat16 g_h1[NROWS * H1];
__device__ __nv_bfloat16 g_h2[NROWS * H2];
__device__ __nv_bfloat16 g_w1t[H1 * FDIM];
__device__ __nv_bfloat16 g_w2t[H2 * H1];
__device__ __nv_bfloat16 g_w3t[H3 * H2];
__device__ __nv_bfloat16 g_ew1t[64 * 32];
__device__ __nv_bfloat16 g_ew2t[64 * 64];
__device__ __nv_bfloat16 g_ew3t[16 * 64];

// ---------------- helpers ----------------------------------------------------
__device__ __forceinline__ uint32_t smem_u32(const void* p) {
    uint32_t a;
    asm("{ .reg .u64 t; cvta.to.shared.u64 t, %1; cvt.u32.u64 %0, t; }"
        : "=r"(a) : "l"(p));
    return a;
}
__device__ __forceinline__ void ldsm4(uint32_t addr, uint32_t* r) {
    asm volatile("ldmatrix.sync.aligned.m8n8.x4.shared.b16 {%0,%1,%2,%3}, [%4];"
                 : "=r"(r[0]), "=r"(r[1]), "=r"(r[2]), "=r"(r[3]) : "r"(addr));
}
__device__ __forceinline__ void mma16816(float* c, const uint32_t* a, const uint32_t* b) {
    asm volatile(
        "mma.sync.aligned.m16n8k16.row.col.f32.bf16.bf16.f32 "
        "{%0,%1,%2,%3}, {%4,%5,%6,%7}, {%8,%9}, {%0,%1,%2,%3};"
        : "+f"(c[0]), "+f"(c[1]), "+f"(c[2]), "+f"(c[3])
        : "r"(a[0]), "r"(a[1]), "r"(a[2]), "r"(a[3]), "r"(b[0]), "r"(b[1]));
}
__device__ __forceinline__ void sts128(uint32_t addr, uint4 v) {
    asm volatile("st.shared.v4.b32 [%0], {%1,%2,%3,%4};"
                 :: "r"(addr), "r"(v.x), "r"(v.y), "r"(v.z), "r"(v.w) : "memory");
}
__device__ __forceinline__ uint32_t pack_bf2(float a, float b) {
    __nv_bfloat162 h = __floats2bfloat162_rn(a, b);
    uint32_t u; memcpy(&u, &h, 4); return u;
}
__device__ __forceinline__ void cp16(uint32_t dst, const void* src) {
    asm volatile("cp.async.cg.shared.global [%0], [%1], 16;"
                 :: "r"(dst), "l"(src) : "memory");
}
__device__ __forceinline__ void cp_commit() {
    asm volatile("cp.async.commit_group;" ::: "memory");
}
#define CP_WAIT(n) asm volatile("cp.async.wait_group %0;" :: "n"(n) : "memory")

// ---------------- single-pass bf16 mma GEMM, cp.async 3-stage pipeline ------
// (verified R9 structure; OMODE==2 fuses the node head)
static constexpr int STAGE_BYTES = 16384;   // A|B x 8KB
static constexpr int GEMM_SMEM = 3 * STAGE_BYTES;       // 48KB (pipeline)
static constexpr int GEMM3_SMEM = 128 * 132 * 4;        // 67584 (head tile)

template<int K, int N, int EPI, int OMODE>
__global__ __launch_bounds__(256)
void gemm_mma2(const __nv_bfloat16* __restrict__ A,
               const __nv_bfloat16* __restrict__ B,
               const float* __restrict__ bias,
               const float* __restrict__ bng, const float* __restrict__ bnb,
               const float* __restrict__ bnrm, const float* __restrict__ bnrv,
               const float* __restrict__ hw,  const float* __restrict__ hb,
               float* __restrict__ Cf,
               __nv_bfloat16* __restrict__ Cb)
{
    extern __shared__ char sm_raw[];
    const uint32_t sb = smem_u32(sm_raw);
    const int tid = threadIdx.x;
    const int lane = tid & 31, w = tid >> 5;
    const int bn = blockIdx.x, bm = blockIdx.y;
    const int wr = (w & 3) * 32;
    const int wc = (w >> 2) * 64;

    const __nv_bfloat16* srcs[4];
    uint32_t dsts[4];
    #pragma unroll
    for (int i = 0; i < 4; i++) {
        int idx = i * 256 + tid;
        int slab = idx >> 9;
        int within = idx & 511;
        int r = within >> 2, c = within & 3;
        const __nv_bfloat16* base = (slab == 0) ? A : B;
        int row0 = (slab == 0) ? bm * 128 : bn * 128;
        srcs[i] = base + (size_t)(row0 + r) * K + c * 8;
        dsts[i] = slab * 8192 + r * 64 + ((c ^ ((r >> 1) & 3)) << 4);
    }
    auto ISSUE = [&](int ck) {
        const uint32_t st = sb + (ck % 3) * STAGE_BYTES;
        #pragma unroll
        for (int i = 0; i < 4; i++)
            cp16(st + dsts[i], srcs[i] + ck * 32);
    };

    float acc[2][8][4];
    #pragma unroll
    for (int a = 0; a < 2; a++)
        #pragma unroll
        for (int b = 0; b < 8; b++)
            #pragma unroll
            for (int c = 0; c < 4; c++) acc[a][b][c] = 0.f;

    const int m = lane >> 3, rr = lane & 7;

    auto COMPUTE = [&](int stage) {
        const uint32_t aB = sb + stage * STAGE_BYTES;
        const uint32_t bB = aB + 8192;
        #pragma unroll
        for (int ks = 0; ks < 2; ks++) {
            const int ckb = ks * 2;
            uint32_t ah[2][4], bh[4][4];
            #pragma unroll
            for (int t2 = 0; t2 < 2; t2++) {
                const int r_l = wr + t2 * 16 + ((m & 1) << 3) + rr;
                const int c_l = ckb + (m >> 1);
                const uint32_t off = r_l * 64 + ((c_l ^ ((r_l >> 1) & 3)) << 4);
                ldsm4(aB + off, ah[t2]);
            }
            #pragma unroll
            for (int p = 0; p < 4; p++) {
                const int n_l = wc + p * 16 + ((m >> 1) << 3) + rr;
                const int c_l = ckb + (m & 1);
                const uint32_t off = n_l * 64 + ((c_l ^ ((n_l >> 1) & 3)) << 4);
                ldsm4(bB + off, bh[p]);
            }
            #pragma unroll
            for (int t2 = 0; t2 < 2; t2++)
                #pragma unroll
                for (int nt = 0; nt < 8; nt++)
                    mma16816(acc[t2][nt], ah[t2], &bh[nt >> 1][(nt & 1) * 2]);
        }
    };

    constexpr int NCH = K / 32;
    ISSUE(0); cp_commit();
    ISSUE(1); cp_commit();
    for (int c = 0; c < NCH; c++) {
        CP_WAIT(1);
        __syncthreads();
        if (c + 2 < NCH) ISSUE(c + 2);
        cp_commit();
        COMPUTE(c % 3);
    }

    float* sh3 = (float*)sm_raw;
    if (OMODE == 2) __syncthreads();

    #pragma unroll
    for (int t2 = 0; t2 < 2; t2++) {
        const int rloc = wr + t2 * 16 + (lane >> 2);
        const int row0 = bm * 128 + rloc;
        #pragma unroll
        for (int nt = 0; nt < 8; nt++) {
            const int cloc = wc + nt * 8 + 2 * (lane & 3);
            const int col = bn * 128 + cloc;
            float b0 = __ldg(&bias[col]), b1 = __ldg(&bias[col + 1]);
            float s0 = 1.f, s1 = 1.f, f0 = 0.f, f1 = 0.f;
            if (EPI) {
                s0 = __ldg(&bng[col]) * rsqrtf(__ldg(&bnrv[col]) + 1e-5f);
                f0 = __ldg(&bnb[col]) - __ldg(&bnrm[col]) * s0;
                s1 = __ldg(&bng[col + 1]) * rsqrtf(__ldg(&bnrv[col + 1]) + 1e-5f);
                f1 = __ldg(&bnb[col + 1]) - __ldg(&bnrm[col + 1]) * s1;
            }
            float v00 = acc[t2][nt][0] + b0, v01 = acc[t2][nt][1] + b1;
            float v10 = acc[t2][nt][2] + b0, v11 = acc[t2][nt][3] + b1;
            if (EPI) {
                v00 = v00 * s0 + f0; v01 = v01 * s1 + f1;
                v10 = v10 * s0 + f0; v11 = v11 * s1 + f1;
            }
            v00 = fmaxf(v00, 0.f); v01 = fmaxf(v01, 0.f);
            v10 = fmaxf(v10, 0.f); v11 = fmaxf(v11, 0.f);
            if (OMODE == 1) {
                __nv_bfloat162 h0 = __floats2bfloat162_rn(v00, v01);
                __nv_bfloat162 h1 = __floats2bfloat162_rn(v10, v11);
                *(__nv_bfloat162*)(Cb + (size_t)row0 * N + col) = h0;
                *(__nv_bfloat162*)(Cb + (size_t)(row0 + 8) * N + col) = h1;
            } else if (OMODE == 2) {
                sh3[rloc * 132 + cloc]       = v00;
                sh3[rloc * 132 + cloc + 1]   = v01;
                sh3[(rloc + 8) * 132 + cloc]     = v10;
                sh3[(rloc + 8) * 132 + cloc + 1] = v11;
            } else {
                *(float2*)(Cf + (size_t)row0 * N + col) = make_float2(v00, v01);
                *(float2*)(Cf + (size_t)(row0 + 8) * N + col) = make_float2(v10, v11);
            }
        }
    }

    if (OMODE == 2) {
        __syncthreads();
        const int base = tid * 4;
        #pragma unroll
        for (int i = 0; i < 4; i++) {
            const int idx = base + i;
            const int row = idx >> 3;
            const int j = idx & 7;
            const float* xr = &sh3[row * 132];
            float a = __ldg(&hb[j]);
            #pragma unroll 8
            for (int k = 0; k < H3; k++)
                a += xr[k] * __ldg(&hw[k * NC + j]);
            Cf[(size_t)(bm * 128 + row) * NC + j] = 1.f / (1.f + __expf(-a));
        }
    }
}

// ---------------- fp32 -> bf16 convert (for roi) ----------------------------
__global__ __launch_bounds__(256)
void convert_f32(const float4* __restrict__ in, uint2* __restrict__ ob)
{
    int i = blockIdx.x * 256 + threadIdx.x;
    float4 v = in[i];
    __nv_bfloat162 h0 = __floats2bfloat162_rn(v.x, v.y);
    __nv_bfloat162 h1 = __floats2bfloat162_rn(v.z, v.w);
    uint2 u;
    memcpy(&u.x, &h0, 4); memcpy(&u.y, &h1, 4);
    ob[i] = u;
}

// ------- weight transpose to bf16: in (R x C) -> out (C x R) ----------------
__global__ void transpose_bf16(const float* __restrict__ in,
                               __nv_bfloat16* __restrict__ ob,
                               int R, int C)
{
    __shared__ float t[32][33];
    int x = blockIdx.x * 32 + threadIdx.x;
    int y = blockIdx.y * 32 + threadIdx.y;
    #pragma unroll
    for (int i = 0; i < 32; i += 8)
        t[threadIdx.y + i][threadIdx.x] = in[(size_t)(y + i) * C + x];
    __syncthreads();
    x = blockIdx.y * 32 + threadIdx.x;
    y = blockIdx.x * 32 + threadIdx.y;
    #pragma unroll
    for (int i = 0; i < 32; i += 8)
        ob[(size_t)(y + i) * R + x] = __float2bfloat16(t[threadIdx.x][threadIdx.y + i]);
}

// ---------------- edge weight prep: transpose+pad to bf16 -------------------
__global__ void prep_edge_weights(const float* __restrict__ w1,
                                  const float* __restrict__ w2,
                                  const float* __restrict__ wi,
                                  __nv_bfloat16* __restrict__ o1,
                                  __nv_bfloat16* __restrict__ o2,
                                  __nv_bfloat16* __restrict__ o3)
{
    int t = blockIdx.x * 256 + threadIdx.x;
    int stride = gridDim.x * 256;
    for (int i = t; i < 64 * 32; i += stride) {
        int n = i >> 5, k = i & 31;
        o1[i] = (k < 18) ? __float2bfloat16(w1[k * 64 + n]) : __nv_bfloat16(0.f);
    }
    for (int i = t; i < 64 * 64; i += stride) {
        int n = i >> 6, k = i & 63;
        o2[i] = __float2bfloat16(w2[k * 64 + n]);
    }
    for (int i = t; i < 16 * 64; i += stride) {
        int n = i >> 6, k = i & 63;
        o3[i] = (n < EC) ? __float2bfloat16(wi[k * EC + n]) : __nv_bfloat16(0.f);
    }
}

// ---------------- edge MLP: register-chained B2B mma (no H/G smem) ----------
// 256 edges / 8 warps per CTA. Warp w owns rows [wrow, wrow+32).
// Layer outputs stay in registers: C-fragment of layer L == A-fragment of
// layer L+1 after pairwise bf16 packing (a0=pack(c0,c1)|ntA, a1=pack(c2,c3)|ntA,
// a2=pack(c0,c1)|ntB, a3=pack(c2,c3)|ntB), since each warp owns the full 64-wide
// hidden dimension. Two 16-row halves (t2) processed sequentially to cap regs.
static constexpr int ESA_ATTR = 0;            // 512*10*2  = 10240
static constexpr int ESA_W1   = 10240;        //  4096
static constexpr int ESA_W2   = 14336;        //  8192
static constexpr int ESA_W3   = 22528;        //  2048
static constexpr int ESA_A1   = 24576;        // 256*64 = 16384
static constexpr int EDGE_SMEM = 40960;

__global__ __launch_bounds__(256)
void edge_mma_kernel(const float* __restrict__ bboxes,
                     const float* __restrict__ dirs,
                     const float* __restrict__ prio,
                     const int*   __restrict__ eidx,
                     const __nv_bfloat16* __restrict__ w1t,
                     const __nv_bfloat16* __restrict__ w2t,
                     const __nv_bfloat16* __restrict__ w3t,
                     const float* __restrict__ b1,
                     const float* __restrict__ b2,
                     const float* __restrict__ bi,
                     float* __restrict__ out)
{
    extern __shared__ char sm[];
    const uint32_t sb = smem_u32(sm);
    const int tid = threadIdx.x;
    const int lane = tid & 31, w = tid >> 5;
    const int bt = blockIdx.x >> 7;
    const int e0 = (blockIdx.x & 127) * 256;

    __nv_bfloat16* sAttr = (__nv_bfloat16*)(sm + ESA_ATTR);
    const float inv = 1.f / 1024.f;
    for (int n = tid; n < NNODE; n += 256) {
        int gn = bt * NNODE + n;
        float4 bb = *(const float4*)&bboxes[(size_t)gn * 4];
        float4 dd = *(const float4*)&dirs[(size_t)gn * 4];
        float pr = prio[gn];
        __nv_bfloat16* a = sAttr + n * 10;
        a[0] = __float2bfloat16(bb.x * inv);
        a[1] = __float2bfloat16(bb.y * inv);
        a[2] = __float2bfloat16(bb.z * inv);
        a[3] = __float2bfloat16(bb.w * inv);
        a[4] = __float2bfloat16(dd.x);
        a[5] = __float2bfloat16(dd.y);
        a[6] = __float2bfloat16(dd.z);
        a[7] = __float2bfloat16(dd.w);
        a[8] = __float2bfloat16(pr);
    }
    for (int i = tid; i < 64 * 4; i += 256) {
        int r = i >> 2, c = i & 3;
        uint4 v = ((const uint4*)w1t)[r * 4 + c];
        sts128(sb + ESA_W1 + r * 64 + ((c ^ ((r >> 1) & 3)) << 4), v);
    }
    for (int i = tid; i < 64 * 8; i += 256) {
        int r = i >> 3, c = i & 7;
        uint4 v = ((const uint4*)w2t)[r * 8 + c];
        sts128(sb + ESA_W2 + r * 128 + ((c ^ (r & 7)) << 4), v);
    }
    for (int i = tid; i < 16 * 8; i += 256) {
        int r = i >> 3, c = i & 7;
        uint4 v = ((const uint4*)w3t)[r * 8 + c];
        sts128(sb + ESA_W3 + r * 128 + ((c ^ (r & 7)) << 4), v);
    }
    __syncthreads();

    // build A1: thread tid builds edge e0+tid (row tid of a 256x32 tile)
    {
        const int ebase = bt * 2 * EDGES + e0 + tid;
        const int src = eidx[ebase];
        const int dst = eidx[ebase + EDGES];
        const __nv_bfloat16* as = sAttr + src * 10;
        const __nv_bfloat16* ad = sAttr + dst * 10;
        uint16_t v[32];
        #pragma unroll
        for (int c = 0; c < 9; c++) { memcpy(&v[c], &as[c], 2); memcpy(&v[9 + c], &ad[c], 2); }
        #pragma unroll
        for (int c = 18; c < 32; c++) v[c] = 0;
        const int swz = (tid >> 1) & 3;
        #pragma unroll
        for (int ch = 0; ch < 4; ch++) {
            uint4 p;
            p.x = (uint32_t)v[ch*8+0] | ((uint32_t)v[ch*8+1] << 16);
            p.y = (uint32_t)v[ch*8+2] | ((uint32_t)v[ch*8+3] << 16);
            p.z = (uint32_t)v[ch*8+4] | ((uint32_t)v[ch*8+5] << 16);
            p.w = (uint32_t)v[ch*8+6] | ((uint32_t)v[ch*8+7] << 16);
            sts128(sb + ESA_A1 + tid * 64 + ((ch ^ swz) << 4), p);
        }
    }
    // A1 rows for warp w are written by this warp's own lanes -> warp sync only
    __syncwarp();

    const int m = lane >> 3, rr = lane & 7;
    const int wrow = (w >> 2) * 128 + (w & 3) * 32;
    const int t4 = 2 * (lane & 3);

    #pragma unroll
    for (int t2 = 0; t2 < 2; t2++) {
        const int rbase = wrow + t2 * 16;

        // ---- layer 1: A1(16x32) @ W1(64x32)^T -> acc1 (16x64) ----
        float acc1[8][4];
        #pragma unroll
        for (int b = 0; b < 8; b++)
            #pragma unroll
            for (int c = 0; c < 4; c++) acc1[b][c] = 0.f;
        #pragma unroll
        for (int k16 = 0; k16 < 2; k16++) {
            uint32_t a[4], b[4][4];
            {
                int r = rbase + ((m & 1) << 3) + rr;
                int c = k16 * 2 + (m >> 1);
                ldsm4(sb + ESA_A1 + r * 64 + ((c ^ ((r >> 1) & 3)) << 4), a);
            }
            #pragma unroll
            for (int p = 0; p < 4; p++) {
                int n = p * 16 + ((m >> 1) << 3) + rr;
                int c = k16 * 2 + (m & 1);
                ldsm4(sb + ESA_W1 + n * 64 + ((c ^ ((n >> 1) & 3)) << 4), b[p]);
            }
            #pragma unroll
            for (int nt = 0; nt < 8; nt++)
                mma16816(acc1[nt], a, &b[nt >> 1][(nt & 1) * 2]);
        }

        // ---- bias+relu -> layer-2 A fragments (in registers) ----
        uint32_t a2[4][4];
        #pragma unroll
        for (int kk = 0; kk < 4; kk++) {
            const int ntA = 2 * kk, ntB = ntA + 1;
            const int colA = ntA * 8 + t4, colB = ntB * 8 + t4;
            float bA0 = __ldg(&b1[colA]), bA1 = __ldg(&b1[colA + 1]);
            float bB0 = __ldg(&b1[colB]), bB1 = __ldg(&b1[colB + 1]);
            a2[kk][0] = pack_bf2(fmaxf(acc1[ntA][0] + bA0, 0.f),
                                 fmaxf(acc1[ntA][1] + bA1, 0.f));
            a2[kk][1] = pack_bf2(fmaxf(acc1[ntA][2] + bA0, 0.f),
                                 fmaxf(acc1[ntA][3] + bA1, 0.f));
            a2[kk][2] = pack_bf2(fmaxf(acc1[ntB][0] + bB0, 0.f),
                                 fmaxf(acc1[ntB][1] + bB1, 0.f));
            a2[kk][3] = pack_bf2(fmaxf(acc1[ntB][2] + bB0, 0.f),
                                 fmaxf(acc1[ntB][3] + bB1, 0.f));
        }

        // ---- layer 2: (16x64) @ W2(64x64)^T -> acc2 (16x64) ----
        float acc2[8][4];
        #pragma unroll
        for (int b = 0; b < 8; b++)
            #pragma unroll
            for (int c = 0; c < 4; c++) acc2[b][c] = 0.f;
        #pragma unroll
        for (int kk = 0; kk < 4; kk++) {
            uint32_t b[4][4];
            #pragma unroll
            for (int p = 0; p < 4; p++) {
                int n = p * 16 + ((m >> 1) << 3) + rr;
                int c = kk * 2 + (m & 1);
                ldsm4(sb + ESA_W2 + n * 128 + ((c ^ (n & 7)) << 4), b[p]);
            }
            #pragma unroll
            for (int nt = 0; nt < 8; nt++)
                mma16816(acc2[nt], a2[kk], &b[nt >> 1][(nt & 1) * 2]);
        }

        // ---- bias+relu -> layer-3 A fragments ----
        uint32_t a3[4][4];
        #pragma unroll
        for (int kk = 0; kk < 4; kk++) {
            const int ntA = 2 * kk, ntB = ntA + 1;
            const int colA = ntA * 8 + t4, colB = ntB * 8 + t4;
            float bA0 = __ldg(&b2[colA]), bA1 = __ldg(&b2[colA + 1]);
            float bB0 = __ldg(&b2[colB]), bB1 = __ldg(&b2[colB + 1]);
            a3[kk][0] = pack_bf2(fmaxf(acc2[ntA][0] + bA0, 0.f),
                                 fmaxf(acc2[ntA][1] + bA1, 0.f));
            a3[kk][1] = pack_bf2(fmaxf(acc2[ntA][2] + bA0, 0.f),
                                 fmaxf(acc2[ntA][3] + bA1, 0.f));
            a3[kk][2] = pack_bf2(fmaxf(acc2[ntB][0] + bB0, 0.f),
                                 fmaxf(acc2[ntB][1] + bB1, 0.f));
            a3[kk][3] = pack_bf2(fmaxf(acc2[ntB][2] + bB0, 0.f),
                                 fmaxf(acc2[ntB][3] + bB1, 0.f));
        }

        // ---- layer 3: (16x64) @ W3(16x64)^T -> acc3 (16x16) ----
        float acc3[2][4];
        #pragma unroll
        for (int b = 0; b < 2; b++)
            #pragma unroll
            for (int c = 0; c < 4; c++) acc3[b][c] = 0.f;
        #pragma unroll
        for (int kk = 0; kk < 4; kk++) {
            uint32_t b[4];
            int n = ((m >> 1) << 3) + rr;
            int c = kk * 2 + (m & 1);
            ldsm4(sb + ESA_W3 + n * 128 + ((c ^ (n & 7)) << 4), b);
            mma16816(acc3[0], a3[kk], &b[0]);
            mma16816(acc3[1], a3[kk], &b[2]);
        }

        // ---- sigmoid + store (cols 0..9 of 16) ----
        const int r0 = rbase + (lane >> 2);
        const long eg = (long)bt * EDGES + e0 + r0;
        #pragma unroll
        for (int nt = 0; nt < 2; nt++) {
            const int col = nt * 8 + t4;
            if (col < EC) {
                float bb0 = __ldg(&bi[col]), bb1 = __ldg(&bi[col + 1]);
                float s00 = 1.f / (1.f + __expf(-(acc3[nt][0] + bb0)));
                float s01 = 1.f / (1.f + __expf(-(acc3[nt][1] + bb1)));
                float s10 = 1.f / (1.f + __expf(-(acc3[nt][2] + bb0)));
                float s11 = 1.f / (1.f + __expf(-(acc3[nt][3] + bb1)));
                *(float2*)(out + eg * EC + col) = make_float2(s00, s01);
                *(float2*)(out + (eg + 8) * EC + col) = make_float2(s10, s11);
            }
        }
    }
}

// ---------------- launch ----------------------------------------------------
extern "C" void kernel_launch(void* const* d_in, const int* in_sizes, int n_in,
                              void* d_out, int out_size)
{
    const float* roi    = (const float*)d_in[0];
    const float* bboxes = (const float*)d_in[1];
    const float* dirs   = (const float*)d_in[2];
    const float* prio   = (const float*)d_in[3];
    const int*   eidx   = (const int*)  d_in[4];
    const float* np_w1  = (const float*)d_in[5];
    const float* np_b1  = (const float*)d_in[6];
    const float* bn1_g  = (const float*)d_in[7];
    const float* bn1_b  = (const float*)d_in[8];
    const float* bn1_rm = (const float*)d_in[9];
    const float* bn1_rv = (const float*)d_in[10];
    const float* np_w2  = (const float*)d_in[11];
    const float* np_b2  = (const float*)d_in[12];
    const float* bn2_g  = (const float*)d_in[13];
    const float* bn2_b  = (const float*)d_in[14];
    const float* bn2_rm = (const float*)d_in[15];
    const float* bn2_rv = (const float*)d_in[16];
    const float* np_w3  = (const float*)d_in[17];
    const float* np_b3  = (const float*)d_in[18];
    const float* ni_w   = (const float*)d_in[19];
    const float* ni_b   = (const float*)d_in[20];
    const float* ep_w1  = (const float*)d_in[21];
    const float* ep_b1  = (const float*)d_in[22];
    const float* ep_w2  = (const float*)d_in[23];
    const float* ep_b2  = (const float*)d_in[24];
    const float* ei_w   = (const float*)d_in[25];
    const float* ei_b   = (const float*)d_in[26];

    float* out = (float*)d_out;

    __nv_bfloat16 *x, *h1, *h2, *w1t, *w2t, *w3t, *ew1t, *ew2t, *ew3t;
    cudaGetSymbolAddress((void**)&x, g_x);
    cudaGetSymbolAddress((void**)&h1, g_h1);
    cudaGetSymbolAddress((void**)&h2, g_h2);
    cudaGetSymbolAddress((void**)&w1t, g_w1t);
    cudaGetSymbolAddress((void**)&w2t, g_w2t);
    cudaGetSymbolAddress((void**)&w3t, g_w3t);
    cudaGetSymbolAddress((void**)&ew1t, g_ew1t);
    cudaGetSymbolAddress((void**)&ew2t, g_ew2t);
    cudaGetSymbolAddress((void**)&ew3t, g_ew3t);

    cudaFuncSetAttribute(edge_mma_kernel,
                         cudaFuncAttributeMaxDynamicSharedMemorySize, EDGE_SMEM);
    cudaFuncSetAttribute(gemm_mma2<FDIM, H1, 1, 1>,
                         cudaFuncAttributeMaxDynamicSharedMemorySize, GEMM_SMEM);
    cudaFuncSetAttribute(gemm_mma2<H1, H2, 1, 1>,
                         cudaFuncAttributeMaxDynamicSharedMemorySize, GEMM_SMEM);
    cudaFuncSetAttribute(gemm_mma2<H2, H3, 0, 2>,
                         cudaFuncAttributeMaxDynamicSharedMemorySize, GEMM3_SMEM);

    // one-time stream/event setup (host-side resources; no device memory)
    static cudaStream_t s_edge = nullptr;
    static cudaEvent_t  ev_fork = nullptr, ev_w = nullptr, ev_join = nullptr;
    if (s_edge == nullptr) {
        cudaStreamCreateWithFlags(&s_edge, cudaStreamNonBlocking);
        cudaEventCreateWithFlags(&ev_fork, cudaEventDisableTiming);
        cudaEventCreateWithFlags(&ev_w, cudaEventDisableTiming);
        cudaEventCreateWithFlags(&ev_join, cudaEventDisableTiming);
    }

    // ---- fork immediately; side stream does weight prep + edge branch ----
    cudaEventRecord(ev_fork, 0);
    cudaStreamWaitEvent(s_edge, ev_fork, 0);

    // main stream: roi convert (critical path for GEMM1's A operand)
    convert_f32<<<NROWS * FDIM / 4 / 256, 256>>>((const float4*)roi, (uint2*)x);

    // side stream: node-weight transposes (overlap with convert), then edges
    {
        dim3 b(32, 8);
        transpose_bf16<<<dim3(H1 / 32, FDIM / 32), b, 0, s_edge>>>(np_w1, w1t, FDIM, H1);
        transpose_bf16<<<dim3(H2 / 32, H1 / 32), b, 0, s_edge>>>(np_w2, w2t, H1, H2);
        transpose_bf16<<<dim3(H3 / 32, H2 / 32), b, 0, s_edge>>>(np_w3, w3t, H2, H3);
    }
    cudaEventRecord(ev_w, s_edge);
    prep_edge_weights<<<8, 256, 0, s_edge>>>(ep_w1, ep_w2, ei_w, ew1t, ew2t, ew3t);
    edge_mma_kernel<<<NEDGE / 256, 256, EDGE_SMEM, s_edge>>>(
        bboxes, dirs, prio, eidx, ew1t, ew2t, ew3t,
        ep_b1, ep_b2, ei_b, out + NODE_OUT_ELEMS);
    cudaEventRecord(ev_join, s_edge);

    // main stream: node GEMM chain (needs transposed weights)
    cudaStreamWaitEvent(0, ev_w, 0);
    gemm_mma2<FDIM, H1, 1, 1><<<dim3(H1 / 128, NROWS / 128), 256, GEMM_SMEM>>>(
        x, w1t, np_b1, bn1_g, bn1_b, bn1_rm, bn1_rv,
        nullptr, nullptr, nullptr, h1);
    gemm_mma2<H1, H2, 1, 1><<<dim3(H2 / 128, NROWS / 128), 256, GEMM_SMEM>>>(
        h1, w2t, np_b2, bn2_g, bn2_b, bn2_rm, bn2_rv,
        nullptr, nullptr, nullptr, h2);
    gemm_mma2<H2, H3, 0, 2><<<dim3(H3 / 128, NROWS / 128), 256, GEMM3_SMEM>>>(
        h2, w3t, np_b3, nullptr, nullptr, nullptr, nullptr,
        ni_w, ni_b, out, nullptr);

    // join
    cudaStreamWaitEvent(0, ev_join, 0);
}